// round 5
// baseline (speedup 1.0000x reference)
#include <cuda_runtime.h>
#include <cstdint>

#define BB   8
#define SS   512
#define HH   16
#define DD   64
#define HIDN 1024
#define BH   (BB*HH)   // 128

// ---------------- scratch (device globals: allocation-free) ----------------
__device__ float g_q[BH*SS*DD];                 // [b,h,s,d] 16MB
__device__ float g_k[BH*SS*DD];
__device__ float g_v[BH*SS*DD];
__device__ float g_pos[HH*1024*DD];             // [h,p,d]   4MB

// ---------------- helpers ---------------------------------------------------
__device__ __forceinline__ uint32_t f2tf(float f) {
    uint32_t u;
    asm("cvt.rna.tf32.f32 %0, %1;" : "=r"(u) : "f"(f));
    return u;
}
__device__ __forceinline__ void mma_tf32(float c[4], const uint32_t a[4], const uint32_t b[2]) {
    asm volatile("mma.sync.aligned.m16n8k8.row.col.f32.tf32.tf32.f32 "
        "{%0,%1,%2,%3}, {%4,%5,%6,%7}, {%8,%9}, {%0,%1,%2,%3};"
        : "+f"(c[0]), "+f"(c[1]), "+f"(c[2]), "+f"(c[3])
        : "r"(a[0]), "r"(a[1]), "r"(a[2]), "r"(a[3]), "r"(b[0]), "r"(b[1]));
}

// ---------------- tf32 HMMA projection GEMM, double-buffered ---------------
// C[m,n] = sum_k X[m,k]*W[n,k] + bias[n], scattered to g_q/g_k/g_v/g_pos.
#define GEMM_SMEM (4608*4*4)   // 2 x (A 128x36) + 2 x (B 128x36) words = 73728 B

__global__ __launch_bounds__(256) void gemm_tc(
    const float* __restrict__ hs, const float* __restrict__ rel,
    const float* __restrict__ Wq, const float* __restrict__ bq,
    const float* __restrict__ Wk, const float* __restrict__ bk,
    const float* __restrict__ Wv, const float* __restrict__ bv,
    const float* __restrict__ Wpk, const float* __restrict__ bpk)
{
    extern __shared__ uint32_t sg[];
    uint32_t* AsB[2] = { sg,        sg + 4608  };
    uint32_t* BsB[2] = { sg + 9216, sg + 13824 };

    const int which = blockIdx.z;
    if (which == 3 && blockIdx.y >= 8) return;

    const float* X    = (which == 3) ? rel : hs;
    const float* W    = (which == 0) ? Wq : (which == 1) ? Wk : (which == 2) ? Wv : Wpk;
    const float* bias = (which == 0) ? bq : (which == 1) ? bk : (which == 2) ? bv : bpk;
    float* outp       = (which == 0) ? g_q : (which == 1) ? g_k : (which == 2) ? g_v : g_pos;

    const int bm = blockIdx.y * 128;
    const int bn = blockIdx.x * 128;
    const int tid = threadIdx.x;
    const int wid = tid >> 5, lane = tid & 31;
    const int wm = wid >> 1, wn = wid & 1;
    const int g = lane >> 2, t = lane & 3;

    float acc[2][8][4];
#pragma unroll
    for (int mt = 0; mt < 2; mt++)
#pragma unroll
        for (int nt = 0; nt < 8; nt++)
#pragma unroll
            for (int i = 0; i < 4; i++) acc[mt][nt][i] = 0.f;

    const float* Ag = X + (size_t)bm * HIDN;
    const float* Bg = W + (size_t)bn * HIDN;

    float4 pa[4], pb[4];
#pragma unroll
    for (int i = 0; i < 4; i++) {
        const int fi = i * 256 + tid, r = fi >> 3, c = fi & 7;
        pa[i] = *(const float4*)(Ag + (size_t)r * HIDN + c * 4);
        pb[i] = *(const float4*)(Bg + (size_t)r * HIDN + c * 4);
    }
#pragma unroll
    for (int i = 0; i < 4; i++) {
        const int fi = i * 256 + tid, r = fi >> 3, c = fi & 7;
        *(uint4*)&AsB[0][r*36 + c*4] = make_uint4(f2tf(pa[i].x), f2tf(pa[i].y), f2tf(pa[i].z), f2tf(pa[i].w));
        *(uint4*)&BsB[0][r*36 + c*4] = make_uint4(f2tf(pb[i].x), f2tf(pb[i].y), f2tf(pb[i].z), f2tf(pb[i].w));
    }
    __syncthreads();

    for (int kc = 0; kc < 32; kc++) {
        const int cur = kc & 1;
        if (kc < 31) {
#pragma unroll
            for (int i = 0; i < 4; i++) {
                const int fi = i * 256 + tid, r = fi >> 3, c = fi & 7;
                pa[i] = *(const float4*)(Ag + (size_t)r * HIDN + (kc + 1) * 32 + c * 4);
                pb[i] = *(const float4*)(Bg + (size_t)r * HIDN + (kc + 1) * 32 + c * 4);
            }
        }
        const uint32_t* As = AsB[cur];
        const uint32_t* Bs = BsB[cur];
#pragma unroll
        for (int ks = 0; ks < 4; ks++) {
            uint32_t a[2][4], b[8][2];
#pragma unroll
            for (int mt = 0; mt < 2; mt++) {
                const int ra = (wm*32 + mt*16 + g) * 36 + ks*8 + t;
                a[mt][0] = As[ra];
                a[mt][1] = As[ra + 8*36];
                a[mt][2] = As[ra + 4];
                a[mt][3] = As[ra + 8*36 + 4];
            }
#pragma unroll
            for (int nt = 0; nt < 8; nt++) {
                const int rb = (wn*64 + nt*8 + g) * 36 + ks*8 + t;
                b[nt][0] = Bs[rb];
                b[nt][1] = Bs[rb + 4];
            }
#pragma unroll
            for (int mt = 0; mt < 2; mt++)
#pragma unroll
                for (int nt = 0; nt < 8; nt++)
                    mma_tf32(acc[mt][nt], a[mt], b[nt]);
        }
        if (kc < 31) {
            uint32_t* An = AsB[cur ^ 1];
            uint32_t* Bn = BsB[cur ^ 1];
#pragma unroll
            for (int i = 0; i < 4; i++) {
                const int fi = i * 256 + tid, r = fi >> 3, c = fi & 7;
                *(uint4*)&An[r*36 + c*4] = make_uint4(f2tf(pa[i].x), f2tf(pa[i].y), f2tf(pa[i].z), f2tf(pa[i].w));
                *(uint4*)&Bn[r*36 + c*4] = make_uint4(f2tf(pb[i].x), f2tf(pb[i].y), f2tf(pb[i].z), f2tf(pb[i].w));
            }
        }
        __syncthreads();
    }

#pragma unroll
    for (int mt = 0; mt < 2; mt++) {
#pragma unroll
        for (int nt = 0; nt < 8; nt++) {
            const int n = bn + wn*64 + nt*8 + 2*t;
            const float bv0 = bias[n], bv1 = bias[n+1];
#pragma unroll
            for (int half = 0; half < 2; half++) {
                const int m = bm + wm*32 + mt*16 + g + half*8;
                const float v0 = acc[mt][nt][half*2+0] + bv0;
                const float v1 = acc[mt][nt][half*2+1] + bv1;
                size_t oi;
                if (which < 3) {
                    const int b_ = m >> 9, s = m & 511, h = n >> 6, d = n & 63;
                    oi = (((size_t)(b_*HH + h))*SS + s)*DD + d;
                } else {
                    oi = (((size_t)(n >> 6))*1024 + m)*DD + (n & 63);
                }
                *(float2*)(outp + oi) = make_float2(v0, v1);
            }
        }
    }
}

// ---------------- fused flash kernel: scores + softmax + PV ----------------
// Per CTA: i-tile 64 x one (b,h). 8 j-chunks of 64. 320 threads = 10 warps.
// 4 syncthreads per chunk; scatter via shared atomics; P~ tf32 aliased in Ss.
#define FL_SMEM (26368 * 4)   // 105472 B

__global__ __launch_bounds__(320) void flash_tc(const float* __restrict__ mask,
                                                float* __restrict__ out)
{
    extern __shared__ uint32_t smw[];
    uint32_t* Qs = smw;                    // 64 x 68
    uint32_t* Ks = smw + 4352;             // 64 x 68
    uint32_t* Ps = smw + 8704;             // 128 x 68 (pos band)
    uint32_t* Vt = smw + 17408;            // 64 x 68 (V transposed [d][j])
    float*    SsF = (float*)(smw + 21760); // 64 x 68 score accum / P~ tf32 alias
    uint32_t* PtU = smw + 21760;
    float* sm_m     = (float*)(smw + 26112);
    float* sm_l     = sm_m + 64;
    float* sm_scale = sm_m + 128;
    float* sm_mask  = sm_m + 192;

    const int i0 = blockIdx.x * 64;
    const int bh = blockIdx.y;
    const int b_ = bh >> 4, h = bh & 15;
    const int tid = threadIdx.x;
    const int wid = tid >> 5, lane = tid & 31;
    const int g = lane >> 2, t = lane & 3;
    const int wm = wid >> 1, wn = wid & 1;      // PV warp grid (wid<8): 4x2

    const float* qptr  = g_q + ((size_t)bh*SS + i0) * DD;
    const float* kbase = g_k + (size_t)bh*SS*DD;
    const float* vbase = g_v + (size_t)bh*SS*DD;
    const float* pptr  = g_pos + (size_t)h * 1024 * DD;

    // Q tile once (threads 0..255, 4 uniform unrolled iters)
    if (tid < 256) {
#pragma unroll
        for (int i = 0; i < 4; i++) {
            const int u = tid + i*256, row = u >> 4, c4 = u & 15;
            float4 qv = *(const float4*)(qptr + (size_t)row * DD + c4*4);
            *(uint4*)&Qs[row*68 + c4*4] = make_uint4(f2tf(qv.x), f2tf(qv.y), f2tf(qv.z), f2tf(qv.w));
        }
    }
    if (tid < 64) { sm_m[tid] = -1e30f; sm_l[tid] = 0.f; }

    float acc_o[4][4];
#pragma unroll
    for (int nt = 0; nt < 4; nt++)
#pragma unroll
        for (int e = 0; e < 4; e++) acc_o[nt][e] = 0.f;

    // score-phase chunk assignment
    const uint32_t* Ap; const uint32_t* Bp;
    int Arow, Brow;
    if (wid < 2)      { Ap = Qs; Arow = wid*32;          Bp = Ks; Brow = 0; }
    else if (wid < 6) { Ap = Qs; Arow = ((wid-2)&1)*32;  Bp = Ps; Brow = ((wid-2)>>1)*64; }
    else              { Ap = Ps; Arow = (wid-6)*32;      Bp = Ks; Brow = 0; }

    const float s1 = 0.14433756729740643f;      // 1/sqrt(48)

    for (int j0 = 0; j0 < SS; j0 += 64) {
        __syncthreads();   // previous chunk's Pt/Vt/Ks/Ps reads complete

        // ---- zero score accum ----
        for (int u = tid; u < 4352; u += 320) SsF[u] = 0.f;

        // ---- loads (threads 0..255; batched LDGs for MLP) ----
        if (tid < 256) {
            const int row = tid >> 4, c4 = tid & 15;   // base (i=0) indices
            {   // K: 4 rows per thread group
                float4 x0 = *(const float4*)(kbase + (size_t)(j0+row)    * DD + c4*4);
                float4 x1 = *(const float4*)(kbase + (size_t)(j0+row+16) * DD + c4*4);
                float4 x2 = *(const float4*)(kbase + (size_t)(j0+row+32) * DD + c4*4);
                float4 x3 = *(const float4*)(kbase + (size_t)(j0+row+48) * DD + c4*4);
                *(uint4*)&Ks[(row)   *68 + c4*4] = make_uint4(f2tf(x0.x), f2tf(x0.y), f2tf(x0.z), f2tf(x0.w));
                *(uint4*)&Ks[(row+16)*68 + c4*4] = make_uint4(f2tf(x1.x), f2tf(x1.y), f2tf(x1.z), f2tf(x1.w));
                *(uint4*)&Ks[(row+32)*68 + c4*4] = make_uint4(f2tf(x2.x), f2tf(x2.y), f2tf(x2.z), f2tf(x2.w));
                *(uint4*)&Ks[(row+48)*68 + c4*4] = make_uint4(f2tf(x3.x), f2tf(x3.y), f2tf(x3.z), f2tf(x3.w));
            }
            {   // V: 4 rows, transposed store with e-rotation
                float4 x[4];
                x[0] = *(const float4*)(vbase + (size_t)(j0+row)    * DD + c4*4);
                x[1] = *(const float4*)(vbase + (size_t)(j0+row+16) * DD + c4*4);
                x[2] = *(const float4*)(vbase + (size_t)(j0+row+32) * DD + c4*4);
                x[3] = *(const float4*)(vbase + (size_t)(j0+row+48) * DD + c4*4);
#pragma unroll
                for (int i = 0; i < 4; i++) {
                    uint32_t ve[4] = {f2tf(x[i].x), f2tf(x[i].y), f2tf(x[i].z), f2tf(x[i].w)};
                    const int jrow = row + i*16;
#pragma unroll
                    for (int e2 = 0; e2 < 4; e2++) {
                        const int e = (e2 + c4) & 3;
                        Vt[(c4*4 + e)*68 + jrow] = ve[e];
                    }
                }
            }
            const int base = i0 - j0 + 449;
#pragma unroll
            for (int half = 0; half < 2; half++) {   // P: 8 rows in 2 batches of 4
                float4 x[4];
#pragma unroll
                for (int i = 0; i < 4; i++) {
                    const int pr = row + (half*4 + i)*16;           // 0..127
                    int grow = base + pr;
                    grow = grow < 0 ? 0 : (grow > 1023 ? 1023 : grow);
                    x[i] = *(const float4*)(pptr + (size_t)grow * DD + c4*4);
                }
#pragma unroll
                for (int i = 0; i < 4; i++) {
                    const int pr = row + (half*4 + i)*16;
                    *(uint4*)&Ps[pr*68 + c4*4] = make_uint4(f2tf(x[i].x), f2tf(x[i].y), f2tf(x[i].z), f2tf(x[i].w));
                }
            }
        } else if (tid < 320 && (tid - 256) < 64) {
            sm_mask[tid - 256] = mask[(size_t)b_*SS + j0 + tid - 256];
        }
        __syncthreads();

        // ---- score MMAs ----
        float acc[2][8][4];
#pragma unroll
        for (int mt = 0; mt < 2; mt++)
#pragma unroll
            for (int nt = 0; nt < 8; nt++)
#pragma unroll
                for (int e = 0; e < 4; e++) acc[mt][nt][e] = 0.f;

#pragma unroll
        for (int ks = 0; ks < 8; ks++) {
            uint32_t a[2][4], b[8][2];
#pragma unroll
            for (int mt = 0; mt < 2; mt++) {
                const int ra = (Arow + mt*16 + g) * 68 + ks*8 + t;
                a[mt][0] = Ap[ra];
                a[mt][1] = Ap[ra + 8*68];
                a[mt][2] = Ap[ra + 4];
                a[mt][3] = Ap[ra + 8*68 + 4];
            }
#pragma unroll
            for (int nt = 0; nt < 8; nt++) {
                const int rb = (Brow + nt*8 + g) * 68 + ks*8 + t;
                b[nt][0] = Bp[rb];
                b[nt][1] = Bp[rb + 4];
            }
#pragma unroll
            for (int mt = 0; mt < 2; mt++)
#pragma unroll
                for (int nt = 0; nt < 8; nt++)
                    mma_tf32(acc[mt][nt], a[mt], b[nt]);
        }

        // ---- single-phase scatter via shared atomics ----
        if (wid < 2) {                // CC[r][c] += acc
#pragma unroll
            for (int mt = 0; mt < 2; mt++)
#pragma unroll
                for (int nt = 0; nt < 8; nt++) {
                    const int r0 = Arow + mt*16 + g;
                    const int c0 = nt*8 + 2*t;
                    atomicAdd(&SsF[r0*68 + c0],       acc[mt][nt][0]);
                    atomicAdd(&SsF[r0*68 + c0 + 1],   acc[mt][nt][1]);
                    atomicAdd(&SsF[(r0+8)*68 + c0],   acc[mt][nt][2]);
                    atomicAdd(&SsF[(r0+8)*68 + c0+1], acc[mt][nt][3]);
                }
        } else if (wid < 6) {         // CPF[ai][p] -> S[ai][ai-p+63] * 0.125
#pragma unroll
            for (int mt = 0; mt < 2; mt++)
#pragma unroll
                for (int nt = 0; nt < 8; nt++) {
                    const int ai0 = Arow + mt*16 + g;
                    const int p0 = Brow + nt*8 + 2*t;
#pragma unroll
                    for (int e = 0; e < 4; e++) {
                        const int ai = ai0 + (e >> 1)*8;
                        const int p  = p0 + (e & 1);
                        const int cj = ai - p + 63;
                        if ((unsigned)cj < 64u)
                            atomicAdd(&SsF[ai*68 + cj], 0.125f * acc[mt][nt][e]);
                    }
                }
        } else {                      // PCF[r][cj] -> S[r+cj-63][cj]
#pragma unroll
            for (int mt = 0; mt < 2; mt++)
#pragma unroll
                for (int nt = 0; nt < 8; nt++) {
                    const int r0 = Arow + mt*16 + g;
                    const int c0 = nt*8 + 2*t;
#pragma unroll
                    for (int e = 0; e < 4; e++) {
                        const int r  = r0 + (e >> 1)*8;
                        const int cj = c0 + (e & 1);
                        const int ai = r + cj - 63;
                        if ((unsigned)ai < 64u)
                            atomicAdd(&SsF[ai*68 + cj], acc[mt][nt][e]);
                    }
                }
        }
        __syncthreads();

        // ---- online softmax (threads 0..255, 4 per row); P~ tf32 in place --
        if (tid < 256) {
            const int row = tid >> 2, q4 = tid & 3;
            float mloc = -1e30f;
#pragma unroll
            for (int c = q4*16; c < q4*16 + 16; c++) {
                const float val = SsF[row*68 + c] * s1 + sm_mask[c];
                SsF[row*68 + c] = val;
                mloc = fmaxf(mloc, val);
            }
            mloc = fmaxf(mloc, __shfl_xor_sync(0xffffffffu, mloc, 1));
            mloc = fmaxf(mloc, __shfl_xor_sync(0xffffffffu, mloc, 2));
            const float mold = sm_m[row];
            const float mnew = fmaxf(mold, mloc);
            float lsum = 0.f;
#pragma unroll
            for (int c = q4*16; c < q4*16 + 16; c++) {
                const float p = __expf(SsF[row*68 + c] - mnew);
                PtU[row*68 + c] = f2tf(p);
                lsum += p;
            }
            lsum += __shfl_xor_sync(0xffffffffu, lsum, 1);
            lsum += __shfl_xor_sync(0xffffffffu, lsum, 2);
            if (q4 == 0) {
                const float sc = __expf(mold - mnew);
                sm_m[row] = mnew;
                sm_scale[row] = sc;
                sm_l[row] = sm_l[row] * sc + lsum;
            }
        }
        __syncthreads();

        // ---- PV: warps 0..7, out tile 64x64, warp tile 16x32 ----
        if (wid < 8) {
            const float sc0 = sm_scale[wm*16 + g];
            const float sc1 = sm_scale[wm*16 + g + 8];
#pragma unroll
            for (int nt = 0; nt < 4; nt++) {
                acc_o[nt][0] *= sc0; acc_o[nt][1] *= sc0;
                acc_o[nt][2] *= sc1; acc_o[nt][3] *= sc1;
            }
#pragma unroll
            for (int ks = 0; ks < 8; ks++) {
                uint32_t a[4], b[4][2];
                const int ra = (wm*16 + g) * 68 + ks*8 + t;
                a[0] = PtU[ra];
                a[1] = PtU[ra + 8*68];
                a[2] = PtU[ra + 4];
                a[3] = PtU[ra + 8*68 + 4];
#pragma unroll
                for (int nt = 0; nt < 4; nt++) {
                    const int rb = (wn*32 + nt*8 + g) * 68 + ks*8 + t;
                    b[nt][0] = Vt[rb];
                    b[nt][1] = Vt[rb + 4];
                }
#pragma unroll
                for (int nt = 0; nt < 4; nt++)
                    mma_tf32(acc_o[nt], a, b[nt]);
            }
        }
    }
    __syncthreads();

    // ---- finalize: out[i][d] = acc_o / l ----
    if (wid < 8) {
        const int r0 = wm*16 + g;
        const float inv0 = 1.f / sm_l[r0];
        const float inv1 = 1.f / sm_l[r0 + 8];
#pragma unroll
        for (int nt = 0; nt < 4; nt++) {
            const int col = wn*32 + nt*8 + 2*t;
            const size_t o0 = ((size_t)b_*SS + i0 + r0)*HIDN + h*DD + col;
            const size_t o1 = ((size_t)b_*SS + i0 + r0 + 8)*HIDN + h*DD + col;
            *(float2*)(out + o0) = make_float2(acc_o[nt][0]*inv0, acc_o[nt][1]*inv0);
            *(float2*)(out + o1) = make_float2(acc_o[nt][2]*inv1, acc_o[nt][3]*inv1);
        }
    }
}

// ---------------- launch ---------------------------------------------------
extern "C" void kernel_launch(void* const* d_in, const int* in_sizes, int n_in,
                              void* d_out, int out_size)
{
    const float* hs  = (const float*)d_in[0];
    const float* msk = (const float*)d_in[1];
    const float* Wq  = (const float*)d_in[3];
    const float* bq  = (const float*)d_in[4];
    const float* Wk  = (const float*)d_in[5];
    const float* bk  = (const float*)d_in[6];
    const float* Wv  = (const float*)d_in[7];
    const float* bv  = (const float*)d_in[8];
    const float* Wpk = (const float*)d_in[9];
    const float* bpk = (const float*)d_in[10];
    const float* rel = (const float*)d_in[11];
    float* out = (float*)d_out;

    cudaFuncSetAttribute(gemm_tc, cudaFuncAttributeMaxDynamicSharedMemorySize, GEMM_SMEM);
    cudaFuncSetAttribute(flash_tc, cudaFuncAttributeMaxDynamicSharedMemorySize, FL_SMEM);

    dim3 gg(8, 32, 4);                    // z: Wq, Wk, Wv, Wpk (y>=8 idles for z=3)
    gemm_tc<<<gg, 256, GEMM_SMEM>>>(hs, rel, Wq, bq, Wk, bk, Wv, bv, Wpk, bpk);

    dim3 gf(SS/64, BH);                   // (8, 128)
    flash_tc<<<gf, 320, FL_SMEM>>>(msk, out);
}

// round 6
// speedup vs baseline: 1.3022x; 1.3022x over previous
#include <cuda_runtime.h>
#include <cstdint>

#define BB   8
#define SS   512
#define HH   16
#define DD   64
#define HIDN 1024
#define BH   (BB*HH)   // 128

// ---------------- scratch (device globals: allocation-free) ----------------
__device__ float g_q[BH*SS*DD];                 // [b,h,s,d] 16MB
__device__ float g_k[BH*SS*DD];
__device__ float g_v[BH*SS*DD];
__device__ float g_pos[HH*1024*DD];             // [h,p,d]   4MB

// ---------------- helpers ---------------------------------------------------
__device__ __forceinline__ uint32_t f2tf(float f) {
    uint32_t u;
    asm("cvt.rna.tf32.f32 %0, %1;" : "=r"(u) : "f"(f));
    return u;
}
__device__ __forceinline__ void mma_tf32(float c[4], const uint32_t a[4], const uint32_t b[2]) {
    asm volatile("mma.sync.aligned.m16n8k8.row.col.f32.tf32.tf32.f32 "
        "{%0,%1,%2,%3}, {%4,%5,%6,%7}, {%8,%9}, {%0,%1,%2,%3};"
        : "+f"(c[0]), "+f"(c[1]), "+f"(c[2]), "+f"(c[3])
        : "r"(a[0]), "r"(a[1]), "r"(a[2]), "r"(a[3]), "r"(b[0]), "r"(b[1]));
}

// ---------------- tf32 HMMA projection GEMM (R4 version, reverted) ---------
__global__ __launch_bounds__(256) void gemm_tc(
    const float* __restrict__ hs, const float* __restrict__ rel,
    const float* __restrict__ Wq, const float* __restrict__ bq,
    const float* __restrict__ Wk, const float* __restrict__ bk,
    const float* __restrict__ Wv, const float* __restrict__ bv,
    const float* __restrict__ Wpk, const float* __restrict__ bpk)
{
    __shared__ uint32_t As[128*36];
    __shared__ uint32_t Bs[128*36];

    const int which = blockIdx.z;
    if (which == 3 && blockIdx.y >= 8) return;

    const float* X    = (which == 3) ? rel : hs;
    const float* W    = (which == 0) ? Wq : (which == 1) ? Wk : (which == 2) ? Wv : Wpk;
    const float* bias = (which == 0) ? bq : (which == 1) ? bk : (which == 2) ? bv : bpk;
    float* outp       = (which == 0) ? g_q : (which == 1) ? g_k : (which == 2) ? g_v : g_pos;

    const int bm = blockIdx.y * 128;
    const int bn = blockIdx.x * 128;
    const int tid = threadIdx.x;
    const int wid = tid >> 5, lane = tid & 31;
    const int wm = wid >> 1, wn = wid & 1;
    const int g = lane >> 2, t = lane & 3;

    float acc[2][8][4];
#pragma unroll
    for (int mt = 0; mt < 2; mt++)
#pragma unroll
        for (int nt = 0; nt < 8; nt++)
#pragma unroll
            for (int i = 0; i < 4; i++) acc[mt][nt][i] = 0.f;

    const float* Ag = X + (size_t)bm * HIDN;
    const float* Bg = W + (size_t)bn * HIDN;

    for (int kc = 0; kc < 32; kc++) {
        float4 pa[4], pb[4];
#pragma unroll
        for (int i = 0; i < 4; i++) {
            const int fi = i * 256 + tid;
            const int row = fi >> 3, c4 = fi & 7;
            pa[i] = *(const float4*)(Ag + (size_t)row * HIDN + kc * 32 + c4 * 4);
            pb[i] = *(const float4*)(Bg + (size_t)row * HIDN + kc * 32 + c4 * 4);
        }
        __syncthreads();
#pragma unroll
        for (int i = 0; i < 4; i++) {
            const int fi = i * 256 + tid;
            const int row = fi >> 3, c4 = fi & 7;
            *(uint4*)&As[row*36 + c4*4] = make_uint4(f2tf(pa[i].x), f2tf(pa[i].y), f2tf(pa[i].z), f2tf(pa[i].w));
            *(uint4*)&Bs[row*36 + c4*4] = make_uint4(f2tf(pb[i].x), f2tf(pb[i].y), f2tf(pb[i].z), f2tf(pb[i].w));
        }
        __syncthreads();
#pragma unroll
        for (int ks = 0; ks < 4; ks++) {
            uint32_t a[2][4], b[8][2];
#pragma unroll
            for (int mt = 0; mt < 2; mt++) {
                const int ra = (wm*32 + mt*16 + g) * 36 + ks*8 + t;
                a[mt][0] = As[ra];
                a[mt][1] = As[ra + 8*36];
                a[mt][2] = As[ra + 4];
                a[mt][3] = As[ra + 8*36 + 4];
            }
#pragma unroll
            for (int nt = 0; nt < 8; nt++) {
                const int rb = (wn*64 + nt*8 + g) * 36 + ks*8 + t;
                b[nt][0] = Bs[rb];
                b[nt][1] = Bs[rb + 4];
            }
#pragma unroll
            for (int mt = 0; mt < 2; mt++)
#pragma unroll
                for (int nt = 0; nt < 8; nt++)
                    mma_tf32(acc[mt][nt], a[mt], b[nt]);
        }
    }

#pragma unroll
    for (int mt = 0; mt < 2; mt++) {
#pragma unroll
        for (int nt = 0; nt < 8; nt++) {
            const int n = bn + wn*64 + nt*8 + 2*t;
            const float bv0 = bias[n], bv1 = bias[n+1];
#pragma unroll
            for (int half = 0; half < 2; half++) {
                const int m = bm + wm*32 + mt*16 + g + half*8;
                const float v0 = acc[mt][nt][half*2+0] + bv0;
                const float v1 = acc[mt][nt][half*2+1] + bv1;
                size_t oi;
                if (which < 3) {
                    const int b_ = m >> 9, s = m & 511, h = n >> 6, d = n & 63;
                    oi = (((size_t)(b_*HH + h))*SS + s)*DD + d;
                } else {
                    oi = (((size_t)(n >> 6))*1024 + m)*DD + (n & 63);
                }
                *(float2*)(outp + oi) = make_float2(v0, v1);
            }
        }
    }
}

// ---------------- fused flash kernel: scores + softmax + PV ----------------
// 320 threads = 10 warps; __launch_bounds__(320,2) -> 2 CTAs/SM (<=102 regs).
// Score MMA in two nt-halves (32 live accs) with immediate atomic scatter.
#define FL_SMEM (26368 * 4)   // 105472 B  (x2 = 210944 <= 228KB/SM)

__global__ __launch_bounds__(320, 2) void flash_tc(const float* __restrict__ mask,
                                                   float* __restrict__ out)
{
    extern __shared__ uint32_t smw[];
    uint32_t* Qs = smw;                    // 64 x 68
    uint32_t* Ks = smw + 4352;             // 64 x 68
    uint32_t* Ps = smw + 8704;             // 128 x 68 (pos band)
    uint32_t* Vt = smw + 17408;            // 64 x 68 (V transposed [d][j])
    float*    SsF = (float*)(smw + 21760); // 64 x 68 score accum / P~ tf32 alias
    uint32_t* PtU = smw + 21760;
    float* sm_m     = (float*)(smw + 26112);
    float* sm_l     = sm_m + 64;
    float* sm_scale = sm_m + 128;
    float* sm_mask  = sm_m + 192;

    const int i0 = blockIdx.x * 64;
    const int bh = blockIdx.y;
    const int b_ = bh >> 4, h = bh & 15;
    const int tid = threadIdx.x;
    const int wid = tid >> 5, lane = tid & 31;
    const int g = lane >> 2, t = lane & 3;
    const int wm = wid >> 1, wn = wid & 1;      // PV warp grid (wid<8): 4x2

    const float* qptr  = g_q + ((size_t)bh*SS + i0) * DD;
    const float* kbase = g_k + (size_t)bh*SS*DD;
    const float* vbase = g_v + (size_t)bh*SS*DD;
    const float* pptr  = g_pos + (size_t)h * 1024 * DD;

    if (tid < 256) {
#pragma unroll
        for (int i = 0; i < 4; i++) {
            const int u = tid + i*256, row = u >> 4, c4 = u & 15;
            float4 qv = *(const float4*)(qptr + (size_t)row * DD + c4*4);
            *(uint4*)&Qs[row*68 + c4*4] = make_uint4(f2tf(qv.x), f2tf(qv.y), f2tf(qv.z), f2tf(qv.w));
        }
    }
    if (tid < 64) { sm_m[tid] = -1e30f; sm_l[tid] = 0.f; }

    float acc_o[4][4];
#pragma unroll
    for (int nt = 0; nt < 4; nt++)
#pragma unroll
        for (int e = 0; e < 4; e++) acc_o[nt][e] = 0.f;

    // score-phase chunk assignment (10 warps, one 32x64 chunk each)
    const uint32_t* Ap; const uint32_t* Bp;
    int Arow, Brow;
    int kind;                               // 0=CC, 1=CPF, 2=PCF
    if (wid < 2)      { Ap = Qs; Arow = wid*32;          Bp = Ks; Brow = 0;                 kind = 0; }
    else if (wid < 6) { Ap = Qs; Arow = ((wid-2)&1)*32;  Bp = Ps; Brow = ((wid-2)>>1)*64;   kind = 1; }
    else              { Ap = Ps; Arow = (wid-6)*32;      Bp = Ks; Brow = 0;                 kind = 2; }

    const float s1 = 0.14433756729740643f;      // 1/sqrt(48)

    for (int j0 = 0; j0 < SS; j0 += 64) {
        __syncthreads();   // previous chunk's Pt/Vt/Ks/Ps reads complete

        for (int u = tid; u < 4352; u += 320) SsF[u] = 0.f;

        // ---- loads (threads 0..255; batched LDGs for MLP) ----
        if (tid < 256) {
            const int row = tid >> 4, c4 = tid & 15;
            {   // K
                float4 x0 = *(const float4*)(kbase + (size_t)(j0+row)    * DD + c4*4);
                float4 x1 = *(const float4*)(kbase + (size_t)(j0+row+16) * DD + c4*4);
                float4 x2 = *(const float4*)(kbase + (size_t)(j0+row+32) * DD + c4*4);
                float4 x3 = *(const float4*)(kbase + (size_t)(j0+row+48) * DD + c4*4);
                *(uint4*)&Ks[(row)   *68 + c4*4] = make_uint4(f2tf(x0.x), f2tf(x0.y), f2tf(x0.z), f2tf(x0.w));
                *(uint4*)&Ks[(row+16)*68 + c4*4] = make_uint4(f2tf(x1.x), f2tf(x1.y), f2tf(x1.z), f2tf(x1.w));
                *(uint4*)&Ks[(row+32)*68 + c4*4] = make_uint4(f2tf(x2.x), f2tf(x2.y), f2tf(x2.z), f2tf(x2.w));
                *(uint4*)&Ks[(row+48)*68 + c4*4] = make_uint4(f2tf(x3.x), f2tf(x3.y), f2tf(x3.z), f2tf(x3.w));
            }
            {   // V transposed, e-rotation for STS conflicts
                float4 x[4];
                x[0] = *(const float4*)(vbase + (size_t)(j0+row)    * DD + c4*4);
                x[1] = *(const float4*)(vbase + (size_t)(j0+row+16) * DD + c4*4);
                x[2] = *(const float4*)(vbase + (size_t)(j0+row+32) * DD + c4*4);
                x[3] = *(const float4*)(vbase + (size_t)(j0+row+48) * DD + c4*4);
#pragma unroll
                for (int i = 0; i < 4; i++) {
                    uint32_t ve[4] = {f2tf(x[i].x), f2tf(x[i].y), f2tf(x[i].z), f2tf(x[i].w)};
                    const int jrow = row + i*16;
#pragma unroll
                    for (int e2 = 0; e2 < 4; e2++) {
                        const int e = (e2 + c4) & 3;
                        Vt[(c4*4 + e)*68 + jrow] = ve[e];
                    }
                }
            }
            const int base = i0 - j0 + 449;
#pragma unroll
            for (int half = 0; half < 2; half++) {   // pos band: 8 rows / thread
                float4 x[4];
#pragma unroll
                for (int i = 0; i < 4; i++) {
                    const int pr = row + (half*4 + i)*16;
                    int grow = base + pr;
                    grow = grow < 0 ? 0 : (grow > 1023 ? 1023 : grow);
                    x[i] = *(const float4*)(pptr + (size_t)grow * DD + c4*4);
                }
#pragma unroll
                for (int i = 0; i < 4; i++) {
                    const int pr = row + (half*4 + i)*16;
                    *(uint4*)&Ps[pr*68 + c4*4] = make_uint4(f2tf(x[i].x), f2tf(x[i].y), f2tf(x[i].z), f2tf(x[i].w));
                }
            }
        } else if ((tid - 256) < 64) {
            sm_mask[tid - 256] = mask[(size_t)b_*SS + j0 + tid - 256];
        }
        __syncthreads();

        // ---- score MMAs in two nt-halves (32 live accumulators) ----
#pragma unroll
        for (int hN = 0; hN < 2; hN++) {
            float acc[2][4][4];
#pragma unroll
            for (int mt = 0; mt < 2; mt++)
#pragma unroll
                for (int nt = 0; nt < 4; nt++)
#pragma unroll
                    for (int e = 0; e < 4; e++) acc[mt][nt][e] = 0.f;

#pragma unroll
            for (int ks = 0; ks < 8; ks++) {
                uint32_t a[2][4], b[4][2];
#pragma unroll
                for (int mt = 0; mt < 2; mt++) {
                    const int ra = (Arow + mt*16 + g) * 68 + ks*8 + t;
                    a[mt][0] = Ap[ra];
                    a[mt][1] = Ap[ra + 8*68];
                    a[mt][2] = Ap[ra + 4];
                    a[mt][3] = Ap[ra + 8*68 + 4];
                }
#pragma unroll
                for (int nt = 0; nt < 4; nt++) {
                    const int rb = (Brow + (hN*4 + nt)*8 + g) * 68 + ks*8 + t;
                    b[nt][0] = Bp[rb];
                    b[nt][1] = Bp[rb + 4];
                }
#pragma unroll
                for (int mt = 0; mt < 2; mt++)
#pragma unroll
                    for (int nt = 0; nt < 4; nt++)
                        mma_tf32(acc[mt][nt], a[mt], b[nt]);
            }

            // immediate atomic scatter of this half
            if (kind == 0) {
#pragma unroll
                for (int mt = 0; mt < 2; mt++)
#pragma unroll
                    for (int nt = 0; nt < 4; nt++) {
                        const int r0 = Arow + mt*16 + g;
                        const int c0 = (hN*4 + nt)*8 + 2*t;
                        atomicAdd(&SsF[r0*68 + c0],       acc[mt][nt][0]);
                        atomicAdd(&SsF[r0*68 + c0 + 1],   acc[mt][nt][1]);
                        atomicAdd(&SsF[(r0+8)*68 + c0],   acc[mt][nt][2]);
                        atomicAdd(&SsF[(r0+8)*68 + c0+1], acc[mt][nt][3]);
                    }
            } else if (kind == 1) {     // CPF[ai][p] -> S[ai][ai-p+63] * 0.125
#pragma unroll
                for (int mt = 0; mt < 2; mt++)
#pragma unroll
                    for (int nt = 0; nt < 4; nt++) {
                        const int ai0 = Arow + mt*16 + g;
                        const int p0 = Brow + (hN*4 + nt)*8 + 2*t;
#pragma unroll
                        for (int e = 0; e < 4; e++) {
                            const int ai = ai0 + (e >> 1)*8;
                            const int p  = p0 + (e & 1);
                            const int cj = ai - p + 63;
                            if ((unsigned)cj < 64u)
                                atomicAdd(&SsF[ai*68 + cj], 0.125f * acc[mt][nt][e]);
                        }
                    }
            } else {                    // PCF[r][cj] -> S[r+cj-63][cj]
#pragma unroll
                for (int mt = 0; mt < 2; mt++)
#pragma unroll
                    for (int nt = 0; nt < 4; nt++) {
                        const int r0 = Arow + mt*16 + g;
                        const int c0 = (hN*4 + nt)*8 + 2*t;
#pragma unroll
                        for (int e = 0; e < 4; e++) {
                            const int r  = r0 + (e >> 1)*8;
                            const int cj = c0 + (e & 1);
                            const int ai = r + cj - 63;
                            if ((unsigned)ai < 64u)
                                atomicAdd(&SsF[ai*68 + cj], acc[mt][nt][e]);
                        }
                    }
            }
        }
        __syncthreads();

        // ---- online softmax (threads 0..255); P~ tf32 in place ----
        if (tid < 256) {
            const int row = tid >> 2, q4 = tid & 3;
            float mloc = -1e30f;
#pragma unroll
            for (int c = q4*16; c < q4*16 + 16; c++) {
                const float val = SsF[row*68 + c] * s1 + sm_mask[c];
                SsF[row*68 + c] = val;
                mloc = fmaxf(mloc, val);
            }
            mloc = fmaxf(mloc, __shfl_xor_sync(0xffffffffu, mloc, 1));
            mloc = fmaxf(mloc, __shfl_xor_sync(0xffffffffu, mloc, 2));
            const float mold = sm_m[row];
            const float mnew = fmaxf(mold, mloc);
            float lsum = 0.f;
#pragma unroll
            for (int c = q4*16; c < q4*16 + 16; c++) {
                const float p = __expf(SsF[row*68 + c] - mnew);
                PtU[row*68 + c] = f2tf(p);
                lsum += p;
            }
            lsum += __shfl_xor_sync(0xffffffffu, lsum, 1);
            lsum += __shfl_xor_sync(0xffffffffu, lsum, 2);
            if (q4 == 0) {
                const float sc = __expf(mold - mnew);
                sm_m[row] = mnew;
                sm_scale[row] = sc;
                sm_l[row] = sm_l[row] * sc + lsum;
            }
        }
        __syncthreads();

        // ---- PV: warps 0..7, out tile 64x64, warp tile 16x32 ----
        if (wid < 8) {
            const float sc0 = sm_scale[wm*16 + g];
            const float sc1 = sm_scale[wm*16 + g + 8];
#pragma unroll
            for (int nt = 0; nt < 4; nt++) {
                acc_o[nt][0] *= sc0; acc_o[nt][1] *= sc0;
                acc_o[nt][2] *= sc1; acc_o[nt][3] *= sc1;
            }
#pragma unroll
            for (int ks = 0; ks < 8; ks++) {
                uint32_t a[4], b[4][2];
                const int ra = (wm*16 + g) * 68 + ks*8 + t;
                a[0] = PtU[ra];
                a[1] = PtU[ra + 8*68];
                a[2] = PtU[ra + 4];
                a[3] = PtU[ra + 8*68 + 4];
#pragma unroll
                for (int nt = 0; nt < 4; nt++) {
                    const int rb = (wn*32 + nt*8 + g) * 68 + ks*8 + t;
                    b[nt][0] = Vt[rb];
                    b[nt][1] = Vt[rb + 4];
                }
#pragma unroll
                for (int nt = 0; nt < 4; nt++)
                    mma_tf32(acc_o[nt], a, b[nt]);
            }
        }
    }
    __syncthreads();

    // ---- finalize: out[i][d] = acc_o / l ----
    if (wid < 8) {
        const int r0 = wm*16 + g;
        const float inv0 = 1.f / sm_l[r0];
        const float inv1 = 1.f / sm_l[r0 + 8];
#pragma unroll
        for (int nt = 0; nt < 4; nt++) {
            const int col = wn*32 + nt*8 + 2*t;
            const size_t o0 = ((size_t)b_*SS + i0 + r0)*HIDN + h*DD + col;
            const size_t o1 = ((size_t)b_*SS + i0 + r0 + 8)*HIDN + h*DD + col;
            *(float2*)(out + o0) = make_float2(acc_o[nt][0]*inv0, acc_o[nt][1]*inv0);
            *(float2*)(out + o1) = make_float2(acc_o[nt][2]*inv1, acc_o[nt][3]*inv1);
        }
    }
}

// ---------------- launch ---------------------------------------------------
extern "C" void kernel_launch(void* const* d_in, const int* in_sizes, int n_in,
                              void* d_out, int out_size)
{
    const float* hs  = (const float*)d_in[0];
    const float* msk = (const float*)d_in[1];
    const float* Wq  = (const float*)d_in[3];
    const float* bq  = (const float*)d_in[4];
    const float* Wk  = (const float*)d_in[5];
    const float* bk  = (const float*)d_in[6];
    const float* Wv  = (const float*)d_in[7];
    const float* bv  = (const float*)d_in[8];
    const float* Wpk = (const float*)d_in[9];
    const float* bpk = (const float*)d_in[10];
    const float* rel = (const float*)d_in[11];
    float* out = (float*)d_out;

    cudaFuncSetAttribute(flash_tc, cudaFuncAttributeMaxDynamicSharedMemorySize, FL_SMEM);

    dim3 gg(8, 32, 4);                    // z: Wq, Wk, Wv, Wpk (y>=8 idles for z=3)
    gemm_tc<<<gg, 256>>>(hs, rel, Wq, bq, Wk, bk, Wv, bv, Wpk, bpk);

    dim3 gf(SS/64, BH);                   // (8, 128)
    flash_tc<<<gf, 320, FL_SMEM>>>(msk, out);
}

// round 7
// speedup vs baseline: 1.9609x; 1.5059x over previous
#include <cuda_runtime.h>
#include <cuda_fp16.h>
#include <cstdint>

#define BB   8
#define SS   512
#define HH   16
#define DD   64
#define HIDN 1024
#define BH   (BB*HH)   // 128

// ---------------- scratch (device globals: allocation-free) ----------------
__device__ float g_q[BH*SS*DD];                 // [b,h,s,d] 16MB
__device__ float g_k[BH*SS*DD];
__device__ float g_v[BH*SS*DD];
__device__ float g_pos[HH*1024*DD];             // [h,p,d]   4MB

// ---------------- helpers ---------------------------------------------------
// pack two f32 -> f16x2 word, 'lo' in low half (matches B-frag k-pair order)
__device__ __forceinline__ uint32_t packh2(float lo, float hi) {
    uint32_t u;
    asm("cvt.rn.f16x2.f32 %0, %1, %2;" : "=r"(u) : "f"(hi), "f"(lo));
    return u;
}
__device__ __forceinline__ void mma_f16(float c[4], const uint32_t a[4], const uint32_t b[2]) {
    asm volatile("mma.sync.aligned.m16n8k16.row.col.f32.f16.f16.f32 "
        "{%0,%1,%2,%3}, {%4,%5,%6,%7}, {%8,%9}, {%0,%1,%2,%3};"
        : "+f"(c[0]), "+f"(c[1]), "+f"(c[2]), "+f"(c[3])
        : "r"(a[0]), "r"(a[1]), "r"(a[2]), "r"(a[3]), "r"(b[0]), "r"(b[1]));
}

// ---------------- fp16 HMMA projection GEMM --------------------------------
// C[m,n] = sum_k X[m,k]*W[n,k] + bias[n], scattered to g_q/g_k/g_v/g_pos.
// Block 256 thr, tile 128x128, K-chunk 32 (= 2 x k16). Rows: 16 pairs + 4 pad.
__global__ __launch_bounds__(256, 2) void gemm_tc(
    const float* __restrict__ hs, const float* __restrict__ rel,
    const float* __restrict__ Wq, const float* __restrict__ bq,
    const float* __restrict__ Wk, const float* __restrict__ bk,
    const float* __restrict__ Wv, const float* __restrict__ bv,
    const float* __restrict__ Wpk, const float* __restrict__ bpk)
{
    __shared__ uint32_t As[128*20];
    __shared__ uint32_t Bs[128*20];

    const int which = blockIdx.z;
    if (which == 3 && blockIdx.y >= 8) return;

    const float* X    = (which == 3) ? rel : hs;
    const float* W    = (which == 0) ? Wq : (which == 1) ? Wk : (which == 2) ? Wv : Wpk;
    const float* bias = (which == 0) ? bq : (which == 1) ? bk : (which == 2) ? bv : bpk;
    float* outp       = (which == 0) ? g_q : (which == 1) ? g_k : (which == 2) ? g_v : g_pos;

    const int bm = blockIdx.y * 128;
    const int bn = blockIdx.x * 128;
    const int tid = threadIdx.x;
    const int wid = tid >> 5, lane = tid & 31;
    const int wm = wid >> 1, wn = wid & 1;
    const int g = lane >> 2, t = lane & 3;

    float acc[2][8][4];
#pragma unroll
    for (int mt = 0; mt < 2; mt++)
#pragma unroll
        for (int nt = 0; nt < 8; nt++)
#pragma unroll
            for (int i = 0; i < 4; i++) acc[mt][nt][i] = 0.f;

    const float* Ag = X + (size_t)bm * HIDN;
    const float* Bg = W + (size_t)bn * HIDN;

    for (int kc = 0; kc < 32; kc++) {
        float4 pa[4], pb[4];
#pragma unroll
        for (int i = 0; i < 4; i++) {
            const int fi = i * 256 + tid;
            const int row = fi >> 3, c4 = fi & 7;
            pa[i] = *(const float4*)(Ag + (size_t)row * HIDN + kc * 32 + c4 * 4);
            pb[i] = *(const float4*)(Bg + (size_t)row * HIDN + kc * 32 + c4 * 4);
        }
        __syncthreads();
#pragma unroll
        for (int i = 0; i < 4; i++) {
            const int fi = i * 256 + tid;
            const int row = fi >> 3, c4 = fi & 7;
            As[row*20 + c4*2]     = packh2(pa[i].x, pa[i].y);
            As[row*20 + c4*2 + 1] = packh2(pa[i].z, pa[i].w);
            Bs[row*20 + c4*2]     = packh2(pb[i].x, pb[i].y);
            Bs[row*20 + c4*2 + 1] = packh2(pb[i].z, pb[i].w);
        }
        __syncthreads();
#pragma unroll
        for (int ks = 0; ks < 2; ks++) {           // 2 x k16 = 32
            uint32_t a[2][4], b[8][2];
#pragma unroll
            for (int mt = 0; mt < 2; mt++) {
                const int ra = (wm*32 + mt*16 + g) * 20 + ks*8 + t;
                a[mt][0] = As[ra];
                a[mt][1] = As[ra + 8*20];
                a[mt][2] = As[ra + 4];
                a[mt][3] = As[ra + 8*20 + 4];
            }
#pragma unroll
            for (int nt = 0; nt < 8; nt++) {
                const int rb = (wn*64 + nt*8 + g) * 20 + ks*8 + t;
                b[nt][0] = Bs[rb];
                b[nt][1] = Bs[rb + 4];
            }
#pragma unroll
            for (int mt = 0; mt < 2; mt++)
#pragma unroll
                for (int nt = 0; nt < 8; nt++)
                    mma_f16(acc[mt][nt], a[mt], b[nt]);
        }
    }

#pragma unroll
    for (int mt = 0; mt < 2; mt++) {
#pragma unroll
        for (int nt = 0; nt < 8; nt++) {
            const int n = bn + wn*64 + nt*8 + 2*t;
            const float bv0 = bias[n], bv1 = bias[n+1];
#pragma unroll
            for (int half = 0; half < 2; half++) {
                const int m = bm + wm*32 + mt*16 + g + half*8;
                const float v0 = acc[mt][nt][half*2+0] + bv0;
                const float v1 = acc[mt][nt][half*2+1] + bv1;
                size_t oi;
                if (which < 3) {
                    const int b_ = m >> 9, s = m & 511, h = n >> 6, d = n & 63;
                    oi = (((size_t)(b_*HH + h))*SS + s)*DD + d;
                } else {
                    oi = (((size_t)(n >> 6))*1024 + m)*DD + (n & 63);
                }
                *(float2*)(outp + oi) = make_float2(v0, v1);
            }
        }
    }
}

// ---------------- fused flash kernel (fp16 MMA) ----------------------------
// 320 threads = 10 warps, 2 CTAs/SM. Row stride 36 words (32 half2 + 4 pad).
// smem words: Qs 2304 | Ks 2304 | Ps 4608 | Vt 2304 | Pt2 2304 | Ss 4352 | misc 256
#define FL_SMEM (18432 * 4)   // 73728 B  (x2 = 147456 <= 228KB/SM)

__global__ __launch_bounds__(320, 2) void flash_tc(const float* __restrict__ mask,
                                                   float* __restrict__ out)
{
    extern __shared__ uint32_t smw[];
    uint32_t* Qs  = smw;                    // [64 rows i][36 w] k-pairs of d
    uint32_t* Ks  = smw + 2304;             // [64 rows j][36 w]
    uint32_t* Ps  = smw + 4608;             // [128 rows p][36 w] pos band
    uint32_t* Vt  = smw + 9216;             // [64 rows d][36 w] j-pairs
    __half*   Vth = (__half*)(smw + 9216);
    uint32_t* Pt2 = smw + 11520;            // [64 rows i][36 w] j-pairs (P~ f16)
    float*    SsF = (float*)(smw + 13824);  // [64][68] f32 score accum
    float* sm_m     = (float*)(smw + 18176);
    float* sm_l     = sm_m + 64;
    float* sm_scale = sm_m + 128;
    float* sm_mask  = sm_m + 192;

    const int i0 = blockIdx.x * 64;
    const int bh = blockIdx.y;
    const int b_ = bh >> 4, h = bh & 15;
    const int tid = threadIdx.x;
    const int wid = tid >> 5, lane = tid & 31;
    const int g = lane >> 2, t = lane & 3;
    const int wm = wid >> 1, wn = wid & 1;      // PV warp grid (wid<8): 4x2

    const float* qptr  = g_q + ((size_t)bh*SS + i0) * DD;
    const float* kbase = g_k + (size_t)bh*SS*DD;
    const float* vbase = g_v + (size_t)bh*SS*DD;
    const float* pptr  = g_pos + (size_t)h * 1024 * DD;

    if (tid < 256) {
#pragma unroll
        for (int i = 0; i < 4; i++) {
            const int u = tid + i*256, row = u >> 4, c4 = u & 15;
            float4 qv = *(const float4*)(qptr + (size_t)row * DD + c4*4);
            Qs[row*36 + c4*2]     = packh2(qv.x, qv.y);
            Qs[row*36 + c4*2 + 1] = packh2(qv.z, qv.w);
        }
    }
    if (tid < 64) { sm_m[tid] = -1e30f; sm_l[tid] = 0.f; }

    float acc_o[4][4];
#pragma unroll
    for (int nt = 0; nt < 4; nt++)
#pragma unroll
        for (int e = 0; e < 4; e++) acc_o[nt][e] = 0.f;

    // score-phase chunk assignment (10 warps, one 32x64 chunk each)
    const uint32_t* Ap; const uint32_t* Bp;
    int Arow, Brow;
    int kind;                               // 0=CC, 1=CPF, 2=PCF
    if (wid < 2)      { Ap = Qs; Arow = wid*32;          Bp = Ks; Brow = 0;                 kind = 0; }
    else if (wid < 6) { Ap = Qs; Arow = ((wid-2)&1)*32;  Bp = Ps; Brow = ((wid-2)>>1)*64;   kind = 1; }
    else              { Ap = Ps; Arow = (wid-6)*32;      Bp = Ks; Brow = 0;                 kind = 2; }

    const float s1 = 0.14433756729740643f;      // 1/sqrt(48)

    for (int j0 = 0; j0 < SS; j0 += 64) {
        __syncthreads();   // previous chunk's tile reads complete

        for (int u = tid; u < 4352; u += 320) SsF[u] = 0.f;

        // ---- loads (threads 0..255; batched LDGs) ----
        if (tid < 256) {
            const int row = tid >> 4, c4 = tid & 15;
            {   // K: 4 rows
                float4 x0 = *(const float4*)(kbase + (size_t)(j0+row)    * DD + c4*4);
                float4 x1 = *(const float4*)(kbase + (size_t)(j0+row+16) * DD + c4*4);
                float4 x2 = *(const float4*)(kbase + (size_t)(j0+row+32) * DD + c4*4);
                float4 x3 = *(const float4*)(kbase + (size_t)(j0+row+48) * DD + c4*4);
                Ks[(row)   *36 + c4*2] = packh2(x0.x, x0.y); Ks[(row)   *36 + c4*2+1] = packh2(x0.z, x0.w);
                Ks[(row+16)*36 + c4*2] = packh2(x1.x, x1.y); Ks[(row+16)*36 + c4*2+1] = packh2(x1.z, x1.w);
                Ks[(row+32)*36 + c4*2] = packh2(x2.x, x2.y); Ks[(row+32)*36 + c4*2+1] = packh2(x2.z, x2.w);
                Ks[(row+48)*36 + c4*2] = packh2(x3.x, x3.y); Ks[(row+48)*36 + c4*2+1] = packh2(x3.z, x3.w);
            }
            {   // V: 4 rows, transposed half-stores with e-rotation
                float4 x[4];
                x[0] = *(const float4*)(vbase + (size_t)(j0+row)    * DD + c4*4);
                x[1] = *(const float4*)(vbase + (size_t)(j0+row+16) * DD + c4*4);
                x[2] = *(const float4*)(vbase + (size_t)(j0+row+32) * DD + c4*4);
                x[3] = *(const float4*)(vbase + (size_t)(j0+row+48) * DD + c4*4);
#pragma unroll
                for (int i = 0; i < 4; i++) {
                    const float ve[4] = {x[i].x, x[i].y, x[i].z, x[i].w};
                    const int jrow = row + i*16;
#pragma unroll
                    for (int e2 = 0; e2 < 4; e2++) {
                        const int e = (e2 + c4) & 3;
                        Vth[(c4*4 + e)*72 + jrow] = __float2half_rn(ve[e]);
                    }
                }
            }
            const int base = i0 - j0 + 449;
#pragma unroll
            for (int half = 0; half < 2; half++) {   // pos band: 8 rows / thread
                float4 x[4];
#pragma unroll
                for (int i = 0; i < 4; i++) {
                    const int pr = row + (half*4 + i)*16;
                    int grow = base + pr;
                    grow = grow < 0 ? 0 : (grow > 1023 ? 1023 : grow);
                    x[i] = *(const float4*)(pptr + (size_t)grow * DD + c4*4);
                }
#pragma unroll
                for (int i = 0; i < 4; i++) {
                    const int pr = row + (half*4 + i)*16;
                    Ps[pr*36 + c4*2]     = packh2(x[i].x, x[i].y);
                    Ps[pr*36 + c4*2 + 1] = packh2(x[i].z, x[i].w);
                }
            }
        } else if ((tid - 256) < 64) {
            sm_mask[tid - 256] = mask[(size_t)b_*SS + j0 + tid - 256];
        }
        __syncthreads();

        // ---- score MMAs in two nt-halves (32 live accumulators) ----
#pragma unroll
        for (int hN = 0; hN < 2; hN++) {
            float acc[2][4][4];
#pragma unroll
            for (int mt = 0; mt < 2; mt++)
#pragma unroll
                for (int nt = 0; nt < 4; nt++)
#pragma unroll
                    for (int e = 0; e < 4; e++) acc[mt][nt][e] = 0.f;

#pragma unroll
            for (int ks = 0; ks < 4; ks++) {        // 4 x k16 = 64
                uint32_t a[2][4], b[4][2];
#pragma unroll
                for (int mt = 0; mt < 2; mt++) {
                    const int ra = (Arow + mt*16 + g) * 36 + ks*8 + t;
                    a[mt][0] = Ap[ra];
                    a[mt][1] = Ap[ra + 8*36];
                    a[mt][2] = Ap[ra + 4];
                    a[mt][3] = Ap[ra + 8*36 + 4];
                }
#pragma unroll
                for (int nt = 0; nt < 4; nt++) {
                    const int rb = (Brow + (hN*4 + nt)*8 + g) * 36 + ks*8 + t;
                    b[nt][0] = Bp[rb];
                    b[nt][1] = Bp[rb + 4];
                }
#pragma unroll
                for (int mt = 0; mt < 2; mt++)
#pragma unroll
                    for (int nt = 0; nt < 4; nt++)
                        mma_f16(acc[mt][nt], a[mt], b[nt]);
            }

            // immediate atomic scatter of this half
            if (kind == 0) {
#pragma unroll
                for (int mt = 0; mt < 2; mt++)
#pragma unroll
                    for (int nt = 0; nt < 4; nt++) {
                        const int r0 = Arow + mt*16 + g;
                        const int c0 = (hN*4 + nt)*8 + 2*t;
                        atomicAdd(&SsF[r0*68 + c0],       acc[mt][nt][0]);
                        atomicAdd(&SsF[r0*68 + c0 + 1],   acc[mt][nt][1]);
                        atomicAdd(&SsF[(r0+8)*68 + c0],   acc[mt][nt][2]);
                        atomicAdd(&SsF[(r0+8)*68 + c0+1], acc[mt][nt][3]);
                    }
            } else if (kind == 1) {     // CPF[ai][p] -> S[ai][ai-p+63] * 0.125
#pragma unroll
                for (int mt = 0; mt < 2; mt++)
#pragma unroll
                    for (int nt = 0; nt < 4; nt++) {
                        const int ai0 = Arow + mt*16 + g;
                        const int p0 = Brow + (hN*4 + nt)*8 + 2*t;
#pragma unroll
                        for (int e = 0; e < 4; e++) {
                            const int ai = ai0 + (e >> 1)*8;
                            const int p  = p0 + (e & 1);
                            const int cj = ai - p + 63;
                            if ((unsigned)cj < 64u)
                                atomicAdd(&SsF[ai*68 + cj], 0.125f * acc[mt][nt][e]);
                        }
                    }
            } else {                    // PCF[r][cj] -> S[r+cj-63][cj]
#pragma unroll
                for (int mt = 0; mt < 2; mt++)
#pragma unroll
                    for (int nt = 0; nt < 4; nt++) {
                        const int r0 = Arow + mt*16 + g;
                        const int c0 = (hN*4 + nt)*8 + 2*t;
#pragma unroll
                        for (int e = 0; e < 4; e++) {
                            const int r  = r0 + (e >> 1)*8;
                            const int cj = c0 + (e & 1);
                            const int ai = r + cj - 63;
                            if ((unsigned)ai < 64u)
                                atomicAdd(&SsF[ai*68 + cj], acc[mt][nt][e]);
                        }
                    }
            }
        }
        __syncthreads();

        // ---- online softmax (threads 0..255); P~ packed f16x2 ----
        if (tid < 256) {
            const int row = tid >> 2, q4 = tid & 3;
            float mloc = -1e30f;
#pragma unroll
            for (int c = q4*16; c < q4*16 + 16; c++) {
                const float val = SsF[row*68 + c] * s1 + sm_mask[c];
                SsF[row*68 + c] = val;
                mloc = fmaxf(mloc, val);
            }
            mloc = fmaxf(mloc, __shfl_xor_sync(0xffffffffu, mloc, 1));
            mloc = fmaxf(mloc, __shfl_xor_sync(0xffffffffu, mloc, 2));
            const float mold = sm_m[row];
            const float mnew = fmaxf(mold, mloc);
            float lsum = 0.f;
#pragma unroll
            for (int p = q4*8; p < q4*8 + 8; p++) {
                const float e0 = __expf(SsF[row*68 + 2*p]     - mnew);
                const float e1 = __expf(SsF[row*68 + 2*p + 1] - mnew);
                Pt2[row*36 + p] = packh2(e0, e1);
                lsum += e0 + e1;
            }
            lsum += __shfl_xor_sync(0xffffffffu, lsum, 1);
            lsum += __shfl_xor_sync(0xffffffffu, lsum, 2);
            if (q4 == 0) {
                const float sc = __expf(mold - mnew);
                sm_m[row] = mnew;
                sm_scale[row] = sc;
                sm_l[row] = sm_l[row] * sc + lsum;
            }
        }
        __syncthreads();

        // ---- PV: warps 0..7, out tile 64x64, warp tile 16x32 ----
        if (wid < 8) {
            const float sc0 = sm_scale[wm*16 + g];
            const float sc1 = sm_scale[wm*16 + g + 8];
#pragma unroll
            for (int nt = 0; nt < 4; nt++) {
                acc_o[nt][0] *= sc0; acc_o[nt][1] *= sc0;
                acc_o[nt][2] *= sc1; acc_o[nt][3] *= sc1;
            }
#pragma unroll
            for (int ks = 0; ks < 4; ks++) {        // k = j, 4 x k16 = 64
                uint32_t a[4], b[4][2];
                const int ra = (wm*16 + g) * 36 + ks*8 + t;
                a[0] = Pt2[ra];
                a[1] = Pt2[ra + 8*36];
                a[2] = Pt2[ra + 4];
                a[3] = Pt2[ra + 8*36 + 4];
#pragma unroll
                for (int nt = 0; nt < 4; nt++) {
                    const int rb = (wn*32 + nt*8 + g) * 36 + ks*8 + t;
                    b[nt][0] = Vt[rb];
                    b[nt][1] = Vt[rb + 4];
                }
#pragma unroll
                for (int nt = 0; nt < 4; nt++)
                    mma_f16(acc_o[nt], a, b[nt]);
            }
        }
    }
    __syncthreads();

    // ---- finalize: out[i][d] = acc_o / l ----
    if (wid < 8) {
        const int r0 = wm*16 + g;
        const float inv0 = 1.f / sm_l[r0];
        const float inv1 = 1.f / sm_l[r0 + 8];
#pragma unroll
        for (int nt = 0; nt < 4; nt++) {
            const int col = wn*32 + nt*8 + 2*t;
            const size_t o0 = ((size_t)b_*SS + i0 + r0)*HIDN + h*DD + col;
            const size_t o1 = ((size_t)b_*SS + i0 + r0 + 8)*HIDN + h*DD + col;
            *(float2*)(out + o0) = make_float2(acc_o[nt][0]*inv0, acc_o[nt][1]*inv0);
            *(float2*)(out + o1) = make_float2(acc_o[nt][2]*inv1, acc_o[nt][3]*inv1);
        }
    }
}

// ---------------- launch ---------------------------------------------------
extern "C" void kernel_launch(void* const* d_in, const int* in_sizes, int n_in,
                              void* d_out, int out_size)
{
    const float* hs  = (const float*)d_in[0];
    const float* msk = (const float*)d_in[1];
    const float* Wq  = (const float*)d_in[3];
    const float* bq  = (const float*)d_in[4];
    const float* Wk  = (const float*)d_in[5];
    const float* bk  = (const float*)d_in[6];
    const float* Wv  = (const float*)d_in[7];
    const float* bv  = (const float*)d_in[8];
    const float* Wpk = (const float*)d_in[9];
    const float* bpk = (const float*)d_in[10];
    const float* rel = (const float*)d_in[11];
    float* out = (float*)d_out;

    cudaFuncSetAttribute(flash_tc, cudaFuncAttributeMaxDynamicSharedMemorySize, FL_SMEM);

    dim3 gg(8, 32, 4);                    // z: Wq, Wk, Wv, Wpk (y>=8 idles for z=3)
    gemm_tc<<<gg, 256>>>(hs, rel, Wq, bq, Wk, bk, Wv, bv, Wpk, bpk);

    dim3 gf(SS/64, BH);                   // (8, 128)
    flash_tc<<<gf, 320, FL_SMEM>>>(msk, out);
}

// round 8
// speedup vs baseline: 2.4690x; 1.2591x over previous
#include <cuda_runtime.h>
#include <cuda_fp16.h>
#include <cstdint>

#define BB   8
#define SS   512
#define HH   16
#define DD   64
#define HIDN 1024
#define BH   (BB*HH)   // 128

// ---------------- scratch (device globals: allocation-free) ----------------
__device__ float g_q[BH*SS*DD];                 // [b,h,s,d] 16MB
__device__ float g_k[BH*SS*DD];
__device__ float g_v[BH*SS*DD];
__device__ float g_pos[HH*1024*DD];             // [h,p,d]   4MB

// ---------------- helpers ---------------------------------------------------
// pack two f32 -> f16x2 word, 'lo' in low half
__device__ __forceinline__ uint32_t packh2(float lo, float hi) {
    uint32_t u;
    asm("cvt.rn.f16x2.f32 %0, %1, %2;" : "=r"(u) : "f"(hi), "f"(lo));
    return u;
}
__device__ __forceinline__ void mma_f16(float c[4], const uint32_t a[4], const uint32_t b[2]) {
    asm volatile("mma.sync.aligned.m16n8k16.row.col.f32.f16.f16.f32 "
        "{%0,%1,%2,%3}, {%4,%5,%6,%7}, {%8,%9}, {%0,%1,%2,%3};"
        : "+f"(c[0]), "+f"(c[1]), "+f"(c[2]), "+f"(c[3])
        : "r"(a[0]), "r"(a[1]), "r"(a[2]), "r"(a[3]), "r"(b[0]), "r"(b[1]));
}

// ---------------- fp16 HMMA projection GEMM (unchanged from R7) ------------
__global__ __launch_bounds__(256, 2) void gemm_tc(
    const float* __restrict__ hs, const float* __restrict__ rel,
    const float* __restrict__ Wq, const float* __restrict__ bq,
    const float* __restrict__ Wk, const float* __restrict__ bk,
    const float* __restrict__ Wv, const float* __restrict__ bv,
    const float* __restrict__ Wpk, const float* __restrict__ bpk)
{
    __shared__ uint32_t As[128*20];
    __shared__ uint32_t Bs[128*20];

    const int which = blockIdx.z;
    if (which == 3 && blockIdx.y >= 8) return;

    const float* X    = (which == 3) ? rel : hs;
    const float* W    = (which == 0) ? Wq : (which == 1) ? Wk : (which == 2) ? Wv : Wpk;
    const float* bias = (which == 0) ? bq : (which == 1) ? bk : (which == 2) ? bv : bpk;
    float* outp       = (which == 0) ? g_q : (which == 1) ? g_k : (which == 2) ? g_v : g_pos;

    const int bm = blockIdx.y * 128;
    const int bn = blockIdx.x * 128;
    const int tid = threadIdx.x;
    const int wid = tid >> 5, lane = tid & 31;
    const int wm = wid >> 1, wn = wid & 1;
    const int g = lane >> 2, t = lane & 3;

    float acc[2][8][4];
#pragma unroll
    for (int mt = 0; mt < 2; mt++)
#pragma unroll
        for (int nt = 0; nt < 8; nt++)
#pragma unroll
            for (int i = 0; i < 4; i++) acc[mt][nt][i] = 0.f;

    const float* Ag = X + (size_t)bm * HIDN;
    const float* Bg = W + (size_t)bn * HIDN;

    for (int kc = 0; kc < 32; kc++) {
        float4 pa[4], pb[4];
#pragma unroll
        for (int i = 0; i < 4; i++) {
            const int fi = i * 256 + tid;
            const int row = fi >> 3, c4 = fi & 7;
            pa[i] = *(const float4*)(Ag + (size_t)row * HIDN + kc * 32 + c4 * 4);
            pb[i] = *(const float4*)(Bg + (size_t)row * HIDN + kc * 32 + c4 * 4);
        }
        __syncthreads();
#pragma unroll
        for (int i = 0; i < 4; i++) {
            const int fi = i * 256 + tid;
            const int row = fi >> 3, c4 = fi & 7;
            As[row*20 + c4*2]     = packh2(pa[i].x, pa[i].y);
            As[row*20 + c4*2 + 1] = packh2(pa[i].z, pa[i].w);
            Bs[row*20 + c4*2]     = packh2(pb[i].x, pb[i].y);
            Bs[row*20 + c4*2 + 1] = packh2(pb[i].z, pb[i].w);
        }
        __syncthreads();
#pragma unroll
        for (int ks = 0; ks < 2; ks++) {
            uint32_t a[2][4], b[8][2];
#pragma unroll
            for (int mt = 0; mt < 2; mt++) {
                const int ra = (wm*32 + mt*16 + g) * 20 + ks*8 + t;
                a[mt][0] = As[ra];
                a[mt][1] = As[ra + 8*20];
                a[mt][2] = As[ra + 4];
                a[mt][3] = As[ra + 8*20 + 4];
            }
#pragma unroll
            for (int nt = 0; nt < 8; nt++) {
                const int rb = (wn*64 + nt*8 + g) * 20 + ks*8 + t;
                b[nt][0] = Bs[rb];
                b[nt][1] = Bs[rb + 4];
            }
#pragma unroll
            for (int mt = 0; mt < 2; mt++)
#pragma unroll
                for (int nt = 0; nt < 8; nt++)
                    mma_f16(acc[mt][nt], a[mt], b[nt]);
        }
    }

#pragma unroll
    for (int mt = 0; mt < 2; mt++) {
#pragma unroll
        for (int nt = 0; nt < 8; nt++) {
            const int n = bn + wn*64 + nt*8 + 2*t;
            const float bv0 = bias[n], bv1 = bias[n+1];
#pragma unroll
            for (int half = 0; half < 2; half++) {
                const int m = bm + wm*32 + mt*16 + g + half*8;
                const float v0 = acc[mt][nt][half*2+0] + bv0;
                const float v1 = acc[mt][nt][half*2+1] + bv1;
                size_t oi;
                if (which < 3) {
                    const int b_ = m >> 9, s = m & 511, h = n >> 6, d = n & 63;
                    oi = (((size_t)(b_*HH + h))*SS + s)*DD + d;
                } else {
                    oi = (((size_t)(n >> 6))*1024 + m)*DD + (n & 63);
                }
                *(float2*)(outp + oi) = make_float2(v0, v1);
            }
        }
    }
}

// ---------------- fused flash kernel (fp16 MMA, shear-store scatter) -------
// 320 threads = 10 warps, 2 CTAs/SM. Each score kind writes its OWN buffer
// with plain stores (injective + full band coverage); softmax combines reads.
// words: Qs 2304 | Ks 2304 | Ps 4608 | Vt 2304 | Pt2 2304 | SsF 4352 | B1 4352 | B2 4352 | misc 256
#define FL_SMEM (27136 * 4)   // 108544 B (x2 = 217088 <= 228KB/SM)

__global__ __launch_bounds__(320, 2) void flash_tc(const float* __restrict__ mask,
                                                   float* __restrict__ out)
{
    extern __shared__ uint32_t smw[];
    uint32_t* Qs  = smw;                    // [64 i][36 w] k-pairs of d
    uint32_t* Ks  = smw + 2304;             // [64 j][36 w]
    uint32_t* Ps  = smw + 4608;             // [128 p][36 w] pos band
    uint32_t* Vt  = smw + 9216;             // [64 d][36 w] j-pairs
    __half*   Vth = (__half*)(smw + 9216);
    uint32_t* Pt2 = smw + 11520;            // [64 i][36 w] j-pairs (P~ f16)
    float*    SsF = (float*)(smw + 13824);  // [64][68] CC
    float*    B1  = (float*)(smw + 18176);  // [64][68] sheared CPF
    float*    B2  = (float*)(smw + 22528);  // [64][68] sheared PCF
    float* sm_m     = (float*)(smw + 26880);
    float* sm_l     = sm_m + 64;
    float* sm_scale = sm_m + 128;
    float* sm_mask  = sm_m + 192;

    const int i0 = blockIdx.x * 64;
    const int bh = blockIdx.y;
    const int b_ = bh >> 4, h = bh & 15;
    const int tid = threadIdx.x;
    const int wid = tid >> 5, lane = tid & 31;
    const int g = lane >> 2, t = lane & 3;
    const int wm = wid >> 1, wn = wid & 1;      // PV warp grid (wid<8): 4x2

    const float* qptr  = g_q + ((size_t)bh*SS + i0) * DD;
    const float* kbase = g_k + (size_t)bh*SS*DD;
    const float* vbase = g_v + (size_t)bh*SS*DD;
    const float* pptr  = g_pos + (size_t)h * 1024 * DD;

    if (tid < 256) {
#pragma unroll
        for (int i = 0; i < 4; i++) {
            const int u = tid + i*256, row = u >> 4, c4 = u & 15;
            float4 qv = *(const float4*)(qptr + (size_t)row * DD + c4*4);
            Qs[row*36 + c4*2]     = packh2(qv.x, qv.y);
            Qs[row*36 + c4*2 + 1] = packh2(qv.z, qv.w);
        }
    }
    if (tid < 64) { sm_m[tid] = -1e30f; sm_l[tid] = 0.f; }

    float acc_o[4][4];
#pragma unroll
    for (int nt = 0; nt < 4; nt++)
#pragma unroll
        for (int e = 0; e < 4; e++) acc_o[nt][e] = 0.f;

    // score-phase chunk assignment (10 warps, one 32x64 chunk each)
    const uint32_t* Ap; const uint32_t* Bp;
    int Arow, Brow;
    int kind;                               // 0=CC, 1=CPF, 2=PCF
    if (wid < 2)      { Ap = Qs; Arow = wid*32;          Bp = Ks; Brow = 0;                 kind = 0; }
    else if (wid < 6) { Ap = Qs; Arow = ((wid-2)&1)*32;  Bp = Ps; Brow = ((wid-2)>>1)*64;   kind = 1; }
    else              { Ap = Ps; Arow = (wid-6)*32;      Bp = Ks; Brow = 0;                 kind = 2; }

    const float s1 = 0.14433756729740643f;      // 1/sqrt(48)

    for (int j0 = 0; j0 < SS; j0 += 64) {
        __syncthreads();   // previous chunk's tile reads complete

        // ---- loads (threads 0..255; batched LDGs) ----
        if (tid < 256) {
            const int row = tid >> 4, c4 = tid & 15;
            {   // K: 4 rows
                float4 x0 = *(const float4*)(kbase + (size_t)(j0+row)    * DD + c4*4);
                float4 x1 = *(const float4*)(kbase + (size_t)(j0+row+16) * DD + c4*4);
                float4 x2 = *(const float4*)(kbase + (size_t)(j0+row+32) * DD + c4*4);
                float4 x3 = *(const float4*)(kbase + (size_t)(j0+row+48) * DD + c4*4);
                Ks[(row)   *36 + c4*2] = packh2(x0.x, x0.y); Ks[(row)   *36 + c4*2+1] = packh2(x0.z, x0.w);
                Ks[(row+16)*36 + c4*2] = packh2(x1.x, x1.y); Ks[(row+16)*36 + c4*2+1] = packh2(x1.z, x1.w);
                Ks[(row+32)*36 + c4*2] = packh2(x2.x, x2.y); Ks[(row+32)*36 + c4*2+1] = packh2(x2.z, x2.w);
                Ks[(row+48)*36 + c4*2] = packh2(x3.x, x3.y); Ks[(row+48)*36 + c4*2+1] = packh2(x3.z, x3.w);
            }
            {   // V: 4 rows, transposed half-stores with e-rotation
                float4 x[4];
                x[0] = *(const float4*)(vbase + (size_t)(j0+row)    * DD + c4*4);
                x[1] = *(const float4*)(vbase + (size_t)(j0+row+16) * DD + c4*4);
                x[2] = *(const float4*)(vbase + (size_t)(j0+row+32) * DD + c4*4);
                x[3] = *(const float4*)(vbase + (size_t)(j0+row+48) * DD + c4*4);
#pragma unroll
                for (int i = 0; i < 4; i++) {
                    const float ve[4] = {x[i].x, x[i].y, x[i].z, x[i].w};
                    const int jrow = row + i*16;
#pragma unroll
                    for (int e2 = 0; e2 < 4; e2++) {
                        const int e = (e2 + c4) & 3;
                        Vth[(c4*4 + e)*72 + jrow] = __float2half_rn(ve[e]);
                    }
                }
            }
            const int base = i0 - j0 + 449;
#pragma unroll
            for (int half = 0; half < 2; half++) {   // pos band: 8 rows / thread
                float4 x[4];
#pragma unroll
                for (int i = 0; i < 4; i++) {
                    const int pr = row + (half*4 + i)*16;
                    int grow = base + pr;
                    grow = grow < 0 ? 0 : (grow > 1023 ? 1023 : grow);
                    x[i] = *(const float4*)(pptr + (size_t)grow * DD + c4*4);
                }
#pragma unroll
                for (int i = 0; i < 4; i++) {
                    const int pr = row + (half*4 + i)*16;
                    Ps[pr*36 + c4*2]     = packh2(x[i].x, x[i].y);
                    Ps[pr*36 + c4*2 + 1] = packh2(x[i].z, x[i].w);
                }
            }
        } else if ((tid - 256) < 64) {
            sm_mask[tid - 256] = mask[(size_t)b_*SS + j0 + tid - 256];
        }
        __syncthreads();

        // ---- score MMAs in two nt-halves; plain shear-stores per kind ----
#pragma unroll
        for (int hN = 0; hN < 2; hN++) {
            float acc[2][4][4];
#pragma unroll
            for (int mt = 0; mt < 2; mt++)
#pragma unroll
                for (int nt = 0; nt < 4; nt++)
#pragma unroll
                    for (int e = 0; e < 4; e++) acc[mt][nt][e] = 0.f;

#pragma unroll
            for (int ks = 0; ks < 4; ks++) {
                uint32_t a[2][4], b[4][2];
#pragma unroll
                for (int mt = 0; mt < 2; mt++) {
                    const int ra = (Arow + mt*16 + g) * 36 + ks*8 + t;
                    a[mt][0] = Ap[ra];
                    a[mt][1] = Ap[ra + 8*36];
                    a[mt][2] = Ap[ra + 4];
                    a[mt][3] = Ap[ra + 8*36 + 4];
                }
#pragma unroll
                for (int nt = 0; nt < 4; nt++) {
                    const int rb = (Brow + (hN*4 + nt)*8 + g) * 36 + ks*8 + t;
                    b[nt][0] = Bp[rb];
                    b[nt][1] = Bp[rb + 4];
                }
#pragma unroll
                for (int mt = 0; mt < 2; mt++)
#pragma unroll
                    for (int nt = 0; nt < 4; nt++)
                        mma_f16(acc[mt][nt], a[mt], b[nt]);
            }

            if (kind == 0) {              // CC -> SsF, dense float2 stores
#pragma unroll
                for (int mt = 0; mt < 2; mt++)
#pragma unroll
                    for (int nt = 0; nt < 4; nt++) {
                        const int r0 = Arow + mt*16 + g;
                        const int c0 = (hN*4 + nt)*8 + 2*t;
                        *(float2*)&SsF[r0*68 + c0]     = make_float2(acc[mt][nt][0], acc[mt][nt][1]);
                        *(float2*)&SsF[(r0+8)*68 + c0] = make_float2(acc[mt][nt][2], acc[mt][nt][3]);
                    }
            } else if (kind == 1) {       // CPF[ai][p] -> B1[ai][ai-p+63]
#pragma unroll
                for (int mt = 0; mt < 2; mt++)
#pragma unroll
                    for (int nt = 0; nt < 4; nt++) {
                        const int ai0 = Arow + mt*16 + g;
                        const int p0 = Brow + (hN*4 + nt)*8 + 2*t;
#pragma unroll
                        for (int e = 0; e < 4; e++) {
                            const int ai = ai0 + (e >> 1)*8;
                            const int p  = p0 + (e & 1);
                            const int cj = ai - p + 63;
                            if ((unsigned)cj < 64u)
                                B1[ai*68 + cj] = acc[mt][nt][e];
                        }
                    }
            } else {                      // PCF[r][cj] -> B2[r+cj-63][cj]
#pragma unroll
                for (int mt = 0; mt < 2; mt++)
#pragma unroll
                    for (int nt = 0; nt < 4; nt++) {
                        const int r0 = Arow + mt*16 + g;
                        const int c0 = (hN*4 + nt)*8 + 2*t;
#pragma unroll
                        for (int e = 0; e < 4; e++) {
                            const int r  = r0 + (e >> 1)*8;
                            const int cj = c0 + (e & 1);
                            const int ai = r + cj - 63;
                            if ((unsigned)ai < 64u)
                                B2[ai*68 + cj] = acc[mt][nt][e];
                        }
                    }
            }
        }
        __syncthreads();

        // ---- online softmax (threads 0..255); combine 3 buffers on read ----
        if (tid < 256) {
            const int row = tid >> 2, q4 = tid & 3;
            float v[16];
            float mloc = -1e30f;
#pragma unroll
            for (int i = 0; i < 16; i++) {
                const int c = q4*16 + i;
                const float val = (SsF[row*68 + c] + B2[row*68 + c]
                                   + 0.125f * B1[row*68 + c]) * s1 + sm_mask[c];
                v[i] = val;
                mloc = fmaxf(mloc, val);
            }
            mloc = fmaxf(mloc, __shfl_xor_sync(0xffffffffu, mloc, 1));
            mloc = fmaxf(mloc, __shfl_xor_sync(0xffffffffu, mloc, 2));
            const float mold = sm_m[row];
            const float mnew = fmaxf(mold, mloc);
            float lsum = 0.f;
#pragma unroll
            for (int i = 0; i < 8; i++) {
                const float e0 = __expf(v[2*i]   - mnew);
                const float e1 = __expf(v[2*i+1] - mnew);
                Pt2[row*36 + q4*8 + i] = packh2(e0, e1);
                lsum += e0 + e1;
            }
            lsum += __shfl_xor_sync(0xffffffffu, lsum, 1);
            lsum += __shfl_xor_sync(0xffffffffu, lsum, 2);
            if (q4 == 0) {
                const float sc = __expf(mold - mnew);
                sm_m[row] = mnew;
                sm_scale[row] = sc;
                sm_l[row] = sm_l[row] * sc + lsum;
            }
        }
        __syncthreads();

        // ---- PV: warps 0..7, out tile 64x64, warp tile 16x32 ----
        if (wid < 8) {
            const float sc0 = sm_scale[wm*16 + g];
            const float sc1 = sm_scale[wm*16 + g + 8];
#pragma unroll
            for (int nt = 0; nt < 4; nt++) {
                acc_o[nt][0] *= sc0; acc_o[nt][1] *= sc0;
                acc_o[nt][2] *= sc1; acc_o[nt][3] *= sc1;
            }
#pragma unroll
            for (int ks = 0; ks < 4; ks++) {
                uint32_t a[4], b[4][2];
                const int ra = (wm*16 + g) * 36 + ks*8 + t;
                a[0] = Pt2[ra];
                a[1] = Pt2[ra + 8*36];
                a[2] = Pt2[ra + 4];
                a[3] = Pt2[ra + 8*36 + 4];
#pragma unroll
                for (int nt = 0; nt < 4; nt++) {
                    const int rb = (wn*32 + nt*8 + g) * 36 + ks*8 + t;
                    b[nt][0] = Vt[rb];
                    b[nt][1] = Vt[rb + 4];
                }
#pragma unroll
                for (int nt = 0; nt < 4; nt++)
                    mma_f16(acc_o[nt], a, b[nt]);
            }
        }
    }
    __syncthreads();

    // ---- finalize: out[i][d] = acc_o / l ----
    if (wid < 8) {
        const int r0 = wm*16 + g;
        const float inv0 = 1.f / sm_l[r0];
        const float inv1 = 1.f / sm_l[r0 + 8];
#pragma unroll
        for (int nt = 0; nt < 4; nt++) {
            const int col = wn*32 + nt*8 + 2*t;
            const size_t o0 = ((size_t)b_*SS + i0 + r0)*HIDN + h*DD + col;
            const size_t o1 = ((size_t)b_*SS + i0 + r0 + 8)*HIDN + h*DD + col;
            *(float2*)(out + o0) = make_float2(acc_o[nt][0]*inv0, acc_o[nt][1]*inv0);
            *(float2*)(out + o1) = make_float2(acc_o[nt][2]*inv1, acc_o[nt][3]*inv1);
        }
    }
}

// ---------------- launch ---------------------------------------------------
extern "C" void kernel_launch(void* const* d_in, const int* in_sizes, int n_in,
                              void* d_out, int out_size)
{
    const float* hs  = (const float*)d_in[0];
    const float* msk = (const float*)d_in[1];
    const float* Wq  = (const float*)d_in[3];
    const float* bq  = (const float*)d_in[4];
    const float* Wk  = (const float*)d_in[5];
    const float* bk  = (const float*)d_in[6];
    const float* Wv  = (const float*)d_in[7];
    const float* bv  = (const float*)d_in[8];
    const float* Wpk = (const float*)d_in[9];
    const float* bpk = (const float*)d_in[10];
    const float* rel = (const float*)d_in[11];
    float* out = (float*)d_out;

    cudaFuncSetAttribute(flash_tc, cudaFuncAttributeMaxDynamicSharedMemorySize, FL_SMEM);

    dim3 gg(8, 32, 4);                    // z: Wq, Wk, Wv, Wpk (y>=8 idles for z=3)
    gemm_tc<<<gg, 256>>>(hs, rel, Wq, bq, Wk, bk, Wv, bv, Wpk, bpk);

    dim3 gf(SS/64, BH);                   // (8, 128)
    flash_tc<<<gf, 320, FL_SMEM>>>(msk, out);
}

// round 9
// speedup vs baseline: 2.5500x; 1.0328x over previous
#include <cuda_runtime.h>
#include <cuda_fp16.h>
#include <cstdint>

#define BB   8
#define SS   512
#define HH   16
#define DD   64
#define HIDN 1024
#define BH   (BB*HH)   // 128

// ---------------- scratch (device globals: allocation-free) ----------------
__device__ float g_q[BH*SS*DD];                 // [b,h,s,d] 16MB
__device__ float g_k[BH*SS*DD];
__device__ float g_v[BH*SS*DD];
__device__ float g_pos[HH*1024*DD];             // [h,p,d]   4MB

// ---------------- helpers ---------------------------------------------------
__device__ __forceinline__ uint32_t packh2(float lo, float hi) {
    uint32_t u;
    asm("cvt.rn.f16x2.f32 %0, %1, %2;" : "=r"(u) : "f"(hi), "f"(lo));
    return u;
}
__device__ __forceinline__ uint32_t smaddr(const void* p) {
    uint32_t a;
    asm("{ .reg .u64 t; cvta.to.shared.u64 t, %1; cvt.u32.u64 %0, t; }" : "=r"(a) : "l"(p));
    return a;
}
__device__ __forceinline__ void mma_f16(float c[4], const uint32_t a[4], const uint32_t b[2]) {
    asm volatile("mma.sync.aligned.m16n8k16.row.col.f32.f16.f16.f32 "
        "{%0,%1,%2,%3}, {%4,%5,%6,%7}, {%8,%9}, {%0,%1,%2,%3};"
        : "+f"(c[0]), "+f"(c[1]), "+f"(c[2]), "+f"(c[3])
        : "r"(a[0]), "r"(a[1]), "r"(a[2]), "r"(a[3]), "r"(b[0]), "r"(b[1]));
}
__device__ __forceinline__ void ldm_x4(uint32_t& r0, uint32_t& r1, uint32_t& r2, uint32_t& r3,
                                       uint32_t addr) {
    asm volatile("ldmatrix.sync.aligned.m8n8.x4.shared.b16 {%0,%1,%2,%3}, [%4];"
        : "=r"(r0), "=r"(r1), "=r"(r2), "=r"(r3) : "r"(addr));
}

// fragment-base lane offsets (shared by A-style and B-style ldmatrix x4)
//   A tile (16 rows x k16): row = base + (lane&15), colw = +4 if lane>=16
//   B tiles (2 x 8 rows x k16): row = base + ((lane>>4)<<3) + (lane&7), colw = +4 if (lane>>3)&1
#define A_ROW(lane)  ((lane) & 15)
#define A_COL(lane)  ((((lane) >> 4) & 1) << 2)
#define B_ROW(lane)  (((((lane) >> 4) & 1) << 3) + ((lane) & 7))
#define B_COL(lane)  ((((lane) >> 3) & 1) << 2)

// ---------------- fp16 HMMA projection GEMM (ldmatrix fragments) -----------
__global__ __launch_bounds__(256, 2) void gemm_tc(
    const float* __restrict__ hs, const float* __restrict__ rel,
    const float* __restrict__ Wq, const float* __restrict__ bq,
    const float* __restrict__ Wk, const float* __restrict__ bk,
    const float* __restrict__ Wv, const float* __restrict__ bv,
    const float* __restrict__ Wpk, const float* __restrict__ bpk)
{
    __shared__ uint32_t As[128*20];
    __shared__ uint32_t Bs[128*20];

    const int which = blockIdx.z;
    if (which == 3 && blockIdx.y >= 8) return;

    const float* X    = (which == 3) ? rel : hs;
    const float* W    = (which == 0) ? Wq : (which == 1) ? Wk : (which == 2) ? Wv : Wpk;
    const float* bias = (which == 0) ? bq : (which == 1) ? bk : (which == 2) ? bv : bpk;
    float* outp       = (which == 0) ? g_q : (which == 1) ? g_k : (which == 2) ? g_v : g_pos;

    const int bm = blockIdx.y * 128;
    const int bn = blockIdx.x * 128;
    const int tid = threadIdx.x;
    const int wid = tid >> 5, lane = tid & 31;
    const int wm = wid >> 1, wn = wid & 1;
    const int g = lane >> 2, t = lane & 3;

    float acc[2][8][4];
#pragma unroll
    for (int mt = 0; mt < 2; mt++)
#pragma unroll
        for (int nt = 0; nt < 8; nt++)
#pragma unroll
            for (int i = 0; i < 4; i++) acc[mt][nt][i] = 0.f;

    const float* Ag = X + (size_t)bm * HIDN;
    const float* Bg = W + (size_t)bn * HIDN;

    const uint32_t aFB = smaddr(&As[(wm*32 + A_ROW(lane))*20 + A_COL(lane)]);
    const uint32_t bFB = smaddr(&Bs[(wn*64 + B_ROW(lane))*20 + B_COL(lane)]);

    for (int kc = 0; kc < 32; kc++) {
        float4 pa[4], pb[4];
#pragma unroll
        for (int i = 0; i < 4; i++) {
            const int fi = i * 256 + tid;
            const int row = fi >> 3, c4 = fi & 7;
            pa[i] = *(const float4*)(Ag + (size_t)row * HIDN + kc * 32 + c4 * 4);
            pb[i] = *(const float4*)(Bg + (size_t)row * HIDN + kc * 32 + c4 * 4);
        }
        __syncthreads();
#pragma unroll
        for (int i = 0; i < 4; i++) {
            const int fi = i * 256 + tid;
            const int row = fi >> 3, c4 = fi & 7;
            As[row*20 + c4*2]     = packh2(pa[i].x, pa[i].y);
            As[row*20 + c4*2 + 1] = packh2(pa[i].z, pa[i].w);
            Bs[row*20 + c4*2]     = packh2(pb[i].x, pb[i].y);
            Bs[row*20 + c4*2 + 1] = packh2(pb[i].z, pb[i].w);
        }
        __syncthreads();
#pragma unroll
        for (int ks = 0; ks < 2; ks++) {
            uint32_t a[2][4], b[8][2];
#pragma unroll
            for (int mt = 0; mt < 2; mt++)
                ldm_x4(a[mt][0], a[mt][1], a[mt][2], a[mt][3],
                       aFB + (uint32_t)(mt*16*20*4 + ks*32));
#pragma unroll
            for (int ntp = 0; ntp < 4; ntp++)
                ldm_x4(b[2*ntp][0], b[2*ntp][1], b[2*ntp+1][0], b[2*ntp+1][1],
                       bFB + (uint32_t)(ntp*16*20*4 + ks*32));
#pragma unroll
            for (int mt = 0; mt < 2; mt++)
#pragma unroll
                for (int nt = 0; nt < 8; nt++)
                    mma_f16(acc[mt][nt], a[mt], b[nt]);
        }
    }

#pragma unroll
    for (int mt = 0; mt < 2; mt++) {
#pragma unroll
        for (int nt = 0; nt < 8; nt++) {
            const int n = bn + wn*64 + nt*8 + 2*t;
            const float bv0 = bias[n], bv1 = bias[n+1];
#pragma unroll
            for (int half = 0; half < 2; half++) {
                const int m = bm + wm*32 + mt*16 + g + half*8;
                const float v0 = acc[mt][nt][half*2+0] + bv0;
                const float v1 = acc[mt][nt][half*2+1] + bv1;
                size_t oi;
                if (which < 3) {
                    const int b_ = m >> 9, s = m & 511, h = n >> 6, d = n & 63;
                    oi = (((size_t)(b_*HH + h))*SS + s)*DD + d;
                } else {
                    oi = (((size_t)(n >> 6))*1024 + m)*DD + (n & 63);
                }
                *(float2*)(outp + oi) = make_float2(v0, v1);
            }
        }
    }
}

// ---------------- fused flash kernel (fp16 MMA, shear stores, ldmatrix) ----
#define FL_SMEM (27136 * 4)   // 108544 B (x2 = 217088 <= 228KB/SM)

__global__ __launch_bounds__(320, 2) void flash_tc(const float* __restrict__ mask,
                                                   float* __restrict__ out)
{
    extern __shared__ uint32_t smw[];
    uint32_t* Qs  = smw;                    // [64 i][36 w] k-pairs of d
    uint32_t* Ks  = smw + 2304;             // [64 j][36 w]
    uint32_t* Ps  = smw + 4608;             // [128 p][36 w] pos band
    uint32_t* Vt  = smw + 9216;             // [64 d][36 w] j-pairs
    __half*   Vth = (__half*)(smw + 9216);
    uint32_t* Pt2 = smw + 11520;            // [64 i][36 w] j-pairs (P~ f16)
    float*    SsF = (float*)(smw + 13824);  // [64][68] CC
    float*    B1  = (float*)(smw + 18176);  // [64][68] sheared CPF
    float*    B2  = (float*)(smw + 22528);  // [64][68] sheared PCF
    float* sm_m     = (float*)(smw + 26880);
    float* sm_l     = sm_m + 64;
    float* sm_scale = sm_m + 128;
    float* sm_mask  = sm_m + 192;

    const int i0 = blockIdx.x * 64;
    const int bh = blockIdx.y;
    const int b_ = bh >> 4, h = bh & 15;
    const int tid = threadIdx.x;
    const int wid = tid >> 5, lane = tid & 31;
    const int g = lane >> 2, t = lane & 3;
    const int wm = wid >> 1, wn = wid & 1;      // PV warp grid (wid<8): 4x2

    const float* qptr  = g_q + ((size_t)bh*SS + i0) * DD;
    const float* kbase = g_k + (size_t)bh*SS*DD;
    const float* vbase = g_v + (size_t)bh*SS*DD;
    const float* pptr  = g_pos + (size_t)h * 1024 * DD;

    if (tid < 256) {
#pragma unroll
        for (int i = 0; i < 4; i++) {
            const int u = tid + i*256, row = u >> 4, c4 = u & 15;
            float4 qv = *(const float4*)(qptr + (size_t)row * DD + c4*4);
            Qs[row*36 + c4*2]     = packh2(qv.x, qv.y);
            Qs[row*36 + c4*2 + 1] = packh2(qv.z, qv.w);
        }
    }
    if (tid < 64) { sm_m[tid] = -1e30f; sm_l[tid] = 0.f; }

    float acc_o[4][4];
#pragma unroll
    for (int nt = 0; nt < 4; nt++)
#pragma unroll
        for (int e = 0; e < 4; e++) acc_o[nt][e] = 0.f;

    // score-phase chunk assignment (10 warps, one 32x64 chunk each)
    const uint32_t* Ap; const uint32_t* Bp;
    int Arow, Brow;
    int kind;                               // 0=CC, 1=CPF, 2=PCF
    if (wid < 2)      { Ap = Qs; Arow = wid*32;          Bp = Ks; Brow = 0;                 kind = 0; }
    else if (wid < 6) { Ap = Qs; Arow = ((wid-2)&1)*32;  Bp = Ps; Brow = ((wid-2)>>1)*64;   kind = 1; }
    else              { Ap = Ps; Arow = (wid-6)*32;      Bp = Ks; Brow = 0;                 kind = 2; }

    // ldmatrix fragment bases
    const uint32_t aFB = smaddr(&Ap[(Arow + A_ROW(lane))*36 + A_COL(lane)]);
    const uint32_t bFB = smaddr(&Bp[(Brow + B_ROW(lane))*36 + B_COL(lane)]);
    const uint32_t aPV = smaddr(&Pt2[(wm*16 + A_ROW(lane))*36 + A_COL(lane)]);
    const uint32_t bPV = smaddr(&Vt[(wn*32 + B_ROW(lane))*36 + B_COL(lane)]);

    const float s1 = 0.14433756729740643f;      // 1/sqrt(48)

    for (int j0 = 0; j0 < SS; j0 += 64) {
        __syncthreads();   // previous chunk's tile reads complete

        // ---- loads (threads 0..255; batched LDGs) ----
        if (tid < 256) {
            const int row = tid >> 4, c4 = tid & 15;
            {   // K: 4 rows
                float4 x0 = *(const float4*)(kbase + (size_t)(j0+row)    * DD + c4*4);
                float4 x1 = *(const float4*)(kbase + (size_t)(j0+row+16) * DD + c4*4);
                float4 x2 = *(const float4*)(kbase + (size_t)(j0+row+32) * DD + c4*4);
                float4 x3 = *(const float4*)(kbase + (size_t)(j0+row+48) * DD + c4*4);
                Ks[(row)   *36 + c4*2] = packh2(x0.x, x0.y); Ks[(row)   *36 + c4*2+1] = packh2(x0.z, x0.w);
                Ks[(row+16)*36 + c4*2] = packh2(x1.x, x1.y); Ks[(row+16)*36 + c4*2+1] = packh2(x1.z, x1.w);
                Ks[(row+32)*36 + c4*2] = packh2(x2.x, x2.y); Ks[(row+32)*36 + c4*2+1] = packh2(x2.z, x2.w);
                Ks[(row+48)*36 + c4*2] = packh2(x3.x, x3.y); Ks[(row+48)*36 + c4*2+1] = packh2(x3.z, x3.w);
            }
            {   // V: 4 rows, transposed half-stores with e-rotation
                float4 x[4];
                x[0] = *(const float4*)(vbase + (size_t)(j0+row)    * DD + c4*4);
                x[1] = *(const float4*)(vbase + (size_t)(j0+row+16) * DD + c4*4);
                x[2] = *(const float4*)(vbase + (size_t)(j0+row+32) * DD + c4*4);
                x[3] = *(const float4*)(vbase + (size_t)(j0+row+48) * DD + c4*4);
#pragma unroll
                for (int i = 0; i < 4; i++) {
                    const float ve[4] = {x[i].x, x[i].y, x[i].z, x[i].w};
                    const int jrow = row + i*16;
#pragma unroll
                    for (int e2 = 0; e2 < 4; e2++) {
                        const int e = (e2 + c4) & 3;
                        Vth[(c4*4 + e)*72 + jrow] = __float2half_rn(ve[e]);
                    }
                }
            }
            const int base = i0 - j0 + 449;
#pragma unroll
            for (int half = 0; half < 2; half++) {   // pos band: 8 rows / thread
                float4 x[4];
#pragma unroll
                for (int i = 0; i < 4; i++) {
                    const int pr = row + (half*4 + i)*16;
                    int grow = base + pr;
                    grow = grow < 0 ? 0 : (grow > 1023 ? 1023 : grow);
                    x[i] = *(const float4*)(pptr + (size_t)grow * DD + c4*4);
                }
#pragma unroll
                for (int i = 0; i < 4; i++) {
                    const int pr = row + (half*4 + i)*16;
                    Ps[pr*36 + c4*2]     = packh2(x[i].x, x[i].y);
                    Ps[pr*36 + c4*2 + 1] = packh2(x[i].z, x[i].w);
                }
            }
        } else if ((tid - 256) < 64) {
            sm_mask[tid - 256] = mask[(size_t)b_*SS + j0 + tid - 256];
        }
        __syncthreads();

        // ---- score MMAs in two nt-halves; plain shear-stores per kind ----
#pragma unroll
        for (int hN = 0; hN < 2; hN++) {
            float acc[2][4][4];
#pragma unroll
            for (int mt = 0; mt < 2; mt++)
#pragma unroll
                for (int nt = 0; nt < 4; nt++)
#pragma unroll
                    for (int e = 0; e < 4; e++) acc[mt][nt][e] = 0.f;

#pragma unroll
            for (int ks = 0; ks < 4; ks++) {
                uint32_t a[2][4], b[4][2];
#pragma unroll
                for (int mt = 0; mt < 2; mt++)
                    ldm_x4(a[mt][0], a[mt][1], a[mt][2], a[mt][3],
                           aFB + (uint32_t)(mt*16*36*4 + ks*32));
#pragma unroll
                for (int ntp = 0; ntp < 2; ntp++)
                    ldm_x4(b[2*ntp][0], b[2*ntp][1], b[2*ntp+1][0], b[2*ntp+1][1],
                           bFB + (uint32_t)((hN*32 + ntp*16)*36*4 + ks*32));
#pragma unroll
                for (int mt = 0; mt < 2; mt++)
#pragma unroll
                    for (int nt = 0; nt < 4; nt++)
                        mma_f16(acc[mt][nt], a[mt], b[nt]);
            }

            if (kind == 0) {              // CC -> SsF, dense float2 stores
#pragma unroll
                for (int mt = 0; mt < 2; mt++)
#pragma unroll
                    for (int nt = 0; nt < 4; nt++) {
                        const int r0 = Arow + mt*16 + g;
                        const int c0 = (hN*4 + nt)*8 + 2*t;
                        *(float2*)&SsF[r0*68 + c0]     = make_float2(acc[mt][nt][0], acc[mt][nt][1]);
                        *(float2*)&SsF[(r0+8)*68 + c0] = make_float2(acc[mt][nt][2], acc[mt][nt][3]);
                    }
            } else if (kind == 1) {       // CPF[ai][p] -> B1[ai][ai-p+63]
#pragma unroll
                for (int mt = 0; mt < 2; mt++)
#pragma unroll
                    for (int nt = 0; nt < 4; nt++) {
                        const int ai0 = Arow + mt*16 + g;
                        const int p0 = Brow + (hN*4 + nt)*8 + 2*t;
#pragma unroll
                        for (int e = 0; e < 4; e++) {
                            const int ai = ai0 + (e >> 1)*8;
                            const int p  = p0 + (e & 1);
                            const int cj = ai - p + 63;
                            if ((unsigned)cj < 64u)
                                B1[ai*68 + cj] = acc[mt][nt][e];
                        }
                    }
            } else {                      // PCF[r][cj] -> B2[r+cj-63][cj]
#pragma unroll
                for (int mt = 0; mt < 2; mt++)
#pragma unroll
                    for (int nt = 0; nt < 4; nt++) {
                        const int r0 = Arow + mt*16 + g;
                        const int c0 = (hN*4 + nt)*8 + 2*t;
#pragma unroll
                        for (int e = 0; e < 4; e++) {
                            const int r  = r0 + (e >> 1)*8;
                            const int cj = c0 + (e & 1);
                            const int ai = r + cj - 63;
                            if ((unsigned)ai < 64u)
                                B2[ai*68 + cj] = acc[mt][nt][e];
                        }
                    }
            }
        }
        __syncthreads();

        // ---- online softmax (threads 0..255); combine 3 buffers on read ----
        if (tid < 256) {
            const int row = tid >> 2, q4 = tid & 3;
            float v[16];
            float mloc = -1e30f;
#pragma unroll
            for (int i = 0; i < 16; i++) {
                const int c = q4*16 + i;
                const float val = (SsF[row*68 + c] + B2[row*68 + c]
                                   + 0.125f * B1[row*68 + c]) * s1 + sm_mask[c];
                v[i] = val;
                mloc = fmaxf(mloc, val);
            }
            mloc = fmaxf(mloc, __shfl_xor_sync(0xffffffffu, mloc, 1));
            mloc = fmaxf(mloc, __shfl_xor_sync(0xffffffffu, mloc, 2));
            const float mold = sm_m[row];
            const float mnew = fmaxf(mold, mloc);
            float lsum = 0.f;
#pragma unroll
            for (int i = 0; i < 8; i++) {
                const float e0 = __expf(v[2*i]   - mnew);
                const float e1 = __expf(v[2*i+1] - mnew);
                Pt2[row*36 + q4*8 + i] = packh2(e0, e1);
                lsum += e0 + e1;
            }
            lsum += __shfl_xor_sync(0xffffffffu, lsum, 1);
            lsum += __shfl_xor_sync(0xffffffffu, lsum, 2);
            if (q4 == 0) {
                const float sc = __expf(mold - mnew);
                sm_m[row] = mnew;
                sm_scale[row] = sc;
                sm_l[row] = sm_l[row] * sc + lsum;
            }
        }
        __syncthreads();

        // ---- PV: warps 0..7, out tile 64x64, warp tile 16x32 ----
        if (wid < 8) {
            const float sc0 = sm_scale[wm*16 + g];
            const float sc1 = sm_scale[wm*16 + g + 8];
#pragma unroll
            for (int nt = 0; nt < 4; nt++) {
                acc_o[nt][0] *= sc0; acc_o[nt][1] *= sc0;
                acc_o[nt][2] *= sc1; acc_o[nt][3] *= sc1;
            }
#pragma unroll
            for (int ks = 0; ks < 4; ks++) {
                uint32_t a[4], b[4][2];
                ldm_x4(a[0], a[1], a[2], a[3], aPV + (uint32_t)(ks*32));
#pragma unroll
                for (int ntp = 0; ntp < 2; ntp++)
                    ldm_x4(b[2*ntp][0], b[2*ntp][1], b[2*ntp+1][0], b[2*ntp+1][1],
                           bPV + (uint32_t)(ntp*16*36*4 + ks*32));
#pragma unroll
                for (int nt = 0; nt < 4; nt++)
                    mma_f16(acc_o[nt], a, b[nt]);
            }
        }
    }
    __syncthreads();

    // ---- finalize: out[i][d] = acc_o / l ----
    if (wid < 8) {
        const int r0 = wm*16 + g;
        const float inv0 = 1.f / sm_l[r0];
        const float inv1 = 1.f / sm_l[r0 + 8];
#pragma unroll
        for (int nt = 0; nt < 4; nt++) {
            const int col = wn*32 + nt*8 + 2*t;
            const size_t o0 = ((size_t)b_*SS + i0 + r0)*HIDN + h*DD + col;
            const size_t o1 = ((size_t)b_*SS + i0 + r0 + 8)*HIDN + h*DD + col;
            *(float2*)(out + o0) = make_float2(acc_o[nt][0]*inv0, acc_o[nt][1]*inv0);
            *(float2*)(out + o1) = make_float2(acc_o[nt][2]*inv1, acc_o[nt][3]*inv1);
        }
    }
}

// ---------------- launch ---------------------------------------------------
extern "C" void kernel_launch(void* const* d_in, const int* in_sizes, int n_in,
                              void* d_out, int out_size)
{
    const float* hs  = (const float*)d_in[0];
    const float* msk = (const float*)d_in[1];
    const float* Wq  = (const float*)d_in[3];
    const float* bq  = (const float*)d_in[4];
    const float* Wk  = (const float*)d_in[5];
    const float* bk  = (const float*)d_in[6];
    const float* Wv  = (const float*)d_in[7];
    const float* bv  = (const float*)d_in[8];
    const float* Wpk = (const float*)d_in[9];
    const float* bpk = (const float*)d_in[10];
    const float* rel = (const float*)d_in[11];
    float* out = (float*)d_out;

    cudaFuncSetAttribute(flash_tc, cudaFuncAttributeMaxDynamicSharedMemorySize, FL_SMEM);

    dim3 gg(8, 32, 4);                    // z: Wq, Wk, Wv, Wpk (y>=8 idles for z=3)
    gemm_tc<<<gg, 256>>>(hs, rel, Wq, bq, Wk, bk, Wv, bv, Wpk, bpk);

    dim3 gf(SS/64, BH);                   // (8, 128)
    flash_tc<<<gf, 320, FL_SMEM>>>(msk, out);
}

// round 10
// speedup vs baseline: 2.6485x; 1.0386x over previous
#include <cuda_runtime.h>
#include <cuda_fp16.h>
#include <cstdint>

#define BB   8
#define SS   512
#define HH   16
#define DD   64
#define HIDN 1024
#define BH   (BB*HH)   // 128

// ---------------- scratch (device globals: allocation-free) ----------------
__device__ float g_q[BH*SS*DD];                 // [b,h,s,d] 16MB
__device__ float g_k[BH*SS*DD];
__device__ float g_v[BH*SS*DD];
__device__ float g_pos[HH*1024*DD];             // [h,p,d]   4MB

// ---------------- helpers ---------------------------------------------------
__device__ __forceinline__ uint32_t packh2(float lo, float hi) {
    uint32_t u;
    asm("cvt.rn.f16x2.f32 %0, %1, %2;" : "=r"(u) : "f"(hi), "f"(lo));
    return u;
}
__device__ __forceinline__ uint32_t smaddr(const void* p) {
    uint32_t a;
    asm("{ .reg .u64 t; cvta.to.shared.u64 t, %1; cvt.u32.u64 %0, t; }" : "=r"(a) : "l"(p));
    return a;
}
__device__ __forceinline__ void mma_f16(float c[4], const uint32_t a[4], const uint32_t b[2]) {
    asm volatile("mma.sync.aligned.m16n8k16.row.col.f32.f16.f16.f32 "
        "{%0,%1,%2,%3}, {%4,%5,%6,%7}, {%8,%9}, {%0,%1,%2,%3};"
        : "+f"(c[0]), "+f"(c[1]), "+f"(c[2]), "+f"(c[3])
        : "r"(a[0]), "r"(a[1]), "r"(a[2]), "r"(a[3]), "r"(b[0]), "r"(b[1]));
}
__device__ __forceinline__ void ldm_x4(uint32_t& r0, uint32_t& r1, uint32_t& r2, uint32_t& r3,
                                       uint32_t addr) {
    asm volatile("ldmatrix.sync.aligned.m8n8.x4.shared.b16 {%0,%1,%2,%3}, [%4];"
        : "=r"(r0), "=r"(r1), "=r"(r2), "=r"(r3) : "r"(addr));
}
__device__ __forceinline__ void ldm_x4_t(uint32_t& r0, uint32_t& r1, uint32_t& r2, uint32_t& r3,
                                         uint32_t addr) {
    asm volatile("ldmatrix.sync.aligned.m8n8.x4.trans.shared.b16 {%0,%1,%2,%3}, [%4];"
        : "=r"(r0), "=r"(r1), "=r"(r2), "=r"(r3) : "r"(addr));
}

// fragment-base lane offsets
#define A_ROW(lane)  ((lane) & 15)
#define A_COL(lane)  ((((lane) >> 4) & 1) << 2)
#define B_ROW(lane)  (((((lane) >> 4) & 1) << 3) + ((lane) & 7))
#define B_COL(lane)  ((((lane) >> 3) & 1) << 2)

// ---------------- fp16 HMMA projection GEMM (unchanged from R9) ------------
__global__ __launch_bounds__(256, 2) void gemm_tc(
    const float* __restrict__ hs, const float* __restrict__ rel,
    const float* __restrict__ Wq, const float* __restrict__ bq,
    const float* __restrict__ Wk, const float* __restrict__ bk,
    const float* __restrict__ Wv, const float* __restrict__ bv,
    const float* __restrict__ Wpk, const float* __restrict__ bpk)
{
    __shared__ uint32_t As[128*20];
    __shared__ uint32_t Bs[128*20];

    const int which = blockIdx.z;
    if (which == 3 && blockIdx.y >= 8) return;

    const float* X    = (which == 3) ? rel : hs;
    const float* W    = (which == 0) ? Wq : (which == 1) ? Wk : (which == 2) ? Wv : Wpk;
    const float* bias = (which == 0) ? bq : (which == 1) ? bk : (which == 2) ? bv : bpk;
    float* outp       = (which == 0) ? g_q : (which == 1) ? g_k : (which == 2) ? g_v : g_pos;

    const int bm = blockIdx.y * 128;
    const int bn = blockIdx.x * 128;
    const int tid = threadIdx.x;
    const int wid = tid >> 5, lane = tid & 31;
    const int wm = wid >> 1, wn = wid & 1;
    const int g = lane >> 2, t = lane & 3;

    float acc[2][8][4];
#pragma unroll
    for (int mt = 0; mt < 2; mt++)
#pragma unroll
        for (int nt = 0; nt < 8; nt++)
#pragma unroll
            for (int i = 0; i < 4; i++) acc[mt][nt][i] = 0.f;

    const float* Ag = X + (size_t)bm * HIDN;
    const float* Bg = W + (size_t)bn * HIDN;

    const uint32_t aFB = smaddr(&As[(wm*32 + A_ROW(lane))*20 + A_COL(lane)]);
    const uint32_t bFB = smaddr(&Bs[(wn*64 + B_ROW(lane))*20 + B_COL(lane)]);

    for (int kc = 0; kc < 32; kc++) {
        float4 pa[4], pb[4];
#pragma unroll
        for (int i = 0; i < 4; i++) {
            const int fi = i * 256 + tid;
            const int row = fi >> 3, c4 = fi & 7;
            pa[i] = *(const float4*)(Ag + (size_t)row * HIDN + kc * 32 + c4 * 4);
            pb[i] = *(const float4*)(Bg + (size_t)row * HIDN + kc * 32 + c4 * 4);
        }
        __syncthreads();
#pragma unroll
        for (int i = 0; i < 4; i++) {
            const int fi = i * 256 + tid;
            const int row = fi >> 3, c4 = fi & 7;
            As[row*20 + c4*2]     = packh2(pa[i].x, pa[i].y);
            As[row*20 + c4*2 + 1] = packh2(pa[i].z, pa[i].w);
            Bs[row*20 + c4*2]     = packh2(pb[i].x, pb[i].y);
            Bs[row*20 + c4*2 + 1] = packh2(pb[i].z, pb[i].w);
        }
        __syncthreads();
#pragma unroll
        for (int ks = 0; ks < 2; ks++) {
            uint32_t a[2][4], b[8][2];
#pragma unroll
            for (int mt = 0; mt < 2; mt++)
                ldm_x4(a[mt][0], a[mt][1], a[mt][2], a[mt][3],
                       aFB + (uint32_t)(mt*16*20*4 + ks*32));
#pragma unroll
            for (int ntp = 0; ntp < 4; ntp++)
                ldm_x4(b[2*ntp][0], b[2*ntp][1], b[2*ntp+1][0], b[2*ntp+1][1],
                       bFB + (uint32_t)(ntp*16*20*4 + ks*32));
#pragma unroll
            for (int mt = 0; mt < 2; mt++)
#pragma unroll
                for (int nt = 0; nt < 8; nt++)
                    mma_f16(acc[mt][nt], a[mt], b[nt]);
        }
    }

#pragma unroll
    for (int mt = 0; mt < 2; mt++) {
#pragma unroll
        for (int nt = 0; nt < 8; nt++) {
            const int n = bn + wn*64 + nt*8 + 2*t;
            const float bv0 = bias[n], bv1 = bias[n+1];
#pragma unroll
            for (int half = 0; half < 2; half++) {
                const int m = bm + wm*32 + mt*16 + g + half*8;
                const float v0 = acc[mt][nt][half*2+0] + bv0;
                const float v1 = acc[mt][nt][half*2+1] + bv1;
                size_t oi;
                if (which < 3) {
                    const int b_ = m >> 9, s = m & 511, h = n >> 6, d = n & 63;
                    oi = (((size_t)(b_*HH + h))*SS + s)*DD + d;
                } else {
                    oi = (((size_t)(n >> 6))*1024 + m)*DD + (n & 63);
                }
                *(float2*)(outp + oi) = make_float2(v0, v1);
            }
        }
    }
}

// ---------------- fused flash kernel (V row-major + ldmatrix.trans) --------
#define FL_SMEM (27136 * 4)   // 108544 B (x2 = 217088 <= 228KB/SM)

__global__ __launch_bounds__(320, 2) void flash_tc(const float* __restrict__ mask,
                                                   float* __restrict__ out)
{
    extern __shared__ uint32_t smw[];
    uint32_t* Qs  = smw;                    // [64 i][36 w] k-pairs of d
    uint32_t* Ks  = smw + 2304;             // [64 j][36 w]
    uint32_t* Ps  = smw + 4608;             // [128 p][36 w] pos band
    uint32_t* Vs  = smw + 9216;             // [64 j][36 w] ROW-MAJOR V (like K)
    uint32_t* Pt2 = smw + 11520;            // [64 i][36 w] j-pairs (P~ f16)
    float*    SsF = (float*)(smw + 13824);  // [64][68] CC
    float*    B1  = (float*)(smw + 18176);  // [64][68] sheared CPF
    float*    B2  = (float*)(smw + 22528);  // [64][68] sheared PCF
    float* sm_m     = (float*)(smw + 26880);
    float* sm_l     = sm_m + 64;
    float* sm_scale = sm_m + 128;
    float* sm_mask  = sm_m + 192;

    const int i0 = blockIdx.x * 64;
    const int bh = blockIdx.y;
    const int b_ = bh >> 4, h = bh & 15;
    const int tid = threadIdx.x;
    const int wid = tid >> 5, lane = tid & 31;
    const int g = lane >> 2, t = lane & 3;
    const int wm = wid >> 1, wn = wid & 1;      // PV warp grid (wid<8): 4x2

    const float* qptr  = g_q + ((size_t)bh*SS + i0) * DD;
    const float* kbase = g_k + (size_t)bh*SS*DD;
    const float* vbase = g_v + (size_t)bh*SS*DD;
    const float* pptr  = g_pos + (size_t)h * 1024 * DD;

    if (tid < 256) {
#pragma unroll
        for (int i = 0; i < 4; i++) {
            const int u = tid + i*256, row = u >> 4, c4 = u & 15;
            float4 qv = *(const float4*)(qptr + (size_t)row * DD + c4*4);
            Qs[row*36 + c4*2]     = packh2(qv.x, qv.y);
            Qs[row*36 + c4*2 + 1] = packh2(qv.z, qv.w);
        }
    }
    if (tid < 64) { sm_m[tid] = -1e30f; sm_l[tid] = 0.f; }

    float acc_o[4][4];
#pragma unroll
    for (int nt = 0; nt < 4; nt++)
#pragma unroll
        for (int e = 0; e < 4; e++) acc_o[nt][e] = 0.f;

    // score-phase chunk assignment (10 warps, one 32x64 chunk each)
    const uint32_t* Ap; const uint32_t* Bp;
    int Arow, Brow;
    int kind;                               // 0=CC, 1=CPF, 2=PCF
    if (wid < 2)      { Ap = Qs; Arow = wid*32;          Bp = Ks; Brow = 0;                 kind = 0; }
    else if (wid < 6) { Ap = Qs; Arow = ((wid-2)&1)*32;  Bp = Ps; Brow = ((wid-2)>>1)*64;   kind = 1; }
    else              { Ap = Ps; Arow = (wid-6)*32;      Bp = Ks; Brow = 0;                 kind = 2; }

    // ldmatrix fragment bases
    const uint32_t aFB = smaddr(&Ap[(Arow + A_ROW(lane))*36 + A_COL(lane)]);
    const uint32_t bFB = smaddr(&Bp[(Brow + B_ROW(lane))*36 + B_COL(lane)]);
    const uint32_t aPV = smaddr(&Pt2[(wm*16 + A_ROW(lane))*36 + A_COL(lane)]);
    // trans-load base for V: lane -> row j = (lane>>3&1)*8 + (lane&7), n-halves = (lane>>4)*8 (+wn*32)
    const uint32_t bPVt = smaddr(Vs)
        + (uint32_t)((((lane >> 3) & 1) * 8 + (lane & 7)) * 144
                     + ((lane >> 4) & 1) * 16 + wn * 64);

    const float s1 = 0.14433756729740643f;      // 1/sqrt(48)

    for (int j0 = 0; j0 < SS; j0 += 64) {
        __syncthreads();   // previous chunk's tile reads complete

        // ---- loads (threads 0..255; batched LDGs) ----
        if (tid < 256) {
            const int row = tid >> 4, c4 = tid & 15;
            {   // K: 4 rows
                float4 x0 = *(const float4*)(kbase + (size_t)(j0+row)    * DD + c4*4);
                float4 x1 = *(const float4*)(kbase + (size_t)(j0+row+16) * DD + c4*4);
                float4 x2 = *(const float4*)(kbase + (size_t)(j0+row+32) * DD + c4*4);
                float4 x3 = *(const float4*)(kbase + (size_t)(j0+row+48) * DD + c4*4);
                Ks[(row)   *36 + c4*2] = packh2(x0.x, x0.y); Ks[(row)   *36 + c4*2+1] = packh2(x0.z, x0.w);
                Ks[(row+16)*36 + c4*2] = packh2(x1.x, x1.y); Ks[(row+16)*36 + c4*2+1] = packh2(x1.z, x1.w);
                Ks[(row+32)*36 + c4*2] = packh2(x2.x, x2.y); Ks[(row+32)*36 + c4*2+1] = packh2(x2.z, x2.w);
                Ks[(row+48)*36 + c4*2] = packh2(x3.x, x3.y); Ks[(row+48)*36 + c4*2+1] = packh2(x3.z, x3.w);
            }
            {   // V: 4 rows, ROW-MAJOR (identical pattern to K)
                float4 x0 = *(const float4*)(vbase + (size_t)(j0+row)    * DD + c4*4);
                float4 x1 = *(const float4*)(vbase + (size_t)(j0+row+16) * DD + c4*4);
                float4 x2 = *(const float4*)(vbase + (size_t)(j0+row+32) * DD + c4*4);
                float4 x3 = *(const float4*)(vbase + (size_t)(j0+row+48) * DD + c4*4);
                Vs[(row)   *36 + c4*2] = packh2(x0.x, x0.y); Vs[(row)   *36 + c4*2+1] = packh2(x0.z, x0.w);
                Vs[(row+16)*36 + c4*2] = packh2(x1.x, x1.y); Vs[(row+16)*36 + c4*2+1] = packh2(x1.z, x1.w);
                Vs[(row+32)*36 + c4*2] = packh2(x2.x, x2.y); Vs[(row+32)*36 + c4*2+1] = packh2(x2.z, x2.w);
                Vs[(row+48)*36 + c4*2] = packh2(x3.x, x3.y); Vs[(row+48)*36 + c4*2+1] = packh2(x3.z, x3.w);
            }
            const int base = i0 - j0 + 449;
#pragma unroll
            for (int half = 0; half < 2; half++) {   // pos band: 8 rows / thread
                float4 x[4];
#pragma unroll
                for (int i = 0; i < 4; i++) {
                    const int pr = row + (half*4 + i)*16;
                    int grow = base + pr;
                    grow = grow < 0 ? 0 : (grow > 1023 ? 1023 : grow);
                    x[i] = *(const float4*)(pptr + (size_t)grow * DD + c4*4);
                }
#pragma unroll
                for (int i = 0; i < 4; i++) {
                    const int pr = row + (half*4 + i)*16;
                    Ps[pr*36 + c4*2]     = packh2(x[i].x, x[i].y);
                    Ps[pr*36 + c4*2 + 1] = packh2(x[i].z, x[i].w);
                }
            }
        } else if ((tid - 256) < 64) {
            sm_mask[tid - 256] = mask[(size_t)b_*SS + j0 + tid - 256];
        }
        __syncthreads();

        // ---- score MMAs in two nt-halves; plain shear-stores per kind ----
#pragma unroll
        for (int hN = 0; hN < 2; hN++) {
            float acc[2][4][4];
#pragma unroll
            for (int mt = 0; mt < 2; mt++)
#pragma unroll
                for (int nt = 0; nt < 4; nt++)
#pragma unroll
                    for (int e = 0; e < 4; e++) acc[mt][nt][e] = 0.f;

#pragma unroll
            for (int ks = 0; ks < 4; ks++) {
                uint32_t a[2][4], b[4][2];
#pragma unroll
                for (int mt = 0; mt < 2; mt++)
                    ldm_x4(a[mt][0], a[mt][1], a[mt][2], a[mt][3],
                           aFB + (uint32_t)(mt*16*36*4 + ks*32));
#pragma unroll
                for (int ntp = 0; ntp < 2; ntp++)
                    ldm_x4(b[2*ntp][0], b[2*ntp][1], b[2*ntp+1][0], b[2*ntp+1][1],
                           bFB + (uint32_t)((hN*32 + ntp*16)*36*4 + ks*32));
#pragma unroll
                for (int mt = 0; mt < 2; mt++)
#pragma unroll
                    for (int nt = 0; nt < 4; nt++)
                        mma_f16(acc[mt][nt], a[mt], b[nt]);
            }

            if (kind == 0) {              // CC -> SsF, dense float2 stores
#pragma unroll
                for (int mt = 0; mt < 2; mt++)
#pragma unroll
                    for (int nt = 0; nt < 4; nt++) {
                        const int r0 = Arow + mt*16 + g;
                        const int c0 = (hN*4 + nt)*8 + 2*t;
                        *(float2*)&SsF[r0*68 + c0]     = make_float2(acc[mt][nt][0], acc[mt][nt][1]);
                        *(float2*)&SsF[(r0+8)*68 + c0] = make_float2(acc[mt][nt][2], acc[mt][nt][3]);
                    }
            } else if (kind == 1) {       // CPF[ai][p] -> B1[ai][ai-p+63]
#pragma unroll
                for (int mt = 0; mt < 2; mt++)
#pragma unroll
                    for (int nt = 0; nt < 4; nt++) {
                        const int ai0 = Arow + mt*16 + g;
                        const int p0 = Brow + (hN*4 + nt)*8 + 2*t;
#pragma unroll
                        for (int e = 0; e < 4; e++) {
                            const int ai = ai0 + (e >> 1)*8;
                            const int p  = p0 + (e & 1);
                            const int cj = ai - p + 63;
                            if ((unsigned)cj < 64u)
                                B1[ai*68 + cj] = acc[mt][nt][e];
                        }
                    }
            } else {                      // PCF[r][cj] -> B2[r+cj-63][cj]
#pragma unroll
                for (int mt = 0; mt < 2; mt++)
#pragma unroll
                    for (int nt = 0; nt < 4; nt++) {
                        const int r0 = Arow + mt*16 + g;
                        const int c0 = (hN*4 + nt)*8 + 2*t;
#pragma unroll
                        for (int e = 0; e < 4; e++) {
                            const int r  = r0 + (e >> 1)*8;
                            const int cj = c0 + (e & 1);
                            const int ai = r + cj - 63;
                            if ((unsigned)ai < 64u)
                                B2[ai*68 + cj] = acc[mt][nt][e];
                        }
                    }
            }
        }
        __syncthreads();

        // ---- online softmax (threads 0..255); vectorized 3-buffer combine --
        if (tid < 256) {
            const int row = tid >> 2, q4 = tid & 3;
            const int c0 = q4*16;
            float v[16];
            float mloc = -1e30f;
#pragma unroll
            for (int i4 = 0; i4 < 4; i4++) {
                const float4 sc = *(const float4*)&SsF[row*68 + c0 + 4*i4];
                const float4 y2 = *(const float4*)&B2[row*68 + c0 + 4*i4];
                const float4 y1 = *(const float4*)&B1[row*68 + c0 + 4*i4];
                const float4 mk = *(const float4*)&sm_mask[c0 + 4*i4];
                v[4*i4+0] = (sc.x + y2.x + 0.125f*y1.x) * s1 + mk.x;
                v[4*i4+1] = (sc.y + y2.y + 0.125f*y1.y) * s1 + mk.y;
                v[4*i4+2] = (sc.z + y2.z + 0.125f*y1.z) * s1 + mk.z;
                v[4*i4+3] = (sc.w + y2.w + 0.125f*y1.w) * s1 + mk.w;
                mloc = fmaxf(mloc, fmaxf(fmaxf(v[4*i4], v[4*i4+1]), fmaxf(v[4*i4+2], v[4*i4+3])));
            }
            mloc = fmaxf(mloc, __shfl_xor_sync(0xffffffffu, mloc, 1));
            mloc = fmaxf(mloc, __shfl_xor_sync(0xffffffffu, mloc, 2));
            const float mold = sm_m[row];
            const float mnew = fmaxf(mold, mloc);
            float lsum = 0.f;
#pragma unroll
            for (int i = 0; i < 8; i++) {
                const float e0 = __expf(v[2*i]   - mnew);
                const float e1 = __expf(v[2*i+1] - mnew);
                Pt2[row*36 + q4*8 + i] = packh2(e0, e1);
                lsum += e0 + e1;
            }
            lsum += __shfl_xor_sync(0xffffffffu, lsum, 1);
            lsum += __shfl_xor_sync(0xffffffffu, lsum, 2);
            if (q4 == 0) {
                const float sc = __expf(mold - mnew);
                sm_m[row] = mnew;
                sm_scale[row] = sc;
                sm_l[row] = sm_l[row] * sc + lsum;
            }
        }
        __syncthreads();

        // ---- PV: warps 0..7, out tile 64x64, warp tile 16x32 ----
        if (wid < 8) {
            const float sc0 = sm_scale[wm*16 + g];
            const float sc1 = sm_scale[wm*16 + g + 8];
#pragma unroll
            for (int nt = 0; nt < 4; nt++) {
                acc_o[nt][0] *= sc0; acc_o[nt][1] *= sc0;
                acc_o[nt][2] *= sc1; acc_o[nt][3] *= sc1;
            }
#pragma unroll
            for (int ks = 0; ks < 4; ks++) {
                uint32_t a[4], b[4][2];
                ldm_x4(a[0], a[1], a[2], a[3], aPV + (uint32_t)(ks*32));
#pragma unroll
                for (int ntp = 0; ntp < 2; ntp++)
                    ldm_x4_t(b[2*ntp][0], b[2*ntp][1], b[2*ntp+1][0], b[2*ntp+1][1],
                             bPVt + (uint32_t)(ks*16*144 + ntp*32));
#pragma unroll
                for (int nt = 0; nt < 4; nt++)
                    mma_f16(acc_o[nt], a, b[nt]);
            }
        }
    }
    __syncthreads();

    // ---- finalize: out[i][d] = acc_o / l ----
    if (wid < 8) {
        const int r0 = wm*16 + g;
        const float inv0 = 1.f / sm_l[r0];
        const float inv1 = 1.f / sm_l[r0 + 8];
#pragma unroll
        for (int nt = 0; nt < 4; nt++) {
            const int col = wn*32 + nt*8 + 2*t;
            const size_t o0 = ((size_t)b_*SS + i0 + r0)*HIDN + h*DD + col;
            const size_t o1 = ((size_t)b_*SS + i0 + r0 + 8)*HIDN + h*DD + col;
            *(float2*)(out + o0) = make_float2(acc_o[nt][0]*inv0, acc_o[nt][1]*inv0);
            *(float2*)(out + o1) = make_float2(acc_o[nt][2]*inv1, acc_o[nt][3]*inv1);
        }
    }
}

// ---------------- launch ---------------------------------------------------
extern "C" void kernel_launch(void* const* d_in, const int* in_sizes, int n_in,
                              void* d_out, int out_size)
{
    const float* hs  = (const float*)d_in[0];
    const float* msk = (const float*)d_in[1];
    const float* Wq  = (const float*)d_in[3];
    const float* bq  = (const float*)d_in[4];
    const float* Wk  = (const float*)d_in[5];
    const float* bk  = (const float*)d_in[6];
    const float* Wv  = (const float*)d_in[7];
    const float* bv  = (const float*)d_in[8];
    const float* Wpk = (const float*)d_in[9];
    const float* bpk = (const float*)d_in[10];
    const float* rel = (const float*)d_in[11];
    float* out = (float*)d_out;

    cudaFuncSetAttribute(flash_tc, cudaFuncAttributeMaxDynamicSharedMemorySize, FL_SMEM);

    dim3 gg(8, 32, 4);                    // z: Wq, Wk, Wv, Wpk (y>=8 idles for z=3)
    gemm_tc<<<gg, 256>>>(hs, rel, Wq, bq, Wk, bk, Wv, bv, Wpk, bpk);

    dim3 gf(SS/64, BH);                   // (8, 128)
    flash_tc<<<gf, 320, FL_SMEM>>>(msk, out);
}

// round 11
// speedup vs baseline: 2.8336x; 1.0699x over previous
#include <cuda_runtime.h>
#include <cuda_fp16.h>
#include <cstdint>

#define BB   8
#define SS   512
#define HH   16
#define DD   64
#define HIDN 1024
#define BH   (BB*HH)   // 128

// ---------------- scratch (device globals, fp16 packed as half2 words) -----
__device__ uint32_t g_q[BH*SS*DD/2];            // [b,h,s,d/2] 8MB
__device__ uint32_t g_k[BH*SS*DD/2];
__device__ uint32_t g_v[BH*SS*DD/2];
__device__ uint32_t g_pos[HH*1024*DD/2];        // [h,p,d/2]   2MB

// ---------------- helpers ---------------------------------------------------
__device__ __forceinline__ uint32_t packh2(float lo, float hi) {
    uint32_t u;
    asm("cvt.rn.f16x2.f32 %0, %1, %2;" : "=r"(u) : "f"(hi), "f"(lo));
    return u;
}
__device__ __forceinline__ uint32_t smaddr(const void* p) {
    uint32_t a;
    asm("{ .reg .u64 t; cvta.to.shared.u64 t, %1; cvt.u32.u64 %0, t; }" : "=r"(a) : "l"(p));
    return a;
}
__device__ __forceinline__ void mma_f16(float c[4], const uint32_t a[4], const uint32_t b[2]) {
    asm volatile("mma.sync.aligned.m16n8k16.row.col.f32.f16.f16.f32 "
        "{%0,%1,%2,%3}, {%4,%5,%6,%7}, {%8,%9}, {%0,%1,%2,%3};"
        : "+f"(c[0]), "+f"(c[1]), "+f"(c[2]), "+f"(c[3])
        : "r"(a[0]), "r"(a[1]), "r"(a[2]), "r"(a[3]), "r"(b[0]), "r"(b[1]));
}
__device__ __forceinline__ void ldm_x4(uint32_t& r0, uint32_t& r1, uint32_t& r2, uint32_t& r3,
                                       uint32_t addr) {
    asm volatile("ldmatrix.sync.aligned.m8n8.x4.shared.b16 {%0,%1,%2,%3}, [%4];"
        : "=r"(r0), "=r"(r1), "=r"(r2), "=r"(r3) : "r"(addr));
}
__device__ __forceinline__ void ldm_x4_t(uint32_t& r0, uint32_t& r1, uint32_t& r2, uint32_t& r3,
                                         uint32_t addr) {
    asm volatile("ldmatrix.sync.aligned.m8n8.x4.trans.shared.b16 {%0,%1,%2,%3}, [%4];"
        : "=r"(r0), "=r"(r1), "=r"(r2), "=r"(r3) : "r"(addr));
}
__device__ __forceinline__ void cp16(uint32_t smem_dst, const void* gsrc) {
    asm volatile("cp.async.ca.shared.global [%0], [%1], 16;" :: "r"(smem_dst), "l"(gsrc));
}
#define CP_COMMIT() asm volatile("cp.async.commit_group;" ::: "memory")
#define CP_WAIT0()  asm volatile("cp.async.wait_group 0;" ::: "memory")

// fragment-base lane offsets
#define A_ROW(lane)  ((lane) & 15)
#define A_COL(lane)  ((((lane) >> 4) & 1) << 2)
#define B_ROW(lane)  (((((lane) >> 4) & 1) << 3) + ((lane) & 7))
#define B_COL(lane)  ((((lane) >> 3) & 1) << 2)

// ---------------- fp16 HMMA projection GEMM (half2 epilogue) ---------------
__global__ __launch_bounds__(256, 2) void gemm_tc(
    const float* __restrict__ hs, const float* __restrict__ rel,
    const float* __restrict__ Wq, const float* __restrict__ bq,
    const float* __restrict__ Wk, const float* __restrict__ bk,
    const float* __restrict__ Wv, const float* __restrict__ bv,
    const float* __restrict__ Wpk, const float* __restrict__ bpk)
{
    __shared__ uint32_t As[128*20];
    __shared__ uint32_t Bs[128*20];

    const int which = blockIdx.z;
    if (which == 3 && blockIdx.y >= 8) return;

    const float* X    = (which == 3) ? rel : hs;
    const float* W    = (which == 0) ? Wq : (which == 1) ? Wk : (which == 2) ? Wv : Wpk;
    const float* bias = (which == 0) ? bq : (which == 1) ? bk : (which == 2) ? bv : bpk;
    uint32_t* outp    = (which == 0) ? g_q : (which == 1) ? g_k : (which == 2) ? g_v : g_pos;

    const int bm = blockIdx.y * 128;
    const int bn = blockIdx.x * 128;
    const int tid = threadIdx.x;
    const int wid = tid >> 5, lane = tid & 31;
    const int wm = wid >> 1, wn = wid & 1;
    const int g = lane >> 2, t = lane & 3;

    float acc[2][8][4];
#pragma unroll
    for (int mt = 0; mt < 2; mt++)
#pragma unroll
        for (int nt = 0; nt < 8; nt++)
#pragma unroll
            for (int i = 0; i < 4; i++) acc[mt][nt][i] = 0.f;

    const float* Ag = X + (size_t)bm * HIDN;
    const float* Bg = W + (size_t)bn * HIDN;

    const uint32_t aFB = smaddr(&As[(wm*32 + A_ROW(lane))*20 + A_COL(lane)]);
    const uint32_t bFB = smaddr(&Bs[(wn*64 + B_ROW(lane))*20 + B_COL(lane)]);

    for (int kc = 0; kc < 32; kc++) {
        float4 pa[4], pb[4];
#pragma unroll
        for (int i = 0; i < 4; i++) {
            const int fi = i * 256 + tid;
            const int row = fi >> 3, c4 = fi & 7;
            pa[i] = *(const float4*)(Ag + (size_t)row * HIDN + kc * 32 + c4 * 4);
            pb[i] = *(const float4*)(Bg + (size_t)row * HIDN + kc * 32 + c4 * 4);
        }
        __syncthreads();
#pragma unroll
        for (int i = 0; i < 4; i++) {
            const int fi = i * 256 + tid;
            const int row = fi >> 3, c4 = fi & 7;
            As[row*20 + c4*2]     = packh2(pa[i].x, pa[i].y);
            As[row*20 + c4*2 + 1] = packh2(pa[i].z, pa[i].w);
            Bs[row*20 + c4*2]     = packh2(pb[i].x, pb[i].y);
            Bs[row*20 + c4*2 + 1] = packh2(pb[i].z, pb[i].w);
        }
        __syncthreads();
#pragma unroll
        for (int ks = 0; ks < 2; ks++) {
            uint32_t a[2][4], b[8][2];
#pragma unroll
            for (int mt = 0; mt < 2; mt++)
                ldm_x4(a[mt][0], a[mt][1], a[mt][2], a[mt][3],
                       aFB + (uint32_t)(mt*16*20*4 + ks*32));
#pragma unroll
            for (int ntp = 0; ntp < 4; ntp++)
                ldm_x4(b[2*ntp][0], b[2*ntp][1], b[2*ntp+1][0], b[2*ntp+1][1],
                       bFB + (uint32_t)(ntp*16*20*4 + ks*32));
#pragma unroll
            for (int mt = 0; mt < 2; mt++)
#pragma unroll
                for (int nt = 0; nt < 8; nt++)
                    mma_f16(acc[mt][nt], a[mt], b[nt]);
        }
    }

#pragma unroll
    for (int mt = 0; mt < 2; mt++) {
#pragma unroll
        for (int nt = 0; nt < 8; nt++) {
            const int n = bn + wn*64 + nt*8 + 2*t;    // even d
            const float bv0 = bias[n], bv1 = bias[n+1];
#pragma unroll
            for (int half = 0; half < 2; half++) {
                const int m = bm + wm*32 + mt*16 + g + half*8;
                const float v0 = acc[mt][nt][half*2+0] + bv0;
                const float v1 = acc[mt][nt][half*2+1] + bv1;
                size_t oi;
                if (which < 3) {
                    const int b_ = m >> 9, s = m & 511, h = n >> 6, d = n & 63;
                    oi = (((size_t)(b_*HH + h))*SS + s)*DD + d;
                } else {
                    oi = (((size_t)(n >> 6))*1024 + m)*DD + (n & 63);
                }
                outp[oi >> 1] = packh2(v0, v1);
            }
        }
    }
}

// ---------------- fused flash kernel (fp16 intermediates + cp.async) -------
#define FL_SMEM (27136 * 4)   // 108544 B (x2 = 217088 <= 228KB/SM)

__global__ __launch_bounds__(320, 2) void flash_tc(const float* __restrict__ mask,
                                                   float* __restrict__ out)
{
    extern __shared__ uint32_t smw[];
    uint32_t* Qs  = smw;                    // [64 i][36 w] k-pairs of d
    uint32_t* Ks  = smw + 2304;             // [64 j][36 w]
    uint32_t* Ps  = smw + 4608;             // [128 p][36 w] pos band
    uint32_t* Vs  = smw + 9216;             // [64 j][36 w] row-major V
    uint32_t* Pt2 = smw + 11520;            // [64 i][36 w] j-pairs (P~ f16)
    float*    SsF = (float*)(smw + 13824);  // [64][68] CC
    float*    B1  = (float*)(smw + 18176);  // [64][68] sheared CPF
    float*    B2  = (float*)(smw + 22528);  // [64][68] sheared PCF
    float* sm_m     = (float*)(smw + 26880);
    float* sm_l     = sm_m + 64;
    float* sm_scale = sm_m + 128;
    float* sm_mask  = sm_m + 192;

    const int i0 = blockIdx.x * 64;
    const int bh = blockIdx.y;
    const int b_ = bh >> 4, h = bh & 15;
    const int tid = threadIdx.x;
    const int wid = tid >> 5, lane = tid & 31;
    const int g = lane >> 2, t = lane & 3;
    const int wm = wid >> 1, wn = wid & 1;      // PV warp grid (wid<8): 4x2

    const uint32_t* q32 = g_q + ((size_t)bh*SS + i0) * (DD/2);
    const uint32_t* k32 = g_k + (size_t)bh*SS*(DD/2);
    const uint32_t* v32 = g_v + (size_t)bh*SS*(DD/2);
    const uint32_t* p32 = g_pos + (size_t)h * 1024 * (DD/2);

    const uint32_t smQs = smaddr(Qs), smKs = smaddr(Ks), smPs = smaddr(Ps), smVs = smaddr(Vs);

    // Q tile: 512 x 16B chunks via cp.async (waited in chunk 0's wait0)
    if (tid < 256) {
#pragma unroll
        for (int i = 0; i < 2; i++) {
            const int u = tid + i*256;           // 0..511
            const int row = u >> 3, c = u & 7;
            cp16(smQs + (uint32_t)(row*144 + c*16), q32 + row*32 + c*4);
        }
    }
    if (tid < 64) { sm_m[tid] = -1e30f; sm_l[tid] = 0.f; }

    float acc_o[4][4];
#pragma unroll
    for (int nt = 0; nt < 4; nt++)
#pragma unroll
        for (int e = 0; e < 4; e++) acc_o[nt][e] = 0.f;

    // score-phase chunk assignment (10 warps, one 32x64 chunk each)
    const uint32_t* Ap; const uint32_t* Bp;
    int Arow, Brow;
    int kind;                               // 0=CC, 1=CPF, 2=PCF
    if (wid < 2)      { Ap = Qs; Arow = wid*32;          Bp = Ks; Brow = 0;                 kind = 0; }
    else if (wid < 6) { Ap = Qs; Arow = ((wid-2)&1)*32;  Bp = Ps; Brow = ((wid-2)>>1)*64;   kind = 1; }
    else              { Ap = Ps; Arow = (wid-6)*32;      Bp = Ks; Brow = 0;                 kind = 2; }

    // ldmatrix fragment bases
    const uint32_t aFB = smaddr(&Ap[(Arow + A_ROW(lane))*36 + A_COL(lane)]);
    const uint32_t bFB = smaddr(&Bp[(Brow + B_ROW(lane))*36 + B_COL(lane)]);
    const uint32_t aPV = smaddr(&Pt2[(wm*16 + A_ROW(lane))*36 + A_COL(lane)]);
    const uint32_t bPVt = smVs
        + (uint32_t)((((lane >> 3) & 1) * 8 + (lane & 7)) * 144
                     + ((lane >> 4) & 1) * 16 + wn * 64);

    const float s1 = 0.14433756729740643f;      // 1/sqrt(48)

    for (int j0 = 0; j0 < SS; j0 += 64) {
        __syncthreads();   // previous chunk's tile reads complete

        // ---- loads: K/V/P via cp.async (2048 x 16B chunks over 256 thr) ----
        if (tid < 256) {
            const uint32_t* kc32 = k32 + (size_t)j0 * 32;
            const uint32_t* vc32 = v32 + (size_t)j0 * 32;
            const int base = i0 - j0 + 449;
#pragma unroll
            for (int i = 0; i < 8; i++) {
                const int u = tid + i*256;       // 0..2047
                const int idx = u & 1023;
                const int row = idx >> 3, c = idx & 7;
                if (u < 512) {
                    cp16(smKs + (uint32_t)(row*144 + c*16), kc32 + row*32 + c*4);
                } else if (u < 1024) {
                    cp16(smVs + (uint32_t)((row-64)*144 + c*16), vc32 + (row-64)*32 + c*4);
                } else {
                    const int pr = (u - 1024) >> 3;
                    int grow = base + pr;
                    grow = grow < 0 ? 0 : (grow > 1023 ? 1023 : grow);
                    cp16(smPs + (uint32_t)(pr*144 + (u & 7)*16), p32 + grow*32 + (u & 7)*4);
                }
            }
            CP_COMMIT();
            CP_WAIT0();
        } else if ((tid - 256) < 64) {
            sm_mask[tid - 256] = mask[(size_t)b_*SS + j0 + tid - 256];
        }
        __syncthreads();

        // ---- score MMAs in two nt-halves; plain shear-stores per kind ----
#pragma unroll
        for (int hN = 0; hN < 2; hN++) {
            float acc[2][4][4];
#pragma unroll
            for (int mt = 0; mt < 2; mt++)
#pragma unroll
                for (int nt = 0; nt < 4; nt++)
#pragma unroll
                    for (int e = 0; e < 4; e++) acc[mt][nt][e] = 0.f;

#pragma unroll
            for (int ks = 0; ks < 4; ks++) {
                uint32_t a[2][4], b[4][2];
#pragma unroll
                for (int mt = 0; mt < 2; mt++)
                    ldm_x4(a[mt][0], a[mt][1], a[mt][2], a[mt][3],
                           aFB + (uint32_t)(mt*16*36*4 + ks*32));
#pragma unroll
                for (int ntp = 0; ntp < 2; ntp++)
                    ldm_x4(b[2*ntp][0], b[2*ntp][1], b[2*ntp+1][0], b[2*ntp+1][1],
                           bFB + (uint32_t)((hN*32 + ntp*16)*36*4 + ks*32));
#pragma unroll
                for (int mt = 0; mt < 2; mt++)
#pragma unroll
                    for (int nt = 0; nt < 4; nt++)
                        mma_f16(acc[mt][nt], a[mt], b[nt]);
            }

            if (kind == 0) {              // CC -> SsF, dense float2 stores
#pragma unroll
                for (int mt = 0; mt < 2; mt++)
#pragma unroll
                    for (int nt = 0; nt < 4; nt++) {
                        const int r0 = Arow + mt*16 + g;
                        const int c0 = (hN*4 + nt)*8 + 2*t;
                        *(float2*)&SsF[r0*68 + c0]     = make_float2(acc[mt][nt][0], acc[mt][nt][1]);
                        *(float2*)&SsF[(r0+8)*68 + c0] = make_float2(acc[mt][nt][2], acc[mt][nt][3]);
                    }
            } else if (kind == 1) {       // CPF[ai][p] -> B1[ai][ai-p+63]
#pragma unroll
                for (int mt = 0; mt < 2; mt++)
#pragma unroll
                    for (int nt = 0; nt < 4; nt++) {
                        const int ai0 = Arow + mt*16 + g;
                        const int p0 = Brow + (hN*4 + nt)*8 + 2*t;
#pragma unroll
                        for (int e = 0; e < 4; e++) {
                            const int ai = ai0 + (e >> 1)*8;
                            const int p  = p0 + (e & 1);
                            const int cj = ai - p + 63;
                            if ((unsigned)cj < 64u)
                                B1[ai*68 + cj] = acc[mt][nt][e];
                        }
                    }
            } else {                      // PCF[r][cj] -> B2[r+cj-63][cj]
#pragma unroll
                for (int mt = 0; mt < 2; mt++)
#pragma unroll
                    for (int nt = 0; nt < 4; nt++) {
                        const int r0 = Arow + mt*16 + g;
                        const int c0 = (hN*4 + nt)*8 + 2*t;
#pragma unroll
                        for (int e = 0; e < 4; e++) {
                            const int r  = r0 + (e >> 1)*8;
                            const int cj = c0 + (e & 1);
                            const int ai = r + cj - 63;
                            if ((unsigned)ai < 64u)
                                B2[ai*68 + cj] = acc[mt][nt][e];
                        }
                    }
            }
        }
        __syncthreads();

        // ---- online softmax (threads 0..255); vectorized 3-buffer combine --
        if (tid < 256) {
            const int row = tid >> 2, q4 = tid & 3;
            const int c0 = q4*16;
            float v[16];
            float mloc = -1e30f;
#pragma unroll
            for (int i4 = 0; i4 < 4; i4++) {
                const float4 sc = *(const float4*)&SsF[row*68 + c0 + 4*i4];
                const float4 y2 = *(const float4*)&B2[row*68 + c0 + 4*i4];
                const float4 y1 = *(const float4*)&B1[row*68 + c0 + 4*i4];
                const float4 mk = *(const float4*)&sm_mask[c0 + 4*i4];
                v[4*i4+0] = (sc.x + y2.x + 0.125f*y1.x) * s1 + mk.x;
                v[4*i4+1] = (sc.y + y2.y + 0.125f*y1.y) * s1 + mk.y;
                v[4*i4+2] = (sc.z + y2.z + 0.125f*y1.z) * s1 + mk.z;
                v[4*i4+3] = (sc.w + y2.w + 0.125f*y1.w) * s1 + mk.w;
                mloc = fmaxf(mloc, fmaxf(fmaxf(v[4*i4], v[4*i4+1]), fmaxf(v[4*i4+2], v[4*i4+3])));
            }
            mloc = fmaxf(mloc, __shfl_xor_sync(0xffffffffu, mloc, 1));
            mloc = fmaxf(mloc, __shfl_xor_sync(0xffffffffu, mloc, 2));
            const float mold = sm_m[row];
            const float mnew = fmaxf(mold, mloc);
            float lsum = 0.f;
#pragma unroll
            for (int i = 0; i < 8; i++) {
                const float e0 = __expf(v[2*i]   - mnew);
                const float e1 = __expf(v[2*i+1] - mnew);
                Pt2[row*36 + q4*8 + i] = packh2(e0, e1);
                lsum += e0 + e1;
            }
            lsum += __shfl_xor_sync(0xffffffffu, lsum, 1);
            lsum += __shfl_xor_sync(0xffffffffu, lsum, 2);
            if (q4 == 0) {
                const float sc = __expf(mold - mnew);
                sm_m[row] = mnew;
                sm_scale[row] = sc;
                sm_l[row] = sm_l[row] * sc + lsum;
            }
        }
        __syncthreads();

        // ---- PV: warps 0..7, out tile 64x64, warp tile 16x32 ----
        if (wid < 8) {
            const float sc0 = sm_scale[wm*16 + g];
            const float sc1 = sm_scale[wm*16 + g + 8];
#pragma unroll
            for (int nt = 0; nt < 4; nt++) {
                acc_o[nt][0] *= sc0; acc_o[nt][1] *= sc0;
                acc_o[nt][2] *= sc1; acc_o[nt][3] *= sc1;
            }
#pragma unroll
            for (int ks = 0; ks < 4; ks++) {
                uint32_t a[4], b[4][2];
                ldm_x4(a[0], a[1], a[2], a[3], aPV + (uint32_t)(ks*32));
#pragma unroll
                for (int ntp = 0; ntp < 2; ntp++)
                    ldm_x4_t(b[2*ntp][0], b[2*ntp][1], b[2*ntp+1][0], b[2*ntp+1][1],
                             bPVt + (uint32_t)(ks*16*144 + ntp*32));
#pragma unroll
                for (int nt = 0; nt < 4; nt++)
                    mma_f16(acc_o[nt], a, b[nt]);
            }
        }
    }
    __syncthreads();

    // ---- finalize: out[i][d] = acc_o / l ----
    if (wid < 8) {
        const int r0 = wm*16 + g;
        const float inv0 = 1.f / sm_l[r0];
        const float inv1 = 1.f / sm_l[r0 + 8];
#pragma unroll
        for (int nt = 0; nt < 4; nt++) {
            const int col = wn*32 + nt*8 + 2*t;
            const size_t o0 = ((size_t)b_*SS + i0 + r0)*HIDN + h*DD + col;
            const size_t o1 = ((size_t)b_*SS + i0 + r0 + 8)*HIDN + h*DD + col;
            *(float2*)(out + o0) = make_float2(acc_o[nt][0]*inv0, acc_o[nt][1]*inv0);
            *(float2*)(out + o1) = make_float2(acc_o[nt][2]*inv1, acc_o[nt][3]*inv1);
        }
    }
}

// ---------------- launch ---------------------------------------------------
extern "C" void kernel_launch(void* const* d_in, const int* in_sizes, int n_in,
                              void* d_out, int out_size)
{
    const float* hs  = (const float*)d_in[0];
    const float* msk = (const float*)d_in[1];
    const float* Wq  = (const float*)d_in[3];
    const float* bq  = (const float*)d_in[4];
    const float* Wk  = (const float*)d_in[5];
    const float* bk  = (const float*)d_in[6];
    const float* Wv  = (const float*)d_in[7];
    const float* bv  = (const float*)d_in[8];
    const float* Wpk = (const float*)d_in[9];
    const float* bpk = (const float*)d_in[10];
    const float* rel = (const float*)d_in[11];
    float* out = (float*)d_out;

    cudaFuncSetAttribute(flash_tc, cudaFuncAttributeMaxDynamicSharedMemorySize, FL_SMEM);

    dim3 gg(8, 32, 4);                    // z: Wq, Wk, Wv, Wpk (y>=8 idles for z=3)
    gemm_tc<<<gg, 256>>>(hs, rel, Wq, bq, Wk, bk, Wv, bv, Wpk, bpk);

    dim3 gf(SS/64, BH);                   // (8, 128)
    flash_tc<<<gf, 320, FL_SMEM>>>(msk, out);
}

// round 12
// speedup vs baseline: 3.0258x; 1.0678x over previous
#include <cuda_runtime.h>
#include <cuda_fp16.h>
#include <cstdint>

#define BB   8
#define SS   512
#define HH   16
#define DD   64
#define HIDN 1024
#define BH   (BB*HH)   // 128

// ---------------- scratch (device globals, fp16 packed as half2 words) -----
__device__ uint32_t g_q[BH*SS*DD/2];            // [b,h,s,d/2] 8MB
__device__ uint32_t g_k[BH*SS*DD/2];
__device__ uint32_t g_v[BH*SS*DD/2];
__device__ uint32_t g_pos[HH*1024*DD/2];        // [h,p,d/2]   2MB
__device__ uint32_t g_hs16[BB*SS*HIDN/2];       // fp16 hidden_states 8MB
__device__ uint32_t g_rel16[1024*HIDN/2];       // fp16 rel_emb 2MB
__device__ uint32_t g_w16[4][HIDN*HIDN/2];      // fp16 Wq,Wk,Wv,Wpk 4x2MB

// ---------------- helpers ---------------------------------------------------
__device__ __forceinline__ uint32_t packh2(float lo, float hi) {
    uint32_t u;
    asm("cvt.rn.f16x2.f32 %0, %1, %2;" : "=r"(u) : "f"(hi), "f"(lo));
    return u;
}
__device__ __forceinline__ uint32_t smaddr(const void* p) {
    uint32_t a;
    asm("{ .reg .u64 t; cvta.to.shared.u64 t, %1; cvt.u32.u64 %0, t; }" : "=r"(a) : "l"(p));
    return a;
}
__device__ __forceinline__ void mma_f16(float c[4], const uint32_t a[4], const uint32_t b[2]) {
    asm volatile("mma.sync.aligned.m16n8k16.row.col.f32.f16.f16.f32 "
        "{%0,%1,%2,%3}, {%4,%5,%6,%7}, {%8,%9}, {%0,%1,%2,%3};"
        : "+f"(c[0]), "+f"(c[1]), "+f"(c[2]), "+f"(c[3])
        : "r"(a[0]), "r"(a[1]), "r"(a[2]), "r"(a[3]), "r"(b[0]), "r"(b[1]));
}
__device__ __forceinline__ void ldm_x4(uint32_t& r0, uint32_t& r1, uint32_t& r2, uint32_t& r3,
                                       uint32_t addr) {
    asm volatile("ldmatrix.sync.aligned.m8n8.x4.shared.b16 {%0,%1,%2,%3}, [%4];"
        : "=r"(r0), "=r"(r1), "=r"(r2), "=r"(r3) : "r"(addr));
}
__device__ __forceinline__ void ldm_x4_t(uint32_t& r0, uint32_t& r1, uint32_t& r2, uint32_t& r3,
                                         uint32_t addr) {
    asm volatile("ldmatrix.sync.aligned.m8n8.x4.trans.shared.b16 {%0,%1,%2,%3}, [%4];"
        : "=r"(r0), "=r"(r1), "=r"(r2), "=r"(r3) : "r"(addr));
}
__device__ __forceinline__ void cp16(uint32_t smem_dst, const void* gsrc) {
    asm volatile("cp.async.ca.shared.global [%0], [%1], 16;" :: "r"(smem_dst), "l"(gsrc));
}
#define CP_COMMIT() asm volatile("cp.async.commit_group;" ::: "memory")
#define CP_WAIT0()  asm volatile("cp.async.wait_group 0;" ::: "memory")
#define CP_WAIT1()  asm volatile("cp.async.wait_group 1;" ::: "memory")

// fragment-base lane offsets
#define A_ROW(lane)  ((lane) & 15)
#define A_COL(lane)  ((((lane) >> 4) & 1) << 2)
#define B_ROW(lane)  (((((lane) >> 4) & 1) << 3) + ((lane) & 7))
#define B_COL(lane)  ((((lane) >> 3) & 1) << 2)

// ---------------- precvt: fp32 -> fp16 (one-time) ---------------------------
__global__ __launch_bounds__(256) void precvt(
    const float* __restrict__ hs, const float* __restrict__ rel,
    const float* __restrict__ Wq, const float* __restrict__ Wk,
    const float* __restrict__ Wv, const float* __restrict__ Wpk)
{
    const int seg = blockIdx.y;
    const float* src;
    uint32_t* dst;
    int n;
    switch (seg) {
        case 0: src = hs;  dst = g_hs16;  n = BB*SS*HIDN; break;
        case 1: src = rel; dst = g_rel16; n = 1024*HIDN;  break;
        case 2: src = Wq;  dst = g_w16[0]; n = HIDN*HIDN; break;
        case 3: src = Wk;  dst = g_w16[1]; n = HIDN*HIDN; break;
        case 4: src = Wv;  dst = g_w16[2]; n = HIDN*HIDN; break;
        default: src = Wpk; dst = g_w16[3]; n = HIDN*HIDN; break;
    }
    const int i = (blockIdx.x * 256 + threadIdx.x) * 4;
    if (i >= n) return;
    const float4 x = *(const float4*)(src + i);
    *(uint2*)&dst[i >> 1] = make_uint2(packh2(x.x, x.y), packh2(x.z, x.w));
}

// ---------------- fp16 HMMA projection GEMM (f16 operands, cp.async, 2-buf) -
__global__ __launch_bounds__(256, 2) void gemm_tc(
    const float* __restrict__ bq, const float* __restrict__ bk,
    const float* __restrict__ bv, const float* __restrict__ bpk)
{
    __shared__ uint32_t sm[4*2560];   // [As0|Bs0|As1|Bs1], each 128x20 words

    const int which = blockIdx.z;
    if (which == 3 && blockIdx.y >= 8) return;

    const uint32_t* Ag = ((which == 3) ? g_rel16 : g_hs16);
    const uint32_t* Bg = g_w16[which];
    const float* bias = (which == 0) ? bq : (which == 1) ? bk : (which == 2) ? bv : bpk;
    uint32_t* outp    = (which == 0) ? g_q : (which == 1) ? g_k : (which == 2) ? g_v : g_pos;

    const int bm = blockIdx.y * 128;
    const int bn = blockIdx.x * 128;
    const int tid = threadIdx.x;
    const int wid = tid >> 5, lane = tid & 31;
    const int wm = wid >> 1, wn = wid & 1;
    const int g = lane >> 2, t = lane & 3;

    Ag += (size_t)bm * (HIDN/2);
    Bg += (size_t)bn * (HIDN/2);

    float acc[2][8][4];
#pragma unroll
    for (int mt = 0; mt < 2; mt++)
#pragma unroll
        for (int nt = 0; nt < 8; nt++)
#pragma unroll
            for (int i = 0; i < 4; i++) acc[mt][nt][i] = 0.f;

    const uint32_t smBase = smaddr(sm);
    // per-thread cp targets: u = tid + i*256 in [0,512): row=u>>2, c=u&3
    const int r0c = (tid + 0)   >> 2, c0c = (tid + 0)   & 3;
    const int r1c = (tid + 256) >> 2, c1c = (tid + 256) & 3;

    const uint32_t aFB = smaddr(&sm[(wm*32 + A_ROW(lane))*20 + A_COL(lane)]);
    const uint32_t bFB = smaddr(&sm[2560 + (wn*64 + B_ROW(lane))*20 + B_COL(lane)]);

    // prologue: fill buffer 0
    {
        const uint32_t sA = smBase, sB = smBase + 2560*4;
        cp16(sA + (uint32_t)(r0c*80 + c0c*16), Ag + (size_t)r0c*512 + c0c*4);
        cp16(sA + (uint32_t)(r1c*80 + c1c*16), Ag + (size_t)r1c*512 + c1c*4);
        cp16(sB + (uint32_t)(r0c*80 + c0c*16), Bg + (size_t)r0c*512 + c0c*4);
        cp16(sB + (uint32_t)(r1c*80 + c1c*16), Bg + (size_t)r1c*512 + c1c*4);
        CP_COMMIT();
    }

    for (int kc = 0; kc < 32; kc++) {
        const int cur = kc & 1;
        if (kc < 31) {
            const uint32_t off = (uint32_t)((cur ^ 1) * 5120 * 4);
            const uint32_t sA = smBase + off, sB = smBase + off + 2560*4;
            const int kk = (kc + 1) * 16;
            cp16(sA + (uint32_t)(r0c*80 + c0c*16), Ag + (size_t)r0c*512 + kk + c0c*4);
            cp16(sA + (uint32_t)(r1c*80 + c1c*16), Ag + (size_t)r1c*512 + kk + c1c*4);
            cp16(sB + (uint32_t)(r0c*80 + c0c*16), Bg + (size_t)r0c*512 + kk + c0c*4);
            cp16(sB + (uint32_t)(r1c*80 + c1c*16), Bg + (size_t)r1c*512 + kk + c1c*4);
            CP_COMMIT();
            CP_WAIT1();
        } else {
            CP_WAIT0();
        }
        __syncthreads();

        const uint32_t boff = (uint32_t)(cur * 5120 * 4);
#pragma unroll
        for (int ks = 0; ks < 2; ks++) {
            uint32_t a[2][4], b[8][2];
#pragma unroll
            for (int mt = 0; mt < 2; mt++)
                ldm_x4(a[mt][0], a[mt][1], a[mt][2], a[mt][3],
                       aFB + boff + (uint32_t)(mt*16*20*4 + ks*32));
#pragma unroll
            for (int ntp = 0; ntp < 4; ntp++)
                ldm_x4(b[2*ntp][0], b[2*ntp][1], b[2*ntp+1][0], b[2*ntp+1][1],
                       bFB + boff + (uint32_t)(ntp*16*20*4 + ks*32));
#pragma unroll
            for (int mt = 0; mt < 2; mt++)
#pragma unroll
                for (int nt = 0; nt < 8; nt++)
                    mma_f16(acc[mt][nt], a[mt], b[nt]);
        }
        __syncthreads();
    }

#pragma unroll
    for (int mt = 0; mt < 2; mt++) {
#pragma unroll
        for (int nt = 0; nt < 8; nt++) {
            const int n = bn + wn*64 + nt*8 + 2*t;    // even d
            const float bv0 = bias[n], bv1 = bias[n+1];
#pragma unroll
            for (int half = 0; half < 2; half++) {
                const int m = bm + wm*32 + mt*16 + g + half*8;
                const float v0 = acc[mt][nt][half*2+0] + bv0;
                const float v1 = acc[mt][nt][half*2+1] + bv1;
                size_t oi;
                if (which < 3) {
                    const int b_ = m >> 9, s = m & 511, h = n >> 6, d = n & 63;
                    oi = (((size_t)(b_*HH + h))*SS + s)*DD + d;
                } else {
                    oi = (((size_t)(n >> 6))*1024 + m)*DD + (n & 63);
                }
                outp[oi >> 1] = packh2(v0, v1);
            }
        }
    }
}

// ---------------- fused flash kernel (unchanged from R11) ------------------
#define FL_SMEM (27136 * 4)   // 108544 B (x2 = 217088 <= 228KB/SM)

__global__ __launch_bounds__(320, 2) void flash_tc(const float* __restrict__ mask,
                                                   float* __restrict__ out)
{
    extern __shared__ uint32_t smw[];
    uint32_t* Qs  = smw;                    // [64 i][36 w] k-pairs of d
    uint32_t* Ks  = smw + 2304;             // [64 j][36 w]
    uint32_t* Ps  = smw + 4608;             // [128 p][36 w] pos band
    uint32_t* Vs  = smw + 9216;             // [64 j][36 w] row-major V
    uint32_t* Pt2 = smw + 11520;            // [64 i][36 w] j-pairs (P~ f16)
    float*    SsF = (float*)(smw + 13824);  // [64][68] CC
    float*    B1  = (float*)(smw + 18176);  // [64][68] sheared CPF
    float*    B2  = (float*)(smw + 22528);  // [64][68] sheared PCF
    float* sm_m     = (float*)(smw + 26880);
    float* sm_l     = sm_m + 64;
    float* sm_scale = sm_m + 128;
    float* sm_mask  = sm_m + 192;

    const int i0 = blockIdx.x * 64;
    const int bh = blockIdx.y;
    const int b_ = bh >> 4, h = bh & 15;
    const int tid = threadIdx.x;
    const int wid = tid >> 5, lane = tid & 31;
    const int g = lane >> 2, t = lane & 3;
    const int wm = wid >> 1, wn = wid & 1;      // PV warp grid (wid<8): 4x2

    const uint32_t* q32 = g_q + ((size_t)bh*SS + i0) * (DD/2);
    const uint32_t* k32 = g_k + (size_t)bh*SS*(DD/2);
    const uint32_t* v32 = g_v + (size_t)bh*SS*(DD/2);
    const uint32_t* p32 = g_pos + (size_t)h * 1024 * (DD/2);

    const uint32_t smQs = smaddr(Qs), smKs = smaddr(Ks), smPs = smaddr(Ps), smVs = smaddr(Vs);

    if (tid < 256) {
#pragma unroll
        for (int i = 0; i < 2; i++) {
            const int u = tid + i*256;
            const int row = u >> 3, c = u & 7;
            cp16(smQs + (uint32_t)(row*144 + c*16), q32 + row*32 + c*4);
        }
    }
    if (tid < 64) { sm_m[tid] = -1e30f; sm_l[tid] = 0.f; }

    float acc_o[4][4];
#pragma unroll
    for (int nt = 0; nt < 4; nt++)
#pragma unroll
        for (int e = 0; e < 4; e++) acc_o[nt][e] = 0.f;

    const uint32_t* Ap; const uint32_t* Bp;
    int Arow, Brow;
    int kind;
    if (wid < 2)      { Ap = Qs; Arow = wid*32;          Bp = Ks; Brow = 0;                 kind = 0; }
    else if (wid < 6) { Ap = Qs; Arow = ((wid-2)&1)*32;  Bp = Ps; Brow = ((wid-2)>>1)*64;   kind = 1; }
    else              { Ap = Ps; Arow = (wid-6)*32;      Bp = Ks; Brow = 0;                 kind = 2; }

    const uint32_t aFB = smaddr(&Ap[(Arow + A_ROW(lane))*36 + A_COL(lane)]);
    const uint32_t bFB = smaddr(&Bp[(Brow + B_ROW(lane))*36 + B_COL(lane)]);
    const uint32_t aPV = smaddr(&Pt2[(wm*16 + A_ROW(lane))*36 + A_COL(lane)]);
    const uint32_t bPVt = smVs
        + (uint32_t)((((lane >> 3) & 1) * 8 + (lane & 7)) * 144
                     + ((lane >> 4) & 1) * 16 + wn * 64);

    const float s1 = 0.14433756729740643f;      // 1/sqrt(48)

    for (int j0 = 0; j0 < SS; j0 += 64) {
        __syncthreads();

        if (tid < 256) {
            const uint32_t* kc32 = k32 + (size_t)j0 * 32;
            const uint32_t* vc32 = v32 + (size_t)j0 * 32;
            const int base = i0 - j0 + 449;
#pragma unroll
            for (int i = 0; i < 8; i++) {
                const int u = tid + i*256;
                const int idx = u & 1023;
                const int row = idx >> 3, c = idx & 7;
                if (u < 512) {
                    cp16(smKs + (uint32_t)(row*144 + c*16), kc32 + row*32 + c*4);
                } else if (u < 1024) {
                    cp16(smVs + (uint32_t)((row-64)*144 + c*16), vc32 + (row-64)*32 + c*4);
                } else {
                    const int pr = (u - 1024) >> 3;
                    int grow = base + pr;
                    grow = grow < 0 ? 0 : (grow > 1023 ? 1023 : grow);
                    cp16(smPs + (uint32_t)(pr*144 + (u & 7)*16), p32 + grow*32 + (u & 7)*4);
                }
            }
            CP_COMMIT();
            CP_WAIT0();
        } else if ((tid - 256) < 64) {
            sm_mask[tid - 256] = mask[(size_t)b_*SS + j0 + tid - 256];
        }
        __syncthreads();

#pragma unroll
        for (int hN = 0; hN < 2; hN++) {
            float acc[2][4][4];
#pragma unroll
            for (int mt = 0; mt < 2; mt++)
#pragma unroll
                for (int nt = 0; nt < 4; nt++)
#pragma unroll
                    for (int e = 0; e < 4; e++) acc[mt][nt][e] = 0.f;

#pragma unroll
            for (int ks = 0; ks < 4; ks++) {
                uint32_t a[2][4], b[4][2];
#pragma unroll
                for (int mt = 0; mt < 2; mt++)
                    ldm_x4(a[mt][0], a[mt][1], a[mt][2], a[mt][3],
                           aFB + (uint32_t)(mt*16*36*4 + ks*32));
#pragma unroll
                for (int ntp = 0; ntp < 2; ntp++)
                    ldm_x4(b[2*ntp][0], b[2*ntp][1], b[2*ntp+1][0], b[2*ntp+1][1],
                           bFB + (uint32_t)((hN*32 + ntp*16)*36*4 + ks*32));
#pragma unroll
                for (int mt = 0; mt < 2; mt++)
#pragma unroll
                    for (int nt = 0; nt < 4; nt++)
                        mma_f16(acc[mt][nt], a[mt], b[nt]);
            }

            if (kind == 0) {
#pragma unroll
                for (int mt = 0; mt < 2; mt++)
#pragma unroll
                    for (int nt = 0; nt < 4; nt++) {
                        const int r0 = Arow + mt*16 + g;
                        const int c0 = (hN*4 + nt)*8 + 2*t;
                        *(float2*)&SsF[r0*68 + c0]     = make_float2(acc[mt][nt][0], acc[mt][nt][1]);
                        *(float2*)&SsF[(r0+8)*68 + c0] = make_float2(acc[mt][nt][2], acc[mt][nt][3]);
                    }
            } else if (kind == 1) {
#pragma unroll
                for (int mt = 0; mt < 2; mt++)
#pragma unroll
                    for (int nt = 0; nt < 4; nt++) {
                        const int ai0 = Arow + mt*16 + g;
                        const int p0 = Brow + (hN*4 + nt)*8 + 2*t;
#pragma unroll
                        for (int e = 0; e < 4; e++) {
                            const int ai = ai0 + (e >> 1)*8;
                            const int p  = p0 + (e & 1);
                            const int cj = ai - p + 63;
                            if ((unsigned)cj < 64u)
                                B1[ai*68 + cj] = acc[mt][nt][e];
                        }
                    }
            } else {
#pragma unroll
                for (int mt = 0; mt < 2; mt++)
#pragma unroll
                    for (int nt = 0; nt < 4; nt++) {
                        const int r0 = Arow + mt*16 + g;
                        const int c0 = (hN*4 + nt)*8 + 2*t;
#pragma unroll
                        for (int e = 0; e < 4; e++) {
                            const int r  = r0 + (e >> 1)*8;
                            const int cj = c0 + (e & 1);
                            const int ai = r + cj - 63;
                            if ((unsigned)ai < 64u)
                                B2[ai*68 + cj] = acc[mt][nt][e];
                        }
                    }
            }
        }
        __syncthreads();

        if (tid < 256) {
            const int row = tid >> 2, q4 = tid & 3;
            const int c0 = q4*16;
            float v[16];
            float mloc = -1e30f;
#pragma unroll
            for (int i4 = 0; i4 < 4; i4++) {
                const float4 sc = *(const float4*)&SsF[row*68 + c0 + 4*i4];
                const float4 y2 = *(const float4*)&B2[row*68 + c0 + 4*i4];
                const float4 y1 = *(const float4*)&B1[row*68 + c0 + 4*i4];
                const float4 mk = *(const float4*)&sm_mask[c0 + 4*i4];
                v[4*i4+0] = (sc.x + y2.x + 0.125f*y1.x) * s1 + mk.x;
                v[4*i4+1] = (sc.y + y2.y + 0.125f*y1.y) * s1 + mk.y;
                v[4*i4+2] = (sc.z + y2.z + 0.125f*y1.z) * s1 + mk.z;
                v[4*i4+3] = (sc.w + y2.w + 0.125f*y1.w) * s1 + mk.w;
                mloc = fmaxf(mloc, fmaxf(fmaxf(v[4*i4], v[4*i4+1]), fmaxf(v[4*i4+2], v[4*i4+3])));
            }
            mloc = fmaxf(mloc, __shfl_xor_sync(0xffffffffu, mloc, 1));
            mloc = fmaxf(mloc, __shfl_xor_sync(0xffffffffu, mloc, 2));
            const float mold = sm_m[row];
            const float mnew = fmaxf(mold, mloc);
            float lsum = 0.f;
#pragma unroll
            for (int i = 0; i < 8; i++) {
                const float e0 = __expf(v[2*i]   - mnew);
                const float e1 = __expf(v[2*i+1] - mnew);
                Pt2[row*36 + q4*8 + i] = packh2(e0, e1);
                lsum += e0 + e1;
            }
            lsum += __shfl_xor_sync(0xffffffffu, lsum, 1);
            lsum += __shfl_xor_sync(0xffffffffu, lsum, 2);
            if (q4 == 0) {
                const float sc = __expf(mold - mnew);
                sm_m[row] = mnew;
                sm_scale[row] = sc;
                sm_l[row] = sm_l[row] * sc + lsum;
            }
        }
        __syncthreads();

        if (wid < 8) {
            const float sc0 = sm_scale[wm*16 + g];
            const float sc1 = sm_scale[wm*16 + g + 8];
#pragma unroll
            for (int nt = 0; nt < 4; nt++) {
                acc_o[nt][0] *= sc0; acc_o[nt][1] *= sc0;
                acc_o[nt][2] *= sc1; acc_o[nt][3] *= sc1;
            }
#pragma unroll
            for (int ks = 0; ks < 4; ks++) {
                uint32_t a[4], b[4][2];
                ldm_x4(a[0], a[1], a[2], a[3], aPV + (uint32_t)(ks*32));
#pragma unroll
                for (int ntp = 0; ntp < 2; ntp++)
                    ldm_x4_t(b[2*ntp][0], b[2*ntp][1], b[2*ntp+1][0], b[2*ntp+1][1],
                             bPVt + (uint32_t)(ks*16*144 + ntp*32));
#pragma unroll
                for (int nt = 0; nt < 4; nt++)
                    mma_f16(acc_o[nt], a, b[nt]);
            }
        }
    }
    __syncthreads();

    if (wid < 8) {
        const int r0 = wm*16 + g;
        const float inv0 = 1.f / sm_l[r0];
        const float inv1 = 1.f / sm_l[r0 + 8];
#pragma unroll
        for (int nt = 0; nt < 4; nt++) {
            const int col = wn*32 + nt*8 + 2*t;
            const size_t o0 = ((size_t)b_*SS + i0 + r0)*HIDN + h*DD + col;
            const size_t o1 = ((size_t)b_*SS + i0 + r0 + 8)*HIDN + h*DD + col;
            *(float2*)(out + o0) = make_float2(acc_o[nt][0]*inv0, acc_o[nt][1]*inv0);
            *(float2*)(out + o1) = make_float2(acc_o[nt][2]*inv1, acc_o[nt][3]*inv1);
        }
    }
}

// ---------------- launch ---------------------------------------------------
extern "C" void kernel_launch(void* const* d_in, const int* in_sizes, int n_in,
                              void* d_out, int out_size)
{
    const float* hs  = (const float*)d_in[0];
    const float* msk = (const float*)d_in[1];
    const float* Wq  = (const float*)d_in[3];
    const float* bq  = (const float*)d_in[4];
    const float* Wk  = (const float*)d_in[5];
    const float* bk  = (const float*)d_in[6];
    const float* Wv  = (const float*)d_in[7];
    const float* bv  = (const float*)d_in[8];
    const float* Wpk = (const float*)d_in[9];
    const float* bpk = (const float*)d_in[10];
    const float* rel = (const float*)d_in[11];
    float* out = (float*)d_out;

    cudaFuncSetAttribute(flash_tc, cudaFuncAttributeMaxDynamicSharedMemorySize, FL_SMEM);

    dim3 gc(4096, 6);                     // fp32 -> fp16 one-time convert
    precvt<<<gc, 256>>>(hs, rel, Wq, Wk, Wv, Wpk);

    dim3 gg(8, 32, 4);                    // z: Wq, Wk, Wv, Wpk (y>=8 idles for z=3)
    gemm_tc<<<gg, 256>>>(bq, bk, bv, bpk);

    dim3 gf(SS/64, BH);                   // (8, 128)
    flash_tc<<<gf, 320, FL_SMEM>>>(msk, out);
}

// round 13
// speedup vs baseline: 3.2314x; 1.0679x over previous
#include <cuda_runtime.h>
#include <cuda_fp16.h>
#include <cstdint>

#define BB   8
#define SS   512
#define HH   16
#define DD   64
#define HIDN 1024
#define BH   (BB*HH)   // 128

// ---------------- scratch (device globals, fp16 packed as half2 words) -----
__device__ uint32_t g_q[BH*SS*DD/2];            // [b,h,s,d/2] 8MB
__device__ uint32_t g_k[BH*SS*DD/2];
__device__ uint32_t g_v[BH*SS*DD/2];
__device__ uint32_t g_pos[HH*1024*DD/2];        // [h,p,d/2]   2MB
__device__ uint32_t g_hs16[BB*SS*HIDN/2];       // fp16 hidden_states 8MB
__device__ uint32_t g_rel16[1024*HIDN/2];       // fp16 rel_emb 2MB
__device__ uint32_t g_w16[4][HIDN*HIDN/2];      // fp16 Wq,Wk,Wv,Wpk 4x2MB

// ---------------- helpers ---------------------------------------------------
__device__ __forceinline__ uint32_t packh2(float lo, float hi) {
    uint32_t u;
    asm("cvt.rn.f16x2.f32 %0, %1, %2;" : "=r"(u) : "f"(hi), "f"(lo));
    return u;
}
__device__ __forceinline__ uint32_t smaddr(const void* p) {
    uint32_t a;
    asm("{ .reg .u64 t; cvta.to.shared.u64 t, %1; cvt.u32.u64 %0, t; }" : "=r"(a) : "l"(p));
    return a;
}
__device__ __forceinline__ void mma_f16(float c[4], const uint32_t a[4], const uint32_t b[2]) {
    asm volatile("mma.sync.aligned.m16n8k16.row.col.f32.f16.f16.f32 "
        "{%0,%1,%2,%3}, {%4,%5,%6,%7}, {%8,%9}, {%0,%1,%2,%3};"
        : "+f"(c[0]), "+f"(c[1]), "+f"(c[2]), "+f"(c[3])
        : "r"(a[0]), "r"(a[1]), "r"(a[2]), "r"(a[3]), "r"(b[0]), "r"(b[1]));
}
__device__ __forceinline__ void ldm_x4(uint32_t& r0, uint32_t& r1, uint32_t& r2, uint32_t& r3,
                                       uint32_t addr) {
    asm volatile("ldmatrix.sync.aligned.m8n8.x4.shared.b16 {%0,%1,%2,%3}, [%4];"
        : "=r"(r0), "=r"(r1), "=r"(r2), "=r"(r3) : "r"(addr));
}
__device__ __forceinline__ void ldm_x4_t(uint32_t& r0, uint32_t& r1, uint32_t& r2, uint32_t& r3,
                                         uint32_t addr) {
    asm volatile("ldmatrix.sync.aligned.m8n8.x4.trans.shared.b16 {%0,%1,%2,%3}, [%4];"
        : "=r"(r0), "=r"(r1), "=r"(r2), "=r"(r3) : "r"(addr));
}
__device__ __forceinline__ void cp16(uint32_t smem_dst, const void* gsrc) {
    asm volatile("cp.async.ca.shared.global [%0], [%1], 16;" :: "r"(smem_dst), "l"(gsrc));
}
#define CP_COMMIT() asm volatile("cp.async.commit_group;" ::: "memory")
#define CP_WAIT0()  asm volatile("cp.async.wait_group 0;" ::: "memory")
#define CP_WAIT1()  asm volatile("cp.async.wait_group 1;" ::: "memory")

// fragment-base lane offsets
#define A_ROW(lane)  ((lane) & 15)
#define A_COL(lane)  ((((lane) >> 4) & 1) << 2)
#define B_ROW(lane)  (((((lane) >> 4) & 1) << 3) + ((lane) & 7))
#define B_COL(lane)  ((((lane) >> 3) & 1) << 2)

// ---------------- precvt: fp32 -> fp16 (one-time, 32B/thread) ---------------
__global__ __launch_bounds__(256) void precvt(
    const float* __restrict__ hs, const float* __restrict__ rel,
    const float* __restrict__ Wq, const float* __restrict__ Wk,
    const float* __restrict__ Wv, const float* __restrict__ Wpk)
{
    const int seg = blockIdx.y;
    const float* src;
    uint32_t* dst;
    int n;
    switch (seg) {
        case 0: src = hs;  dst = g_hs16;  n = BB*SS*HIDN; break;
        case 1: src = rel; dst = g_rel16; n = 1024*HIDN;  break;
        case 2: src = Wq;  dst = g_w16[0]; n = HIDN*HIDN; break;
        case 3: src = Wk;  dst = g_w16[1]; n = HIDN*HIDN; break;
        case 4: src = Wv;  dst = g_w16[2]; n = HIDN*HIDN; break;
        default: src = Wpk; dst = g_w16[3]; n = HIDN*HIDN; break;
    }
    const int i = (blockIdx.x * 256 + threadIdx.x) * 8;
    if (i >= n) return;
    const float4 x = *(const float4*)(src + i);
    const float4 y = *(const float4*)(src + i + 4);
    *(uint4*)&dst[i >> 1] = make_uint4(packh2(x.x, x.y), packh2(x.z, x.w),
                                       packh2(y.x, y.y), packh2(y.z, y.w));
}

// ---------------- fp16 HMMA projection GEMM (K-chunk 64, 2-buf cp.async) ---
__global__ __launch_bounds__(256, 2) void gemm_tc(
    const float* __restrict__ bq, const float* __restrict__ bk,
    const float* __restrict__ bv, const float* __restrict__ bpk)
{
    __shared__ uint32_t sm[2*9216];   // [A0|B0|A1|B1], each 128x36 words

    const int which = blockIdx.z;
    if (which == 3 && blockIdx.y >= 8) return;

    const uint32_t* Ag = ((which == 3) ? g_rel16 : g_hs16);
    const uint32_t* Bg = g_w16[which];
    const float* bias = (which == 0) ? bq : (which == 1) ? bk : (which == 2) ? bv : bpk;
    uint32_t* outp    = (which == 0) ? g_q : (which == 1) ? g_k : (which == 2) ? g_v : g_pos;

    const int bm = blockIdx.y * 128;
    const int bn = blockIdx.x * 128;
    const int tid = threadIdx.x;
    const int wid = tid >> 5, lane = tid & 31;
    const int wm = wid >> 1, wn = wid & 1;
    const int g = lane >> 2, t = lane & 3;

    Ag += (size_t)bm * (HIDN/2);
    Bg += (size_t)bn * (HIDN/2);

    float acc[2][8][4];
#pragma unroll
    for (int mt = 0; mt < 2; mt++)
#pragma unroll
        for (int nt = 0; nt < 8; nt++)
#pragma unroll
            for (int i = 0; i < 4; i++) acc[mt][nt][i] = 0.f;

    const uint32_t smBase = smaddr(sm);
    const uint32_t aFB = smaddr(&sm[(wm*32 + A_ROW(lane))*36 + A_COL(lane)]);
    const uint32_t bFB = smaddr(&sm[4608 + (wn*64 + B_ROW(lane))*36 + B_COL(lane)]);

    // prologue: fill buffer 0 (K-chunk 64 halves = 32 words/row; 4 cp/operand)
#pragma unroll
    for (int i = 0; i < 4; i++) {
        const int u = tid + i*256, row = u >> 3, c = u & 7;
        cp16(smBase + (uint32_t)(row*144 + c*16),          Ag + (size_t)row*512 + c*4);
        cp16(smBase + (uint32_t)(4608*4 + row*144 + c*16), Bg + (size_t)row*512 + c*4);
    }
    CP_COMMIT();

    for (int kc = 0; kc < 16; kc++) {
        const int cur = kc & 1;
        if (kc < 15) {
            const uint32_t off = (uint32_t)((cur ^ 1) * 9216 * 4);
            const int kk = (kc + 1) * 32;
#pragma unroll
            for (int i = 0; i < 4; i++) {
                const int u = tid + i*256, row = u >> 3, c = u & 7;
                cp16(smBase + off + (uint32_t)(row*144 + c*16),          Ag + (size_t)row*512 + kk + c*4);
                cp16(smBase + off + (uint32_t)(4608*4 + row*144 + c*16), Bg + (size_t)row*512 + kk + c*4);
            }
            CP_COMMIT();
            CP_WAIT1();
        } else {
            CP_WAIT0();
        }
        __syncthreads();

        const uint32_t boff = (uint32_t)(cur * 9216 * 4);
#pragma unroll
        for (int ks = 0; ks < 4; ks++) {
            uint32_t a[2][4], b[8][2];
#pragma unroll
            for (int mt = 0; mt < 2; mt++)
                ldm_x4(a[mt][0], a[mt][1], a[mt][2], a[mt][3],
                       aFB + boff + (uint32_t)(mt*16*36*4 + ks*32));
#pragma unroll
            for (int ntp = 0; ntp < 4; ntp++)
                ldm_x4(b[2*ntp][0], b[2*ntp][1], b[2*ntp+1][0], b[2*ntp+1][1],
                       bFB + boff + (uint32_t)(ntp*16*36*4 + ks*32));
#pragma unroll
            for (int mt = 0; mt < 2; mt++)
#pragma unroll
                for (int nt = 0; nt < 8; nt++)
                    mma_f16(acc[mt][nt], a[mt], b[nt]);
        }
        __syncthreads();
    }

#pragma unroll
    for (int mt = 0; mt < 2; mt++) {
#pragma unroll
        for (int nt = 0; nt < 8; nt++) {
            const int n = bn + wn*64 + nt*8 + 2*t;
            const float bv0 = bias[n], bv1 = bias[n+1];
#pragma unroll
            for (int half = 0; half < 2; half++) {
                const int m = bm + wm*32 + mt*16 + g + half*8;
                const float v0 = acc[mt][nt][half*2+0] + bv0;
                const float v1 = acc[mt][nt][half*2+1] + bv1;
                size_t oi;
                if (which < 3) {
                    const int b_ = m >> 9, s = m & 511, h = n >> 6, d = n & 63;
                    oi = (((size_t)(b_*HH + h))*SS + s)*DD + d;
                } else {
                    oi = (((size_t)(n >> 6))*1024 + m)*DD + (n & 63);
                }
                outp[oi >> 1] = packh2(v0, v1);
            }
        }
    }
}

// ---------------- fused flash kernel (K/P prefetch under softmax+PV) -------
#define FL_SMEM (27136 * 4)   // 108544 B (x2 = 217088 <= 228KB/SM)

__global__ __launch_bounds__(320, 2) void flash_tc(const float* __restrict__ mask,
                                                   float* __restrict__ out)
{
    extern __shared__ uint32_t smw[];
    uint32_t* Qs  = smw;                    // [64 i][36 w]
    uint32_t* Ks  = smw + 2304;             // [64 j][36 w]
    uint32_t* Ps  = smw + 4608;             // [128 p][36 w]
    uint32_t* Vs  = smw + 9216;             // [64 j][36 w] row-major V
    uint32_t* Pt2 = smw + 11520;            // [64 i][36 w] P~ f16
    float*    SsF = (float*)(smw + 13824);  // [64][68] CC
    float*    B1  = (float*)(smw + 18176);  // [64][68] sheared CPF
    float*    B2  = (float*)(smw + 22528);  // [64][68] sheared PCF
    float* sm_m     = (float*)(smw + 26880);
    float* sm_l     = sm_m + 64;
    float* sm_scale = sm_m + 128;
    float* sm_mask  = sm_m + 192;

    const int i0 = blockIdx.x * 64;
    const int bh = blockIdx.y;
    const int b_ = bh >> 4, h = bh & 15;
    const int tid = threadIdx.x;
    const int wid = tid >> 5, lane = tid & 31;
    const int g = lane >> 2, t = lane & 3;
    const int wm = wid >> 1, wn = wid & 1;

    const uint32_t* q32 = g_q + ((size_t)bh*SS + i0) * (DD/2);
    const uint32_t* k32 = g_k + (size_t)bh*SS*(DD/2);
    const uint32_t* v32 = g_v + (size_t)bh*SS*(DD/2);
    const uint32_t* p32 = g_pos + (size_t)h * 1024 * (DD/2);

    const uint32_t smQs = smaddr(Qs), smKs = smaddr(Ks), smPs = smaddr(Ps), smVs = smaddr(Vs);

    // Q + chunk-0 K,P via cp.async (committed with chunk 0's V)
    if (tid < 256) {
#pragma unroll
        for (int i = 0; i < 2; i++) {
            const int u = tid + i*256, row = u >> 3, c = u & 7;
            cp16(smQs + (uint32_t)(row*144 + c*16), q32 + row*32 + c*4);
            cp16(smKs + (uint32_t)(row*144 + c*16), k32 + row*32 + c*4);
        }
        const int base0 = i0 + 449;
#pragma unroll
        for (int i = 0; i < 4; i++) {
            const int u = tid + i*256, pr = u >> 3, c = u & 7;
            int grow = base0 + pr;
            grow = grow < 0 ? 0 : (grow > 1023 ? 1023 : grow);
            cp16(smPs + (uint32_t)(pr*144 + c*16), p32 + grow*32 + c*4);
        }
    }
    if (tid < 64) { sm_m[tid] = -1e30f; sm_l[tid] = 0.f; }

    float acc_o[4][4];
#pragma unroll
    for (int nt = 0; nt < 4; nt++)
#pragma unroll
        for (int e = 0; e < 4; e++) acc_o[nt][e] = 0.f;

    const uint32_t* Ap; const uint32_t* Bp;
    int Arow, Brow;
    int kind;
    if (wid < 2)      { Ap = Qs; Arow = wid*32;          Bp = Ks; Brow = 0;                 kind = 0; }
    else if (wid < 6) { Ap = Qs; Arow = ((wid-2)&1)*32;  Bp = Ps; Brow = ((wid-2)>>1)*64;   kind = 1; }
    else              { Ap = Ps; Arow = (wid-6)*32;      Bp = Ks; Brow = 0;                 kind = 2; }

    const uint32_t aFB = smaddr(&Ap[(Arow + A_ROW(lane))*36 + A_COL(lane)]);
    const uint32_t bFB = smaddr(&Bp[(Brow + B_ROW(lane))*36 + B_COL(lane)]);
    const uint32_t aPV = smaddr(&Pt2[(wm*16 + A_ROW(lane))*36 + A_COL(lane)]);
    const uint32_t bPVt = smVs
        + (uint32_t)((((lane >> 3) & 1) * 8 + (lane & 7)) * 144
                     + ((lane >> 4) & 1) * 16 + wn * 64);

    const float s1 = 0.14433756729740643f;      // 1/sqrt(48)

    for (int j0 = 0; j0 < SS; j0 += 64) {
        __syncthreads();   // previous chunk's Vs/Pt2 reads complete

        // ---- load phase: V only (K/P prefetched); wait all outstanding ----
        if (tid < 256) {
            const uint32_t* vc32 = v32 + (size_t)j0 * 32;
#pragma unroll
            for (int i = 0; i < 2; i++) {
                const int u = tid + i*256, row = u >> 3, c = u & 7;
                cp16(smVs + (uint32_t)(row*144 + c*16), vc32 + row*32 + c*4);
            }
            CP_COMMIT();
            CP_WAIT0();
        } else if ((tid - 256) < 64) {
            sm_mask[tid - 256] = mask[(size_t)b_*SS + j0 + tid - 256];
        }
        __syncthreads();

        // ---- score MMAs in two nt-halves; shear stores ----
#pragma unroll
        for (int hN = 0; hN < 2; hN++) {
            float acc[2][4][4];
#pragma unroll
            for (int mt = 0; mt < 2; mt++)
#pragma unroll
                for (int nt = 0; nt < 4; nt++)
#pragma unroll
                    for (int e = 0; e < 4; e++) acc[mt][nt][e] = 0.f;

#pragma unroll
            for (int ks = 0; ks < 4; ks++) {
                uint32_t a[2][4], b[4][2];
#pragma unroll
                for (int mt = 0; mt < 2; mt++)
                    ldm_x4(a[mt][0], a[mt][1], a[mt][2], a[mt][3],
                           aFB + (uint32_t)(mt*16*36*4 + ks*32));
#pragma unroll
                for (int ntp = 0; ntp < 2; ntp++)
                    ldm_x4(b[2*ntp][0], b[2*ntp][1], b[2*ntp+1][0], b[2*ntp+1][1],
                           bFB + (uint32_t)((hN*32 + ntp*16)*36*4 + ks*32));
#pragma unroll
                for (int mt = 0; mt < 2; mt++)
#pragma unroll
                    for (int nt = 0; nt < 4; nt++)
                        mma_f16(acc[mt][nt], a[mt], b[nt]);
            }

            if (kind == 0) {
#pragma unroll
                for (int mt = 0; mt < 2; mt++)
#pragma unroll
                    for (int nt = 0; nt < 4; nt++) {
                        const int r0 = Arow + mt*16 + g;
                        const int c0 = (hN*4 + nt)*8 + 2*t;
                        *(float2*)&SsF[r0*68 + c0]     = make_float2(acc[mt][nt][0], acc[mt][nt][1]);
                        *(float2*)&SsF[(r0+8)*68 + c0] = make_float2(acc[mt][nt][2], acc[mt][nt][3]);
                    }
            } else if (kind == 1) {
#pragma unroll
                for (int mt = 0; mt < 2; mt++)
#pragma unroll
                    for (int nt = 0; nt < 4; nt++) {
                        const int ai0 = Arow + mt*16 + g;
                        const int p0 = Brow + (hN*4 + nt)*8 + 2*t;
#pragma unroll
                        for (int e = 0; e < 4; e++) {
                            const int ai = ai0 + (e >> 1)*8;
                            const int p  = p0 + (e & 1);
                            const int cj = ai - p + 63;
                            if ((unsigned)cj < 64u)
                                B1[ai*68 + cj] = acc[mt][nt][e];
                        }
                    }
            } else {
#pragma unroll
                for (int mt = 0; mt < 2; mt++)
#pragma unroll
                    for (int nt = 0; nt < 4; nt++) {
                        const int r0 = Arow + mt*16 + g;
                        const int c0 = (hN*4 + nt)*8 + 2*t;
#pragma unroll
                        for (int e = 0; e < 4; e++) {
                            const int r  = r0 + (e >> 1)*8;
                            const int cj = c0 + (e & 1);
                            const int ai = r + cj - 63;
                            if ((unsigned)ai < 64u)
                                B2[ai*68 + cj] = acc[mt][nt][e];
                        }
                    }
            }
        }
        __syncthreads();   // all warps past Ks/Ps reads -> safe to prefetch over them

        // ---- prefetch next chunk's K & P; overlaps softmax + PV ----
        if (j0 + 64 < SS && tid < 256) {
            const uint32_t* kn32 = k32 + (size_t)(j0 + 64) * 32;
            const int basen = i0 - (j0 + 64) + 449;
#pragma unroll
            for (int i = 0; i < 2; i++) {
                const int u = tid + i*256, row = u >> 3, c = u & 7;
                cp16(smKs + (uint32_t)(row*144 + c*16), kn32 + row*32 + c*4);
            }
#pragma unroll
            for (int i = 0; i < 4; i++) {
                const int u = tid + i*256, pr = u >> 3, c = u & 7;
                int grow = basen + pr;
                grow = grow < 0 ? 0 : (grow > 1023 ? 1023 : grow);
                cp16(smPs + (uint32_t)(pr*144 + c*16), p32 + grow*32 + c*4);
            }
            CP_COMMIT();
        }

        // ---- online softmax (threads 0..255); vectorized 3-buffer combine --
        if (tid < 256) {
            const int row = tid >> 2, q4 = tid & 3;
            const int c0 = q4*16;
            float v[16];
            float mloc = -1e30f;
#pragma unroll
            for (int i4 = 0; i4 < 4; i4++) {
                const float4 sc = *(const float4*)&SsF[row*68 + c0 + 4*i4];
                const float4 y2 = *(const float4*)&B2[row*68 + c0 + 4*i4];
                const float4 y1 = *(const float4*)&B1[row*68 + c0 + 4*i4];
                const float4 mk = *(const float4*)&sm_mask[c0 + 4*i4];
                v[4*i4+0] = (sc.x + y2.x + 0.125f*y1.x) * s1 + mk.x;
                v[4*i4+1] = (sc.y + y2.y + 0.125f*y1.y) * s1 + mk.y;
                v[4*i4+2] = (sc.z + y2.z + 0.125f*y1.z) * s1 + mk.z;
                v[4*i4+3] = (sc.w + y2.w + 0.125f*y1.w) * s1 + mk.w;
                mloc = fmaxf(mloc, fmaxf(fmaxf(v[4*i4], v[4*i4+1]), fmaxf(v[4*i4+2], v[4*i4+3])));
            }
            mloc = fmaxf(mloc, __shfl_xor_sync(0xffffffffu, mloc, 1));
            mloc = fmaxf(mloc, __shfl_xor_sync(0xffffffffu, mloc, 2));
            const float mold = sm_m[row];
            const float mnew = fmaxf(mold, mloc);
            float lsum = 0.f;
#pragma unroll
            for (int i = 0; i < 8; i++) {
                const float e0 = __expf(v[2*i]   - mnew);
                const float e1 = __expf(v[2*i+1] - mnew);
                Pt2[row*36 + q4*8 + i] = packh2(e0, e1);
                lsum += e0 + e1;
            }
            lsum += __shfl_xor_sync(0xffffffffu, lsum, 1);
            lsum += __shfl_xor_sync(0xffffffffu, lsum, 2);
            if (q4 == 0) {
                const float sc = __expf(mold - mnew);
                sm_m[row] = mnew;
                sm_scale[row] = sc;
                sm_l[row] = sm_l[row] * sc + lsum;
            }
        }
        __syncthreads();

        // ---- PV: warps 0..7, out tile 64x64, warp tile 16x32 ----
        if (wid < 8) {
            const float sc0 = sm_scale[wm*16 + g];
            const float sc1 = sm_scale[wm*16 + g + 8];
#pragma unroll
            for (int nt = 0; nt < 4; nt++) {
                acc_o[nt][0] *= sc0; acc_o[nt][1] *= sc0;
                acc_o[nt][2] *= sc1; acc_o[nt][3] *= sc1;
            }
#pragma unroll
            for (int ks = 0; ks < 4; ks++) {
                uint32_t a[4], b[4][2];
                ldm_x4(a[0], a[1], a[2], a[3], aPV + (uint32_t)(ks*32));
#pragma unroll
                for (int ntp = 0; ntp < 2; ntp++)
                    ldm_x4_t(b[2*ntp][0], b[2*ntp][1], b[2*ntp+1][0], b[2*ntp+1][1],
                             bPVt + (uint32_t)(ks*16*144 + ntp*32));
#pragma unroll
                for (int nt = 0; nt < 4; nt++)
                    mma_f16(acc_o[nt], a, b[nt]);
            }
        }
    }
    __syncthreads();

    // ---- finalize: out[i][d] = acc_o / l ----
    if (wid < 8) {
        const int r0 = wm*16 + g;
        const float inv0 = 1.f / sm_l[r0];
        const float inv1 = 1.f / sm_l[r0 + 8];
#pragma unroll
        for (int nt = 0; nt < 4; nt++) {
            const int col = wn*32 + nt*8 + 2*t;
            const size_t o0 = ((size_t)b_*SS + i0 + r0)*HIDN + h*DD + col;
            const size_t o1 = ((size_t)b_*SS + i0 + r0 + 8)*HIDN + h*DD + col;
            *(float2*)(out + o0) = make_float2(acc_o[nt][0]*inv0, acc_o[nt][1]*inv0);
            *(float2*)(out + o1) = make_float2(acc_o[nt][2]*inv1, acc_o[nt][3]*inv1);
        }
    }
}

// ---------------- launch ---------------------------------------------------
extern "C" void kernel_launch(void* const* d_in, const int* in_sizes, int n_in,
                              void* d_out, int out_size)
{
    const float* hs  = (const float*)d_in[0];
    const float* msk = (const float*)d_in[1];
    const float* Wq  = (const float*)d_in[3];
    const float* bq  = (const float*)d_in[4];
    const float* Wk  = (const float*)d_in[5];
    const float* bk  = (const float*)d_in[6];
    const float* Wv  = (const float*)d_in[7];
    const float* bv  = (const float*)d_in[8];
    const float* Wpk = (const float*)d_in[9];
    const float* bpk = (const float*)d_in[10];
    const float* rel = (const float*)d_in[11];
    float* out = (float*)d_out;

    cudaFuncSetAttribute(flash_tc, cudaFuncAttributeMaxDynamicSharedMemorySize, FL_SMEM);

    dim3 gc(2048, 6);                     // fp32 -> fp16 one-time convert (32B/thr)
    precvt<<<gc, 256>>>(hs, rel, Wq, Wk, Wv, Wpk);

    dim3 gg(8, 32, 4);                    // z: Wq, Wk, Wv, Wpk (y>=8 idles for z=3)
    gemm_tc<<<gg, 256>>>(bq, bk, bv, bpk);

    dim3 gf(SS/64, BH);                   // (8, 128)
    flash_tc<<<gf, 320, FL_SMEM>>>(msk, out);
}

// round 14
// speedup vs baseline: 3.3093x; 1.0241x over previous
#include <cuda_runtime.h>
#include <cuda_fp16.h>
#include <cstdint>

#define BB   8
#define SS   512
#define HH   16
#define DD   64
#define HIDN 1024
#define BH   (BB*HH)   // 128

// ---------------- scratch (device globals, fp16 packed as half2 words) -----
__device__ uint32_t g_q[BH*SS*DD/2];            // [b,h,s,d/2] 8MB
__device__ uint32_t g_k[BH*SS*DD/2];
__device__ uint32_t g_v[BH*SS*DD/2];
__device__ uint32_t g_pos[HH*1024*DD/2];        // [h,p,d/2]   2MB
__device__ uint32_t g_hs16[BB*SS*HIDN/2];       // fp16 hidden_states 8MB
__device__ uint32_t g_rel16[1024*HIDN/2];       // fp16 rel_emb 2MB
__device__ uint32_t g_w16[4][HIDN*HIDN/2];      // fp16 Wq,Wk,Wv,Wpk 4x2MB

// ---------------- helpers ---------------------------------------------------
__device__ __forceinline__ uint32_t packh2(float lo, float hi) {
    uint32_t u;
    asm("cvt.rn.f16x2.f32 %0, %1, %2;" : "=r"(u) : "f"(hi), "f"(lo));
    return u;
}
__device__ __forceinline__ uint32_t smaddr(const void* p) {
    uint32_t a;
    asm("{ .reg .u64 t; cvta.to.shared.u64 t, %1; cvt.u32.u64 %0, t; }" : "=r"(a) : "l"(p));
    return a;
}
__device__ __forceinline__ void mma_f16(float c[4], const uint32_t a[4], const uint32_t b[2]) {
    asm volatile("mma.sync.aligned.m16n8k16.row.col.f32.f16.f16.f32 "
        "{%0,%1,%2,%3}, {%4,%5,%6,%7}, {%8,%9}, {%0,%1,%2,%3};"
        : "+f"(c[0]), "+f"(c[1]), "+f"(c[2]), "+f"(c[3])
        : "r"(a[0]), "r"(a[1]), "r"(a[2]), "r"(a[3]), "r"(b[0]), "r"(b[1]));
}
__device__ __forceinline__ void ldm_x4(uint32_t& r0, uint32_t& r1, uint32_t& r2, uint32_t& r3,
                                       uint32_t addr) {
    asm volatile("ldmatrix.sync.aligned.m8n8.x4.shared.b16 {%0,%1,%2,%3}, [%4];"
        : "=r"(r0), "=r"(r1), "=r"(r2), "=r"(r3) : "r"(addr));
}
__device__ __forceinline__ void ldm_x4_t(uint32_t& r0, uint32_t& r1, uint32_t& r2, uint32_t& r3,
                                         uint32_t addr) {
    asm volatile("ldmatrix.sync.aligned.m8n8.x4.trans.shared.b16 {%0,%1,%2,%3}, [%4];"
        : "=r"(r0), "=r"(r1), "=r"(r2), "=r"(r3) : "r"(addr));
}
__device__ __forceinline__ void cp16(uint32_t smem_dst, const void* gsrc) {
    asm volatile("cp.async.ca.shared.global [%0], [%1], 16;" :: "r"(smem_dst), "l"(gsrc));
}
#define CP_COMMIT() asm volatile("cp.async.commit_group;" ::: "memory")
#define CP_WAIT0()  asm volatile("cp.async.wait_group 0;" ::: "memory")
#define CP_WAIT1()  asm volatile("cp.async.wait_group 1;" ::: "memory")

// fragment-base lane offsets
#define A_ROW(lane)  ((lane) & 15)
#define A_COL(lane)  ((((lane) >> 4) & 1) << 2)
#define B_ROW(lane)  (((((lane) >> 4) & 1) << 3) + ((lane) & 7))
#define B_COL(lane)  ((((lane) >> 3) & 1) << 2)

// ---------------- precvt: fp32 -> fp16 (one-time, 32B/thread) ---------------
__global__ __launch_bounds__(256) void precvt(
    const float* __restrict__ hs, const float* __restrict__ rel,
    const float* __restrict__ Wq, const float* __restrict__ Wk,
    const float* __restrict__ Wv, const float* __restrict__ Wpk)
{
    const int seg = blockIdx.y;
    const float* src;
    uint32_t* dst;
    int n;
    switch (seg) {
        case 0: src = hs;  dst = g_hs16;  n = BB*SS*HIDN; break;
        case 1: src = rel; dst = g_rel16; n = 1024*HIDN;  break;
        case 2: src = Wq;  dst = g_w16[0]; n = HIDN*HIDN; break;
        case 3: src = Wk;  dst = g_w16[1]; n = HIDN*HIDN; break;
        case 4: src = Wv;  dst = g_w16[2]; n = HIDN*HIDN; break;
        default: src = Wpk; dst = g_w16[3]; n = HIDN*HIDN; break;
    }
    const int i = (blockIdx.x * 256 + threadIdx.x) * 8;
    if (i >= n) return;
    const float4 x = *(const float4*)(src + i);
    const float4 y = *(const float4*)(src + i + 4);
    *(uint4*)&dst[i >> 1] = make_uint4(packh2(x.x, x.y), packh2(x.z, x.w),
                                       packh2(y.x, y.y), packh2(y.z, y.w));
}

// ---------------- fp16 HMMA projection GEMM (K-chunk 64, 2-buf cp.async) ---
__global__ __launch_bounds__(256, 2) void gemm_tc(
    const float* __restrict__ bq, const float* __restrict__ bk,
    const float* __restrict__ bv, const float* __restrict__ bpk)
{
    __shared__ uint32_t sm[2*9216];   // [A0|B0|A1|B1], each 128x36 words

    const int which = blockIdx.z;
    if (which == 3 && blockIdx.y >= 8) return;

    const uint32_t* Ag = ((which == 3) ? g_rel16 : g_hs16);
    const uint32_t* Bg = g_w16[which];
    const float* bias = (which == 0) ? bq : (which == 1) ? bk : (which == 2) ? bv : bpk;
    uint32_t* outp    = (which == 0) ? g_q : (which == 1) ? g_k : (which == 2) ? g_v : g_pos;

    const int bm = blockIdx.y * 128;
    const int bn = blockIdx.x * 128;
    const int tid = threadIdx.x;
    const int wid = tid >> 5, lane = tid & 31;
    const int wm = wid >> 1, wn = wid & 1;
    const int g = lane >> 2, t = lane & 3;

    Ag += (size_t)bm * (HIDN/2);
    Bg += (size_t)bn * (HIDN/2);

    float acc[2][8][4];
#pragma unroll
    for (int mt = 0; mt < 2; mt++)
#pragma unroll
        for (int nt = 0; nt < 8; nt++)
#pragma unroll
            for (int i = 0; i < 4; i++) acc[mt][nt][i] = 0.f;

    const uint32_t smBase = smaddr(sm);
    const uint32_t aFB = smaddr(&sm[(wm*32 + A_ROW(lane))*36 + A_COL(lane)]);
    const uint32_t bFB = smaddr(&sm[4608 + (wn*64 + B_ROW(lane))*36 + B_COL(lane)]);

#pragma unroll
    for (int i = 0; i < 4; i++) {
        const int u = tid + i*256, row = u >> 3, c = u & 7;
        cp16(smBase + (uint32_t)(row*144 + c*16),          Ag + (size_t)row*512 + c*4);
        cp16(smBase + (uint32_t)(4608*4 + row*144 + c*16), Bg + (size_t)row*512 + c*4);
    }
    CP_COMMIT();

    for (int kc = 0; kc < 16; kc++) {
        const int cur = kc & 1;
        if (kc < 15) {
            const uint32_t off = (uint32_t)((cur ^ 1) * 9216 * 4);
            const int kk = (kc + 1) * 32;
#pragma unroll
            for (int i = 0; i < 4; i++) {
                const int u = tid + i*256, row = u >> 3, c = u & 7;
                cp16(smBase + off + (uint32_t)(row*144 + c*16),          Ag + (size_t)row*512 + kk + c*4);
                cp16(smBase + off + (uint32_t)(4608*4 + row*144 + c*16), Bg + (size_t)row*512 + kk + c*4);
            }
            CP_COMMIT();
            CP_WAIT1();
        } else {
            CP_WAIT0();
        }
        __syncthreads();

        const uint32_t boff = (uint32_t)(cur * 9216 * 4);
#pragma unroll
        for (int ks = 0; ks < 4; ks++) {
            uint32_t a[2][4], b[8][2];
#pragma unroll
            for (int mt = 0; mt < 2; mt++)
                ldm_x4(a[mt][0], a[mt][1], a[mt][2], a[mt][3],
                       aFB + boff + (uint32_t)(mt*16*36*4 + ks*32));
#pragma unroll
            for (int ntp = 0; ntp < 4; ntp++)
                ldm_x4(b[2*ntp][0], b[2*ntp][1], b[2*ntp+1][0], b[2*ntp+1][1],
                       bFB + boff + (uint32_t)(ntp*16*36*4 + ks*32));
#pragma unroll
            for (int mt = 0; mt < 2; mt++)
#pragma unroll
                for (int nt = 0; nt < 8; nt++)
                    mma_f16(acc[mt][nt], a[mt], b[nt]);
        }
        __syncthreads();
    }

#pragma unroll
    for (int mt = 0; mt < 2; mt++) {
#pragma unroll
        for (int nt = 0; nt < 8; nt++) {
            const int n = bn + wn*64 + nt*8 + 2*t;
            const float bv0 = bias[n], bv1 = bias[n+1];
#pragma unroll
            for (int half = 0; half < 2; half++) {
                const int m = bm + wm*32 + mt*16 + g + half*8;
                const float v0 = acc[mt][nt][half*2+0] + bv0;
                const float v1 = acc[mt][nt][half*2+1] + bv1;
                size_t oi;
                if (which < 3) {
                    const int b_ = m >> 9, s = m & 511, h = n >> 6, d = n & 63;
                    oi = (((size_t)(b_*HH + h))*SS + s)*DD + d;
                } else {
                    oi = (((size_t)(n >> 6))*1024 + m)*DD + (n & 63);
                }
                outp[oi >> 1] = packh2(v0, v1);
            }
        }
    }
}

// ---------------- fused flash kernel (fully pipelined cp.async) ------------
// words: Qs 2304 | Ks 2304 | Ps 4608 | Vs 2304 | Pt2 2304 | SsF 4352 | B1 4352
//        | B2 4352 | m/l/scale 192 | mask512 512  -> 27584 words = 110336 B
#define FL_SMEM (27584 * 4)   // x2 = 220672 <= 228KB/SM

__global__ __launch_bounds__(320, 2) void flash_tc(const float* __restrict__ mask,
                                                   float* __restrict__ out)
{
    extern __shared__ uint32_t smw[];
    uint32_t* Qs  = smw;                    // [64 i][36 w]
    uint32_t* Ks  = smw + 2304;             // [64 j][36 w]
    uint32_t* Ps  = smw + 4608;             // [128 p][36 w]
    uint32_t* Vs  = smw + 9216;             // [64 j][36 w] row-major V
    uint32_t* Pt2 = smw + 11520;            // [64 i][36 w] P~ f16
    float*    SsF = (float*)(smw + 13824);  // [64][68] CC
    float*    B1  = (float*)(smw + 18176);  // [64][68] sheared CPF
    float*    B2  = (float*)(smw + 22528);  // [64][68] sheared PCF
    float* sm_m     = (float*)(smw + 26880);
    float* sm_l     = sm_m + 64;
    float* sm_scale = sm_m + 128;
    float* sm_mask  = sm_m + 192;           // [512] full mask row

    const int i0 = blockIdx.x * 64;
    const int bh = blockIdx.y;
    const int b_ = bh >> 4, h = bh & 15;
    const int tid = threadIdx.x;
    const int wid = tid >> 5, lane = tid & 31;
    const int g = lane >> 2, t = lane & 3;
    const int wm = wid >> 1, wn = wid & 1;

    const uint32_t* q32 = g_q + ((size_t)bh*SS + i0) * (DD/2);
    const uint32_t* k32 = g_k + (size_t)bh*SS*(DD/2);
    const uint32_t* v32 = g_v + (size_t)bh*SS*(DD/2);
    const uint32_t* p32 = g_pos + (size_t)h * 1024 * (DD/2);

    const uint32_t smQs = smaddr(Qs), smKs = smaddr(Ks), smPs = smaddr(Ps), smVs = smaddr(Vs);

    // prologue: full mask row + Q + chunk-0 K,P via cp.async (one group)
    for (int u = tid; u < 512; u += 320)
        sm_mask[u] = mask[(size_t)b_*SS + u];
    if (tid < 256) {
#pragma unroll
        for (int i = 0; i < 2; i++) {
            const int u = tid + i*256, row = u >> 3, c = u & 7;
            cp16(smQs + (uint32_t)(row*144 + c*16), q32 + row*32 + c*4);
            cp16(smKs + (uint32_t)(row*144 + c*16), k32 + row*32 + c*4);
        }
        const int base0 = i0 + 449;
#pragma unroll
        for (int i = 0; i < 4; i++) {
            const int u = tid + i*256, pr = u >> 3, c = u & 7;
            int grow = base0 + pr;
            grow = grow < 0 ? 0 : (grow > 1023 ? 1023 : grow);
            cp16(smPs + (uint32_t)(pr*144 + c*16), p32 + grow*32 + c*4);
        }
        CP_COMMIT();
    }
    if (tid < 64) { sm_m[tid] = -1e30f; sm_l[tid] = 0.f; }

    float acc_o[4][4];
#pragma unroll
    for (int nt = 0; nt < 4; nt++)
#pragma unroll
        for (int e = 0; e < 4; e++) acc_o[nt][e] = 0.f;

    const uint32_t* Ap; const uint32_t* Bp;
    int Arow, Brow;
    int kind;
    if (wid < 2)      { Ap = Qs; Arow = wid*32;          Bp = Ks; Brow = 0;                 kind = 0; }
    else if (wid < 6) { Ap = Qs; Arow = ((wid-2)&1)*32;  Bp = Ps; Brow = ((wid-2)>>1)*64;   kind = 1; }
    else              { Ap = Ps; Arow = (wid-6)*32;      Bp = Ks; Brow = 0;                 kind = 2; }

    const uint32_t aFB = smaddr(&Ap[(Arow + A_ROW(lane))*36 + A_COL(lane)]);
    const uint32_t bFB = smaddr(&Bp[(Brow + B_ROW(lane))*36 + B_COL(lane)]);
    const uint32_t aPV = smaddr(&Pt2[(wm*16 + A_ROW(lane))*36 + A_COL(lane)]);
    const uint32_t bPVt = smVs
        + (uint32_t)((((lane >> 3) & 1) * 8 + (lane & 7)) * 144
                     + ((lane >> 4) & 1) * 16 + wn * 64);

    const float s1 = 0.14433756729740643f;      // 1/sqrt(48)

    for (int j0 = 0; j0 < SS; j0 += 64) {
        __syncthreads();   // previous chunk's Vs/Pt2 reads complete

        // ---- issue V_cur; drain only the older K/P group (V stays in flight)
        if (tid < 256) {
            const uint32_t* vc32 = v32 + (size_t)j0 * 32;
#pragma unroll
            for (int i = 0; i < 2; i++) {
                const int u = tid + i*256, row = u >> 3, c = u & 7;
                cp16(smVs + (uint32_t)(row*144 + c*16), vc32 + row*32 + c*4);
            }
            CP_COMMIT();
            CP_WAIT1();    // outstanding: [KP_cur, V_cur] -> KP_cur done
        }
        __syncthreads();

        // ---- score MMAs in two nt-halves; shear stores ----
#pragma unroll
        for (int hN = 0; hN < 2; hN++) {
            float acc[2][4][4];
#pragma unroll
            for (int mt = 0; mt < 2; mt++)
#pragma unroll
                for (int nt = 0; nt < 4; nt++)
#pragma unroll
                    for (int e = 0; e < 4; e++) acc[mt][nt][e] = 0.f;

#pragma unroll
            for (int ks = 0; ks < 4; ks++) {
                uint32_t a[2][4], b[4][2];
#pragma unroll
                for (int mt = 0; mt < 2; mt++)
                    ldm_x4(a[mt][0], a[mt][1], a[mt][2], a[mt][3],
                           aFB + (uint32_t)(mt*16*36*4 + ks*32));
#pragma unroll
                for (int ntp = 0; ntp < 2; ntp++)
                    ldm_x4(b[2*ntp][0], b[2*ntp][1], b[2*ntp+1][0], b[2*ntp+1][1],
                           bFB + (uint32_t)((hN*32 + ntp*16)*36*4 + ks*32));
#pragma unroll
                for (int mt = 0; mt < 2; mt++)
#pragma unroll
                    for (int nt = 0; nt < 4; nt++)
                        mma_f16(acc[mt][nt], a[mt], b[nt]);
            }

            if (kind == 0) {
#pragma unroll
                for (int mt = 0; mt < 2; mt++)
#pragma unroll
                    for (int nt = 0; nt < 4; nt++) {
                        const int r0 = Arow + mt*16 + g;
                        const int c0 = (hN*4 + nt)*8 + 2*t;
                        *(float2*)&SsF[r0*68 + c0]     = make_float2(acc[mt][nt][0], acc[mt][nt][1]);
                        *(float2*)&SsF[(r0+8)*68 + c0] = make_float2(acc[mt][nt][2], acc[mt][nt][3]);
                    }
            } else if (kind == 1) {
#pragma unroll
                for (int mt = 0; mt < 2; mt++)
#pragma unroll
                    for (int nt = 0; nt < 4; nt++) {
                        const int ai0 = Arow + mt*16 + g;
                        const int p0 = Brow + (hN*4 + nt)*8 + 2*t;
#pragma unroll
                        for (int e = 0; e < 4; e++) {
                            const int ai = ai0 + (e >> 1)*8;
                            const int p  = p0 + (e & 1);
                            const int cj = ai - p + 63;
                            if ((unsigned)cj < 64u)
                                B1[ai*68 + cj] = acc[mt][nt][e];
                        }
                    }
            } else {
#pragma unroll
                for (int mt = 0; mt < 2; mt++)
#pragma unroll
                    for (int nt = 0; nt < 4; nt++) {
                        const int r0 = Arow + mt*16 + g;
                        const int c0 = (hN*4 + nt)*8 + 2*t;
#pragma unroll
                        for (int e = 0; e < 4; e++) {
                            const int r  = r0 + (e >> 1)*8;
                            const int cj = c0 + (e & 1);
                            const int ai = r + cj - 63;
                            if ((unsigned)ai < 64u)
                                B2[ai*68 + cj] = acc[mt][nt][e];
                        }
                    }
            }
        }
        __syncthreads();   // all warps past Ks/Ps reads -> safe to prefetch over them

        // ---- prefetch next chunk's K & P; overlaps softmax + PV ----
        if (j0 + 64 < SS && tid < 256) {
            const uint32_t* kn32 = k32 + (size_t)(j0 + 64) * 32;
            const int basen = i0 - (j0 + 64) + 449;
#pragma unroll
            for (int i = 0; i < 2; i++) {
                const int u = tid + i*256, row = u >> 3, c = u & 7;
                cp16(smKs + (uint32_t)(row*144 + c*16), kn32 + row*32 + c*4);
            }
#pragma unroll
            for (int i = 0; i < 4; i++) {
                const int u = tid + i*256, pr = u >> 3, c = u & 7;
                int grow = basen + pr;
                grow = grow < 0 ? 0 : (grow > 1023 ? 1023 : grow);
                cp16(smPs + (uint32_t)(pr*144 + c*16), p32 + grow*32 + c*4);
            }
            CP_COMMIT();
        }

        // ---- online softmax (threads 0..255); vectorized 3-buffer combine --
        if (tid < 256) {
            const int row = tid >> 2, q4 = tid & 3;
            const int c0 = q4*16;
            float v[16];
            float mloc = -1e30f;
#pragma unroll
            for (int i4 = 0; i4 < 4; i4++) {
                const float4 sc = *(const float4*)&SsF[row*68 + c0 + 4*i4];
                const float4 y2 = *(const float4*)&B2[row*68 + c0 + 4*i4];
                const float4 y1 = *(const float4*)&B1[row*68 + c0 + 4*i4];
                const float4 mk = *(const float4*)&sm_mask[j0 + c0 + 4*i4];
                v[4*i4+0] = (sc.x + y2.x + 0.125f*y1.x) * s1 + mk.x;
                v[4*i4+1] = (sc.y + y2.y + 0.125f*y1.y) * s1 + mk.y;
                v[4*i4+2] = (sc.z + y2.z + 0.125f*y1.z) * s1 + mk.z;
                v[4*i4+3] = (sc.w + y2.w + 0.125f*y1.w) * s1 + mk.w;
                mloc = fmaxf(mloc, fmaxf(fmaxf(v[4*i4], v[4*i4+1]), fmaxf(v[4*i4+2], v[4*i4+3])));
            }
            mloc = fmaxf(mloc, __shfl_xor_sync(0xffffffffu, mloc, 1));
            mloc = fmaxf(mloc, __shfl_xor_sync(0xffffffffu, mloc, 2));
            const float mold = sm_m[row];
            const float mnew = fmaxf(mold, mloc);
            float lsum = 0.f;
#pragma unroll
            for (int i = 0; i < 8; i++) {
                const float e0 = __expf(v[2*i]   - mnew);
                const float e1 = __expf(v[2*i+1] - mnew);
                Pt2[row*36 + q4*8 + i] = packh2(e0, e1);
                lsum += e0 + e1;
            }
            lsum += __shfl_xor_sync(0xffffffffu, lsum, 1);
            lsum += __shfl_xor_sync(0xffffffffu, lsum, 2);
            if (q4 == 0) {
                const float sc = __expf(mold - mnew);
                sm_m[row] = mnew;
                sm_scale[row] = sc;
                sm_l[row] = sm_l[row] * sc + lsum;
            }
            // drain V_cur before PV (KP_next may remain in flight)
            if (j0 + 64 < SS) { CP_WAIT1(); } else { CP_WAIT0(); }
        }
        __syncthreads();   // publishes V_cur + Pt2 to PV warps

        // ---- PV: warps 0..7, out tile 64x64, warp tile 16x32 ----
        if (wid < 8) {
            const float sc0 = sm_scale[wm*16 + g];
            const float sc1 = sm_scale[wm*16 + g + 8];
#pragma unroll
            for (int nt = 0; nt < 4; nt++) {
                acc_o[nt][0] *= sc0; acc_o[nt][1] *= sc0;
                acc_o[nt][2] *= sc1; acc_o[nt][3] *= sc1;
            }
#pragma unroll
            for (int ks = 0; ks < 4; ks++) {
                uint32_t a[4], b[4][2];
                ldm_x4(a[0], a[1], a[2], a[3], aPV + (uint32_t)(ks*32));
#pragma unroll
                for (int ntp = 0; ntp < 2; ntp++)
                    ldm_x4_t(b[2*ntp][0], b[2*ntp][1], b[2*ntp+1][0], b[2*ntp+1][1],
                             bPVt + (uint32_t)(ks*16*144 + ntp*32));
#pragma unroll
                for (int nt = 0; nt < 4; nt++)
                    mma_f16(acc_o[nt], a, b[nt]);
            }
        }
    }
    __syncthreads();

    // ---- finalize: out[i][d] = acc_o / l ----
    if (wid < 8) {
        const int r0 = wm*16 + g;
        const float inv0 = 1.f / sm_l[r0];
        const float inv1 = 1.f / sm_l[r0 + 8];
#pragma unroll
        for (int nt = 0; nt < 4; nt++) {
            const int col = wn*32 + nt*8 + 2*t;
            const size_t o0 = ((size_t)b_*SS + i0 + r0)*HIDN + h*DD + col;
            const size_t o1 = ((size_t)b_*SS + i0 + r0 + 8)*HIDN + h*DD + col;
            *(float2*)(out + o0) = make_float2(acc_o[nt][0]*inv0, acc_o[nt][1]*inv0);
            *(float2*)(out + o1) = make_float2(acc_o[nt][2]*inv1, acc_o[nt][3]*inv1);
        }
    }
}

// ---------------- launch ---------------------------------------------------
extern "C" void kernel_launch(void* const* d_in, const int* in_sizes, int n_in,
                              void* d_out, int out_size)
{
    const float* hs  = (const float*)d_in[0];
    const float* msk = (const float*)d_in[1];
    const float* Wq  = (const float*)d_in[3];
    const float* bq  = (const float*)d_in[4];
    const float* Wk  = (const float*)d_in[5];
    const float* bk  = (const float*)d_in[6];
    const float* Wv  = (const float*)d_in[7];
    const float* bv  = (const float*)d_in[8];
    const float* Wpk = (const float*)d_in[9];
    const float* bpk = (const float*)d_in[10];
    const float* rel = (const float*)d_in[11];
    float* out = (float*)d_out;

    cudaFuncSetAttribute(flash_tc, cudaFuncAttributeMaxDynamicSharedMemorySize, FL_SMEM);

    dim3 gc(2048, 6);                     // fp32 -> fp16 one-time convert (32B/thr)
    precvt<<<gc, 256>>>(hs, rel, Wq, Wk, Wv, Wpk);

    dim3 gg(8, 32, 4);                    // z: Wq, Wk, Wv, Wpk (y>=8 idles for z=3)
    gemm_tc<<<gg, 256>>>(bq, bk, bv, bpk);

    dim3 gf(SS/64, BH);                   // (8, 128)
    flash_tc<<<gf, 320, FL_SMEM>>>(msk, out);
}